// round 7
// baseline (speedup 1.0000x reference)
#include <cuda_runtime.h>
#include <cuda_bf16.h>
#include <cuda_fp16.h>
#include <cstdint>
#include <cstdio>

// ---------------------------------------------------------------------------
// Problem constants
// ---------------------------------------------------------------------------
#define D_MODEL   2048
#define NUM_HEADS 16
#define HEAD_DIM  128
#define BATCH     4
#define TQ        1024
#define CACHE_LEN 1024
#define M_ROWS    (BATCH * TQ)          // 4096

// scratch (device globals: allocation-free scratch per harness rules)
__device__ __half g_hQ[M_ROWS * D_MODEL];             // projected Q, fp16
__device__ __half g_O[M_ROWS * D_MODEL];              // attention out, fp16
// fp16 pre-rounded inputs
__device__ __half g_hq[M_ROWS * D_MODEL];
__device__ __half g_hk[M_ROWS * D_MODEL];
__device__ __half g_hv[M_ROWS * D_MODEL];
__device__ __half g_hWq[D_MODEL * D_MODEL];
__device__ __half g_hWk[D_MODEL * D_MODEL];
__device__ __half g_hWv[D_MODEL * D_MODEL];
__device__ __half g_hWo[D_MODEL * D_MODEL];
__device__ __half g_hck[BATCH * CACHE_LEN * D_MODEL]; // fp16 cache K (attention)
__device__ __half g_hcv[BATCH * CACHE_LEN * D_MODEL]; // fp16 cache V (attention)

// ---------------------------------------------------------------------------
// helpers
// ---------------------------------------------------------------------------
__device__ __forceinline__ uint32_t smem_u32(const void* p) {
    uint32_t a;
    asm("{ .reg .u64 t; cvta.to.shared.u64 t, %1; cvt.u32.u64 %0, t; }"
        : "=r"(a) : "l"(p));
    return a;
}

// fp16 m16n8k16: D += A*B  (row.col, f32 accum)
__device__ __forceinline__ void mma_f16(float* d, const uint32_t* a, const uint32_t* b) {
    asm volatile(
        "mma.sync.aligned.m16n8k16.row.col.f32.f16.f16.f32 "
        "{%0,%1,%2,%3}, {%4,%5,%6,%7}, {%8,%9}, {%0,%1,%2,%3};\n"
        : "+f"(d[0]), "+f"(d[1]), "+f"(d[2]), "+f"(d[3])
        : "r"(a[0]), "r"(a[1]), "r"(a[2]), "r"(a[3]),
          "r"(b[0]), "r"(b[1]));
}

__device__ __forceinline__ void ldsm_x4(uint32_t* r, uint32_t addr) {
    asm volatile("ldmatrix.sync.aligned.m8n8.x4.shared.b16 {%0,%1,%2,%3}, [%4];"
                 : "=r"(r[0]), "=r"(r[1]), "=r"(r[2]), "=r"(r[3]) : "r"(addr));
}

__device__ __forceinline__ void ldsm_x4t(uint32_t* r, uint32_t addr) {
    asm volatile("ldmatrix.sync.aligned.m8n8.x4.trans.shared.b16 {%0,%1,%2,%3}, [%4];"
                 : "=r"(r[0]), "=r"(r[1]), "=r"(r[2]), "=r"(r[3]) : "r"(addr));
}

__device__ __forceinline__ void cp_async16(uint32_t dst, const void* src) {
    asm volatile("cp.async.cg.shared.global [%0], [%1], 16;"
                 :: "r"(dst), "l"(src));
}
#define CP_COMMIT()  asm volatile("cp.async.commit_group;" ::: "memory")
#define CP_WAIT(N)   asm volatile("cp.async.wait_group %0;" :: "n"(N) : "memory")

// ---------------------------------------------------------------------------
// pre-rounding pass: dst = fp16(src), up to 4 tensors per launch (grid.z)
// ---------------------------------------------------------------------------
struct RoundArgs {
    const float* src[4];
    __half*      dst[4];
    int          n4[4];     // number of float4 elements
};

__global__ __launch_bounds__(256) void round_f16(RoundArgs ra) {
    const int z = blockIdx.z;
    const int i = blockIdx.x * 256 + threadIdx.x;
    if (i >= ra.n4[z]) return;
    float4 v = ((const float4*)ra.src[z])[i];
    __half2 h0 = __floats2half2_rn(v.x, v.y);
    __half2 h1 = __floats2half2_rn(v.z, v.w);
    uint2 u;
    u.x = *(uint32_t*)&h0;
    u.y = *(uint32_t*)&h1;
    ((uint2*)ra.dst[z])[i] = u;
}

// ---------------------------------------------------------------------------
// Pipelined TN GEMM (fp16 HMMA):  C[M,N] = A[M,K] * W[N,K]^T + bias[N]
// CTA 128x128, warp 64x32 (8 warps 2x4), K-tile 64, 3-stage cp.async ring,
// ldmatrix frags, m16n8k16 HMMA, fp32 accum + bias.
// Output modes: 0 = fp16 to Ch (Q-proj), 1 = permuted fp32 into new_kv
// (K/V proj land directly in d_out), 2 = plain fp32 (O-proj).
// ---------------------------------------------------------------------------
#define NST        3
#define TILE_B     16384                 // 128 rows * 128 bytes
#define GEMM_SMEM  (2 * NST * TILE_B + 1024)
#define NKT        (D_MODEL / 64)        // 32 k-tiles

struct ProjArgs {
    const __half* A[3];
    const __half* W[3];
    const float*  Bias[3];
    float*        C[3];
    __half*       Ch[3];
    int           mode[3];
};

__global__ __launch_bounds__(256, 2) void gemm_tc(ProjArgs args) {
    extern __shared__ char dyn_smem[];
    char* db = (char*)(((uintptr_t)dyn_smem + 1023) & ~(uintptr_t)1023);
    const uint32_t db_u = smem_u32(db);

    const int z = blockIdx.z;
    const __half* __restrict__ A    = args.A[z];
    const __half* __restrict__ W    = args.W[z];
    const float*  __restrict__ bias = args.Bias[z];
    float* __restrict__        C    = args.C[z];
    __half* __restrict__       Ch   = args.Ch[z];
    const int mode = args.mode[z];

    const int tid  = threadIdx.x;
    const int lane = tid & 31;
    const int w    = tid >> 5;
    const int wm   = w >> 2;       // 0..1
    const int wn   = w & 3;        // 0..3
    const int n0   = blockIdx.x * 128;
    const int m0   = blockIdx.y * 128;

    const __half* Ag = A + (size_t)m0 * D_MODEL;
    const __half* Wg = W + (size_t)n0 * D_MODEL;

    uint32_t swoff[4];
    size_t   gofs[4];
#pragma unroll
    for (int rep = 0; rep < 4; rep++) {
        const int g = rep * 256 + tid;          // 0..1023
        const int r = g >> 3;                   // row 0..127
        const int i = g & 7;                    // 16B chunk
        gofs[rep]  = (size_t)r * D_MODEL + i * 8;
        swoff[rep] = (uint32_t)((r * 128 + i * 16) ^ ((r & 7) << 4));
    }

    float acc[4][4][4];
#pragma unroll
    for (int i = 0; i < 4; i++)
#pragma unroll
        for (int j = 0; j < 4; j++)
#pragma unroll
            for (int k = 0; k < 4; k++) acc[i][j][k] = 0.f;

    auto issue = [&](int ks) {
        const int slot = ks % NST;
        const int kc   = ks * 64;
        const uint32_t da  = db_u + slot * TILE_B;
        const uint32_t dbb = db_u + NST * TILE_B + slot * TILE_B;
#pragma unroll
        for (int rep = 0; rep < 4; rep++)
            cp_async16(da + swoff[rep], Ag + gofs[rep] + kc);
#pragma unroll
        for (int rep = 0; rep < 4; rep++)
            cp_async16(dbb + swoff[rep], Wg + gofs[rep] + kc);
        CP_COMMIT();
    };

    issue(0);
    issue(1);

    const int m_ = lane >> 3;
    const int rr = lane & 7;
    const int a_row_base = wm * 64 + (m_ & 1) * 8 + rr;
    const int b_row_base = wn * 32 + (m_ & 1) * 8 + rr;
    const int k_half     = (m_ >> 1) * 16;

#pragma unroll 1
    for (int kt = 0; kt < NKT; kt++) {
        if (kt < NKT - 2) { CP_WAIT(1); } else { CP_WAIT(0); }
        __syncthreads();
        if (kt + 2 < NKT) issue(kt + 2);

        const int slot = kt % NST;
        const uint32_t da  = db_u + slot * TILE_B;
        const uint32_t dbb = db_u + NST * TILE_B + slot * TILE_B;

#pragma unroll
        for (int ks = 0; ks < 4; ks++) {
            const int kb = ks * 32 + k_half;
            uint32_t a[4][4], b[4][2];
#pragma unroll
            for (int mf = 0; mf < 4; mf++) {
                const int row = a_row_base + mf * 16;
                const uint32_t off = (uint32_t)((row * 128 + kb) ^ ((row & 7) << 4));
                ldsm_x4(a[mf], da + off);
            }
#pragma unroll
            for (int nf2 = 0; nf2 < 2; nf2++) {
                const int row = b_row_base + nf2 * 16;
                const uint32_t off = (uint32_t)((row * 128 + kb) ^ ((row & 7) << 4));
                uint32_t t[4];
                ldsm_x4(t, dbb + off);
                b[nf2 * 2][0]     = t[0]; b[nf2 * 2][1]     = t[2];
                b[nf2 * 2 + 1][0] = t[1]; b[nf2 * 2 + 1][1] = t[3];
            }
#pragma unroll
            for (int mf = 0; mf < 4; mf++)
#pragma unroll
                for (int nf = 0; nf < 4; nf++)
                    mma_f16(acc[mf][nf], a[mf], b[nf]);
        }
    }

    // epilogue (per mode)
#pragma unroll
    for (int mf = 0; mf < 4; mf++) {
#pragma unroll
        for (int nf = 0; nf < 4; nf++) {
            const int row = m0 + wm * 64 + mf * 16 + (lane >> 2);
            const int col = n0 + wn * 32 + nf * 8 + (lane & 3) * 2;
            const float b0 = bias[col], b1 = bias[col + 1];
            const float x0 = acc[mf][nf][0] + b0, x1 = acc[mf][nf][1] + b1;
            const float y0 = acc[mf][nf][2] + b0, y1 = acc[mf][nf][3] + b1;
            if (mode == 0) {
                __half2 h0 = __floats2half2_rn(x0, x1);
                __half2 h1 = __floats2half2_rn(y0, y1);
                *(__half2*)&Ch[(size_t)row * D_MODEL + col]       = h0;
                *(__half2*)&Ch[(size_t)(row + 8) * D_MODEL + col] = h1;
            } else if (mode == 1) {
                // direct write into new_k/new_v (proj half): t' = 1024 + t
                const int h  = col >> 7, d = col & 127;
#pragma unroll
                for (int rep = 0; rep < 2; rep++) {
                    const int rw = row + rep * 8;
                    const int bb = rw >> 10, t = rw & 1023;
                    const int j  = h * 128 + 64 + (t >> 4);
                    const int c  = (t & 15) * 128 + d;
                    float2 v = rep ? make_float2(y0, y1) : make_float2(x0, x1);
                    *(float2*)&C[((size_t)bb * 2048 + j) * 2048 + c] = v;
                }
            } else {
                *(float2*)&C[(size_t)row * D_MODEL + col]       = make_float2(x0, x1);
                *(float2*)&C[(size_t)(row + 8) * D_MODEL + col] = make_float2(y0, y1);
            }
        }
    }
}

// ---------------------------------------------------------------------------
// fp16 flash attention over the cache only (mask tril(TQ,total) => cache half).
// 128 threads (4 warps), 64 q-rows/CTA, 64 kv/tile, K/V double-buffered via
// cp.async. m16n8k16 HMMA; V fragments via ldmatrix.trans. (unchanged R6)
// ---------------------------------------------------------------------------
#define QOFF 0
#define KOFF 16384
#define VOFF (KOFF + 2 * 16384)
#define POFF (VOFF + 2 * 16384)
#define ATT_SMEM (POFF + 8192)   // 90112

__global__ __launch_bounds__(128, 2) void attn_kernel(
    const __half* __restrict__ gQ,
    const __half* __restrict__ hK,
    const __half* __restrict__ hV,
    __half* __restrict__ gO)
{
    extern __shared__ char smc[];
    const uint32_t sb = smem_u32(smc);
    const int tid = threadIdx.x, lane = tid & 31, w = tid >> 5;
    const int qi = blockIdx.x, h = blockIdx.y, b = blockIdx.z;
    const int q0 = qi * 64;

    const __half* Qg = gQ + ((size_t)b * TQ + q0) * D_MODEL + h * HEAD_DIM;
    const __half* Kg = hK + (size_t)b * CACHE_LEN * D_MODEL + h * HEAD_DIM;
    const __half* Vg = hV + (size_t)b * CACHE_LEN * D_MODEL + h * HEAD_DIM;

    // Q tile 64x128 halves -> swizzled smem (rows 256B)
#pragma unroll
    for (int rep = 0; rep < 8; rep++) {
        const int g = rep * 128 + tid;
        const int r = g >> 4, i = g & 15;
        uint4 v = *(const uint4*)(Qg + (size_t)r * D_MODEL + i * 8);
        *(uint4*)(smc + QOFF + ((r * 256 + i * 16) ^ ((r & 7) << 4))) = v;
    }

    auto issueK = [&](int kt) {
#pragma unroll
        for (int rep = 0; rep < 8; rep++) {
            const int g = rep * 128 + tid;
            const int r = g >> 4, i = g & 15;
            cp_async16(sb + KOFF + (kt & 1) * 16384 + ((r * 256 + i * 16) ^ ((r & 7) << 4)),
                       Kg + (size_t)(kt * 64 + r) * D_MODEL + i * 8);
        }
        CP_COMMIT();
    };
    auto issueV = [&](int kt) {
#pragma unroll
        for (int rep = 0; rep < 8; rep++) {
            const int g = rep * 128 + tid;
            const int r = g >> 4, i = g & 15;
            cp_async16(sb + VOFF + (kt & 1) * 16384 + ((r * 256 + i * 16) ^ ((r & 7) << 4)),
                       Vg + (size_t)(kt * 64 + r) * D_MODEL + i * 8);
        }
        CP_COMMIT();
    };

    issueK(0); issueV(0);
    if (qi >= 1) { issueK(1); issueV(1); } else { CP_COMMIT(); CP_COMMIT(); }

    float acc_o[16][4];
#pragma unroll
    for (int i = 0; i < 16; i++)
#pragma unroll
        for (int j = 0; j < 4; j++) acc_o[i][j] = 0.f;
    float mrow[2] = {-1e30f, -1e30f};
    float lrow[2] = {0.f, 0.f};
    const float sc = 0.08838834764831845f;   // 1/sqrt(128)

    const int m_ = lane >> 3, rr = lane & 7;
    const int kh    = (m_ >> 1) * 16;
    const int a_row = w * 16 + (m_ & 1) * 8 + rr;

    for (int kt = 0; kt <= qi; kt++) {
        CP_WAIT(3);            // K(kt) landed (per-thread)
        __syncthreads();       // all threads' chunks visible (also covers Q on kt=0)

        const uint32_t kbase = sb + KOFF + (kt & 1) * 16384;
        float accs[8][4];
#pragma unroll
        for (int i = 0; i < 8; i++)
#pragma unroll
            for (int j = 0; j < 4; j++) accs[i][j] = 0.f;

#pragma unroll
        for (int ks = 0; ks < 8; ks++) {            // 8 x k16 over headdim 128
            const int colb = ks * 32 + kh;
            uint32_t a[4];
            ldsm_x4(a, sb + QOFF + ((a_row * 256 + colb) ^ ((a_row & 7) << 4)));
            uint32_t bfr[8][2];
#pragma unroll
            for (int nf2 = 0; nf2 < 4; nf2++) {
                const int row = nf2 * 16 + (m_ & 1) * 8 + rr;   // kv rows 0..63
                uint32_t t[4];
                ldsm_x4(t, kbase + ((row * 256 + colb) ^ ((row & 7) << 4)));
                bfr[nf2 * 2][0]     = t[0]; bfr[nf2 * 2][1]     = t[2];
                bfr[nf2 * 2 + 1][0] = t[1]; bfr[nf2 * 2 + 1][1] = t[3];
            }
#pragma unroll
            for (int nf = 0; nf < 8; nf++) mma_f16(accs[nf], a, bfr[nf]);
        }

        // scale + causal mask (diagonal tile only)
#pragma unroll
        for (int nf = 0; nf < 8; nf++)
#pragma unroll
            for (int v = 0; v < 4; v++) accs[nf][v] *= sc;
        if (kt == qi) {
#pragma unroll
            for (int nf = 0; nf < 8; nf++)
#pragma unroll
                for (int r = 0; r < 2; r++)
#pragma unroll
                    for (int j = 0; j < 2; j++) {
                        const int cl = nf * 8 + (lane & 3) * 2 + j;
                        const int rl = w * 16 + (lane >> 2) + r * 8;
                        if (cl > rl) accs[nf][r * 2 + j] = -1e30f;
                    }
        }

        // online softmax + write P (fp16, swizzled)
#pragma unroll
        for (int r = 0; r < 2; r++) {
            float vmax = -1e30f;
#pragma unroll
            for (int nf = 0; nf < 8; nf++) {
                vmax = fmaxf(vmax, accs[nf][r * 2]);
                vmax = fmaxf(vmax, accs[nf][r * 2 + 1]);
            }
            vmax = fmaxf(vmax, __shfl_xor_sync(0xffffffffu, vmax, 1));
            vmax = fmaxf(vmax, __shfl_xor_sync(0xffffffffu, vmax, 2));
            const float mnew = fmaxf(mrow[r], vmax);
            float psum = 0.f;
            const int qr = w * 16 + (lane >> 2) + r * 8;
#pragma unroll
            for (int nf = 0; nf < 8; nf++) {
                const float p0 = __expf(accs[nf][r * 2]     - mnew);
                const float p1 = __expf(accs[nf][r * 2 + 1] - mnew);
                psum += p0 + p1;
                __half2 hp = __floats2half2_rn(p0, p1);
                const uint32_t boff = (uint32_t)(qr * 128 + nf * 16 + (lane & 3) * 4)
                                      ^ ((qr & 7) << 4);
                *(uint32_t*)(smc + POFF + boff) = *(uint32_t*)&hp;
            }
            psum += __shfl_xor_sync(0xffffffffu, psum, 1);
            psum += __shfl_xor_sync(0xffffffffu, psum, 2);
            const float alpha = __expf(mrow[r] - mnew);
            lrow[r] = lrow[r] * alpha + psum;
            mrow[r] = mnew;
#pragma unroll
            for (int nf = 0; nf < 16; nf++) {
                acc_o[nf][r * 2]     *= alpha;
                acc_o[nf][r * 2 + 1] *= alpha;
            }
        }

        CP_WAIT(2);            // V(kt) landed
        __syncthreads();       // ... and visible; all warps done reading K(kt)
        if (kt + 2 <= qi) issueK(kt + 2); else CP_COMMIT();

        // O += P * V  (P from swizzled fp16 smem, V frags via ldmatrix.trans)
        const uint32_t vbase = sb + VOFF + (kt & 1) * 16384;
        const int p_row = w * 16 + (m_ & 1) * 8 + rr;
        const int vr_lane = ((lane >> 3) & 1) * 8 + (lane & 7);
        const int vc_lane = (lane >> 4) * 16;
#pragma unroll
        for (int ks = 0; ks < 4; ks++) {            // 4 x k16 over 64 kv
            const int colb = ks * 32 + kh;
            uint32_t aP[4];
            ldsm_x4(aP, sb + POFF + ((p_row * 128 + colb) ^ ((p_row & 7) << 4)));
#pragma unroll
            for (int dg = 0; dg < 8; dg++) {        // 16 halves of headdim each
                const int vrow = ks * 16 + vr_lane;
                const int vcol = dg * 32 + vc_lane;
                uint32_t t[4];
                ldsm_x4t(t, vbase + ((vrow * 256 + vcol) ^ ((vrow & 7) << 4)));
                uint32_t b0[2] = { t[0], t[1] };
                uint32_t b1[2] = { t[2], t[3] };
                mma_f16(acc_o[dg * 2],     aP, b0);
                mma_f16(acc_o[dg * 2 + 1], aP, b1);
            }
        }
        __syncthreads();       // all warps done reading V(kt)
        if (kt + 2 <= qi) issueV(kt + 2); else CP_COMMIT();
    }

    // normalize + write fp16
#pragma unroll
    for (int nf = 0; nf < 16; nf++)
#pragma unroll
        for (int r = 0; r < 2; r++) {
            const int row = q0 + w * 16 + (lane >> 2) + r * 8;
            const int col = h * HEAD_DIM + nf * 8 + (lane & 3) * 2;
            const float inv = 1.f / lrow[r];
            __half2 hv = __floats2half2_rn(acc_o[nf][r * 2] * inv,
                                           acc_o[nf][r * 2 + 1] * inv);
            *(__half2*)&gO[((size_t)b * TQ + row) * D_MODEL + col] = hv;
        }
}

// ---------------------------------------------------------------------------
// cache pass, fused: permuted fp32 cache half of new_k/new_v into d_out AND
// fp16 rounding of the caches for attention (single read of each cache).
// grid.z: 0 -> K, 1 -> V. 2097152 float4 per tensor.
// ---------------------------------------------------------------------------
__global__ __launch_bounds__(256) void copy_cache_kv(
    const float* __restrict__ cacheK,
    const float* __restrict__ cacheV,
    float* __restrict__ dstK,
    float* __restrict__ dstV,
    __half* __restrict__ hcK,
    __half* __restrict__ hcV)
{
    const int i = blockIdx.x * 256 + threadIdx.x;
    const int b   = i >> 19;            // 524288 float4 per batch
    const int rem = i & 524287;
    const int jj  = rem >> 9;           // 0..1023 (h*64 + cache row)
    const int c   = (rem & 511) * 4;
    const int h   = jj >> 6;
    const int j   = h * 128 + (jj & 63);
    const int t   = (jj & 63) * 16 + (c >> 7);
    const int d   = c & 127;

    const float* cache = blockIdx.z ? cacheV : cacheK;
    float*       dst   = blockIdx.z ? dstV   : dstK;
    __half*      hc    = blockIdx.z ? hcV    : hcK;

    const size_t src_off = ((size_t)b * CACHE_LEN + t) * D_MODEL + h * HEAD_DIM + d;
    float4 v = *(const float4*)&cache[src_off];
    *(float4*)&dst[((size_t)b * 2048 + j) * D_MODEL + c] = v;

    __half2 h0 = __floats2half2_rn(v.x, v.y);
    __half2 h1 = __floats2half2_rn(v.z, v.w);
    uint2 u;
    u.x = *(uint32_t*)&h0;
    u.y = *(uint32_t*)&h1;
    *(uint2*)&hc[src_off] = u;
}

// ---------------------------------------------------------------------------
// launch — two-stream fork/join inside graph capture:
//   s0: round(query,Wq,Wo) + cache pass -> Q-proj -> attention -> O-proj
//   s2: round(key,value,Wk,Wv) -> K/V-proj (writes d_out directly)
// ---------------------------------------------------------------------------
extern "C" void kernel_launch(void* const* d_in, const int* in_sizes, int n_in,
                              void* d_out, int out_size)
{
    const float* query   = (const float*)d_in[0];
    const float* key     = (const float*)d_in[1];
    const float* value   = (const float*)d_in[2];
    const float* cacheK  = (const float*)d_in[3];
    const float* cacheV  = (const float*)d_in[4];
    const float* Wq      = (const float*)d_in[5];
    const float* bq      = (const float*)d_in[6];
    const float* Wk      = (const float*)d_in[7];
    const float* bk      = (const float*)d_in[8];
    const float* Wv      = (const float*)d_in[9];
    const float* bv      = (const float*)d_in[10];
    const float* Wo      = (const float*)d_in[11];
    const float* bo      = (const float*)d_in[12];
    float* out = (float*)d_out;

    __half *phQ, *pO, *phq, *phk, *phv, *phWq, *phWk, *phWv, *phWo, *phck, *phcv;
    cudaGetSymbolAddress((void**)&phQ, g_hQ);
    cudaGetSymbolAddress((void**)&pO, g_O);
    cudaGetSymbolAddress((void**)&phq, g_hq);
    cudaGetSymbolAddress((void**)&phk, g_hk);
    cudaGetSymbolAddress((void**)&phv, g_hv);
    cudaGetSymbolAddress((void**)&phWq, g_hWq);
    cudaGetSymbolAddress((void**)&phWk, g_hWk);
    cudaGetSymbolAddress((void**)&phWv, g_hWv);
    cudaGetSymbolAddress((void**)&phWo, g_hWo);
    cudaGetSymbolAddress((void**)&phck, g_hck);
    cudaGetSymbolAddress((void**)&phcv, g_hcv);

    // one-time stream/event creation (resources only; work is identical per call)
    static cudaStream_t s2 = nullptr;
    static cudaEvent_t  evF = nullptr, evJ = nullptr;
    if (s2 == nullptr) {
        cudaStreamCreateWithFlags(&s2, cudaStreamNonBlocking);
        cudaEventCreateWithFlags(&evF, cudaEventDisableTiming);
        cudaEventCreateWithFlags(&evJ, cudaEventDisableTiming);
    }

    cudaFuncSetAttribute(gemm_tc, cudaFuncAttributeMaxDynamicSharedMemorySize,
                         GEMM_SMEM);
    cudaFuncSetAttribute(attn_kernel, cudaFuncAttributeMaxDynamicSharedMemorySize,
                         ATT_SMEM);

    const int NA = M_ROWS * D_MODEL / 4;     // 2097152 float4
    const int NW = D_MODEL * D_MODEL / 4;    // 1048576 float4

    // fork
    cudaEventRecord(evF, 0);
    cudaStreamWaitEvent(s2, evF, 0);

    // ---- stream s2: K/V branch (independent of attention chain) ----
    RoundArgs rb;
    rb.src[0] = key;   rb.dst[0] = phk;  rb.n4[0] = NA;
    rb.src[1] = value; rb.dst[1] = phv;  rb.n4[1] = NA;
    rb.src[2] = Wk;    rb.dst[2] = phWk; rb.n4[2] = NW;
    rb.src[3] = Wv;    rb.dst[3] = phWv; rb.n4[3] = NW;
    round_f16<<<dim3(NA / 256, 1, 4), 256, 0, s2>>>(rb);

    ProjArgs pkv;
    pkv.A[0] = phk; pkv.W[0] = phWk; pkv.Bias[0] = bk;
    pkv.C[0] = out + 8388608;  pkv.Ch[0] = nullptr; pkv.mode[0] = 1;
    pkv.A[1] = phv; pkv.W[1] = phWv; pkv.Bias[1] = bv;
    pkv.C[1] = out + 25165824; pkv.Ch[1] = nullptr; pkv.mode[1] = 1;
    pkv.A[2] = pkv.A[0]; pkv.W[2] = pkv.W[0]; pkv.Bias[2] = pkv.Bias[0];
    pkv.C[2] = pkv.C[0]; pkv.Ch[2] = nullptr; pkv.mode[2] = 1;
    gemm_tc<<<dim3(D_MODEL / 128, M_ROWS / 128, 2), 256, GEMM_SMEM, s2>>>(pkv);

    cudaEventRecord(evJ, s2);

    // ---- stream 0: attention chain ----
    RoundArgs raA;
    raA.src[0] = query; raA.dst[0] = phq;  raA.n4[0] = NA;
    raA.src[1] = Wq;    raA.dst[1] = phWq; raA.n4[1] = NW;
    raA.src[2] = Wo;    raA.dst[2] = phWo; raA.n4[2] = NW;
    raA.src[3] = Wo;    raA.dst[3] = phWo; raA.n4[3] = 0;   // unused slot
    round_f16<<<dim3(NA / 256, 1, 3), 256>>>(raA);

    copy_cache_kv<<<dim3(2097152 / 256, 1, 2), 256>>>(
        cacheK, cacheV, out + 8388608, out + 25165824, phck, phcv);

    ProjArgs pq;
    pq.A[0] = phq; pq.W[0] = phWq; pq.Bias[0] = bq;
    pq.C[0] = nullptr; pq.Ch[0] = phQ; pq.mode[0] = 0;
    pq.A[1] = pq.A[0]; pq.W[1] = pq.W[0]; pq.Bias[1] = pq.Bias[0];
    pq.C[1] = nullptr; pq.Ch[1] = phQ; pq.mode[1] = 0;
    pq.A[2] = pq.A[0]; pq.W[2] = pq.W[0]; pq.Bias[2] = pq.Bias[0];
    pq.C[2] = nullptr; pq.Ch[2] = phQ; pq.mode[2] = 0;
    gemm_tc<<<dim3(D_MODEL / 128, M_ROWS / 128, 1), 256, GEMM_SMEM>>>(pq);

    attn_kernel<<<dim3(TQ / 64, NUM_HEADS, BATCH), 128, ATT_SMEM>>>(
        phQ, phck, phcv, pO);

    ProjArgs po;
    po.A[0] = pO; po.W[0] = phWo; po.Bias[0] = bo;
    po.C[0] = out; po.Ch[0] = nullptr; po.mode[0] = 2;
    po.A[1] = po.A[0]; po.W[1] = po.W[0]; po.Bias[1] = po.Bias[0];
    po.C[1] = po.C[0]; po.Ch[1] = nullptr; po.mode[1] = 2;
    po.A[2] = po.A[0]; po.W[2] = po.W[0]; po.Bias[2] = po.Bias[0];
    po.C[2] = po.C[0]; po.Ch[2] = nullptr; po.mode[2] = 2;
    gemm_tc<<<dim3(D_MODEL / 128, M_ROWS / 128, 1), 256, GEMM_SMEM>>>(po);

    // join
    cudaStreamWaitEvent(0, evJ, 0);
}

// round 8
// speedup vs baseline: 1.1630x; 1.1630x over previous
#include <cuda_runtime.h>
#include <cuda_bf16.h>
#include <cuda_fp16.h>
#include <cstdint>
#include <cstdio>

// ---------------------------------------------------------------------------
// Problem constants
// ---------------------------------------------------------------------------
#define D_MODEL   2048
#define NUM_HEADS 16
#define HEAD_DIM  128
#define BATCH     4
#define TQ        1024
#define CACHE_LEN 1024
#define M_ROWS    (BATCH * TQ)          // 4096

// scratch (device globals: allocation-free scratch per harness rules)
__device__ __half g_hQ[M_ROWS * D_MODEL];             // projected Q, fp16
__device__ __half g_O[M_ROWS * D_MODEL];              // attention out, fp16
// fp16 pre-rounded inputs
__device__ __half g_hq[M_ROWS * D_MODEL];
__device__ __half g_hk[M_ROWS * D_MODEL];
__device__ __half g_hv[M_ROWS * D_MODEL];
__device__ __half g_hWq[D_MODEL * D_MODEL];
__device__ __half g_hWk[D_MODEL * D_MODEL];
__device__ __half g_hWv[D_MODEL * D_MODEL];
__device__ __half g_hWo[D_MODEL * D_MODEL];
__device__ __half g_hck[BATCH * CACHE_LEN * D_MODEL]; // fp16 cache K (attention)
__device__ __half g_hcv[BATCH * CACHE_LEN * D_MODEL]; // fp16 cache V (attention)

// ---------------------------------------------------------------------------
// helpers
// ---------------------------------------------------------------------------
__device__ __forceinline__ uint32_t smem_u32(const void* p) {
    uint32_t a;
    asm("{ .reg .u64 t; cvta.to.shared.u64 t, %1; cvt.u32.u64 %0, t; }"
        : "=r"(a) : "l"(p));
    return a;
}

// fp16 m16n8k16: D += A*B  (row.col, f32 accum)
__device__ __forceinline__ void mma_f16(float* d, const uint32_t* a, const uint32_t* b) {
    asm volatile(
        "mma.sync.aligned.m16n8k16.row.col.f32.f16.f16.f32 "
        "{%0,%1,%2,%3}, {%4,%5,%6,%7}, {%8,%9}, {%0,%1,%2,%3};\n"
        : "+f"(d[0]), "+f"(d[1]), "+f"(d[2]), "+f"(d[3])
        : "r"(a[0]), "r"(a[1]), "r"(a[2]), "r"(a[3]),
          "r"(b[0]), "r"(b[1]));
}

__device__ __forceinline__ void ldsm_x4(uint32_t* r, uint32_t addr) {
    asm volatile("ldmatrix.sync.aligned.m8n8.x4.shared.b16 {%0,%1,%2,%3}, [%4];"
                 : "=r"(r[0]), "=r"(r[1]), "=r"(r[2]), "=r"(r[3]) : "r"(addr));
}

__device__ __forceinline__ void ldsm_x4t(uint32_t* r, uint32_t addr) {
    asm volatile("ldmatrix.sync.aligned.m8n8.x4.trans.shared.b16 {%0,%1,%2,%3}, [%4];"
                 : "=r"(r[0]), "=r"(r[1]), "=r"(r[2]), "=r"(r[3]) : "r"(addr));
}

__device__ __forceinline__ void cp_async16(uint32_t dst, const void* src) {
    asm volatile("cp.async.cg.shared.global [%0], [%1], 16;"
                 :: "r"(dst), "l"(src));
}
#define CP_COMMIT()  asm volatile("cp.async.commit_group;" ::: "memory")
#define CP_WAIT(N)   asm volatile("cp.async.wait_group %0;" :: "n"(N) : "memory")

// ---------------------------------------------------------------------------
// pre-rounding pass: dst = fp16(src) for 7 tensors in one launch (grid.z)
// ---------------------------------------------------------------------------
struct RoundArgs {
    const float* src[7];
    __half*      dst[7];
    int          n4[7];     // number of float4 elements
};

__global__ __launch_bounds__(256) void round_f16(RoundArgs ra) {
    const int z = blockIdx.z;
    const int i = blockIdx.x * 256 + threadIdx.x;
    if (i >= ra.n4[z]) return;
    float4 v = ((const float4*)ra.src[z])[i];
    __half2 h0 = __floats2half2_rn(v.x, v.y);
    __half2 h1 = __floats2half2_rn(v.z, v.w);
    uint2 u;
    u.x = *(uint32_t*)&h0;
    u.y = *(uint32_t*)&h1;
    ((uint2*)ra.dst[z])[i] = u;
}

// ---------------------------------------------------------------------------
// Pipelined TN GEMM (fp16 HMMA):  C[M,N] = A[M,K] * W[N,K]^T + bias[N]
// CTA 128x128 with FOUR warps (128 threads), warp tile 64x64 (2x2 grid):
// halves smem fragment traffic per FLOP vs 64x32 warps while keeping
// 96KB/CTA => 2 CTA/SM. K-tile 64, 3-stage cp.async ring, m16n8k16 HMMA.
// Output modes: 0 = fp16 to Ch (Q-proj), 1 = permuted fp32 into new_kv
// (K/V proj land directly in d_out), 2 = plain fp32 (O-proj).
// ---------------------------------------------------------------------------
#define NST        3
#define TILE_B     16384                 // 128 rows * 128 bytes
#define GEMM_SMEM  (2 * NST * TILE_B + 1024)
#define NKT        (D_MODEL / 64)        // 32 k-tiles

struct ProjArgs {
    const __half* A[3];
    const __half* W[3];
    const float*  Bias[3];
    float*        C[3];
    __half*       Ch[3];
    int           mode[3];
};

__global__ __launch_bounds__(128, 2) void gemm_tc(ProjArgs args) {
    extern __shared__ char dyn_smem[];
    char* db = (char*)(((uintptr_t)dyn_smem + 1023) & ~(uintptr_t)1023);
    const uint32_t db_u = smem_u32(db);

    const int z = blockIdx.z;
    const __half* __restrict__ A    = args.A[z];
    const __half* __restrict__ W    = args.W[z];
    const float*  __restrict__ bias = args.Bias[z];
    float* __restrict__        C    = args.C[z];
    __half* __restrict__       Ch   = args.Ch[z];
    const int mode = args.mode[z];

    const int tid  = threadIdx.x;
    const int lane = tid & 31;
    const int w    = tid >> 5;     // 0..3
    const int wm   = w >> 1;       // 0..1
    const int wn   = w & 1;        // 0..1
    const int n0   = blockIdx.x * 128;
    const int m0   = blockIdx.y * 128;

    const __half* Ag = A + (size_t)m0 * D_MODEL;
    const __half* Wg = W + (size_t)n0 * D_MODEL;

    // per-thread load geometry: 8 chunks A + 8 chunks B per stage (128 thr)
    uint32_t swoff[8];
    size_t   gofs[8];
#pragma unroll
    for (int rep = 0; rep < 8; rep++) {
        const int g = rep * 128 + tid;          // 0..1023
        const int r = g >> 3;                   // row 0..127
        const int i = g & 7;                    // 16B chunk
        gofs[rep]  = (size_t)r * D_MODEL + i * 8;
        swoff[rep] = (uint32_t)((r * 128 + i * 16) ^ ((r & 7) << 4));
    }

    float acc[4][8][4];
#pragma unroll
    for (int i = 0; i < 4; i++)
#pragma unroll
        for (int j = 0; j < 8; j++)
#pragma unroll
            for (int k = 0; k < 4; k++) acc[i][j][k] = 0.f;

    auto issue = [&](int ks) {
        const int slot = ks % NST;
        const int kc   = ks * 64;
        const uint32_t da  = db_u + slot * TILE_B;
        const uint32_t dbb = db_u + NST * TILE_B + slot * TILE_B;
#pragma unroll
        for (int rep = 0; rep < 8; rep++)
            cp_async16(da + swoff[rep], Ag + gofs[rep] + kc);
#pragma unroll
        for (int rep = 0; rep < 8; rep++)
            cp_async16(dbb + swoff[rep], Wg + gofs[rep] + kc);
        CP_COMMIT();
    };

    issue(0);
    issue(1);

    const int m_ = lane >> 3;
    const int rr = lane & 7;
    const int a_row_base = wm * 64 + (m_ & 1) * 8 + rr;   // + mf*16
    const int b_row_base = wn * 64 + (m_ & 1) * 8 + rr;   // + nf2*16
    const int k_half     = (m_ >> 1) * 16;

#pragma unroll 1
    for (int kt = 0; kt < NKT; kt++) {
        if (kt < NKT - 2) { CP_WAIT(1); } else { CP_WAIT(0); }
        __syncthreads();
        if (kt + 2 < NKT) issue(kt + 2);

        const int slot = kt % NST;
        const uint32_t da  = db_u + slot * TILE_B;
        const uint32_t dbb = db_u + NST * TILE_B + slot * TILE_B;

#pragma unroll
        for (int ks = 0; ks < 4; ks++) {
            const int kb = ks * 32 + k_half;
            uint32_t a[4][4], b[8][2];
#pragma unroll
            for (int mf = 0; mf < 4; mf++) {
                const int row = a_row_base + mf * 16;
                const uint32_t off = (uint32_t)((row * 128 + kb) ^ ((row & 7) << 4));
                ldsm_x4(a[mf], da + off);
            }
#pragma unroll
            for (int nf2 = 0; nf2 < 4; nf2++) {
                const int row = b_row_base + nf2 * 16;
                const uint32_t off = (uint32_t)((row * 128 + kb) ^ ((row & 7) << 4));
                uint32_t t[4];
                ldsm_x4(t, dbb + off);
                b[nf2 * 2][0]     = t[0]; b[nf2 * 2][1]     = t[2];
                b[nf2 * 2 + 1][0] = t[1]; b[nf2 * 2 + 1][1] = t[3];
            }
#pragma unroll
            for (int mf = 0; mf < 4; mf++)
#pragma unroll
                for (int nf = 0; nf < 8; nf++)
                    mma_f16(acc[mf][nf], a[mf], b[nf]);
        }
    }

    // epilogue (per mode)
#pragma unroll
    for (int mf = 0; mf < 4; mf++) {
#pragma unroll
        for (int nf = 0; nf < 8; nf++) {
            const int row = m0 + wm * 64 + mf * 16 + (lane >> 2);
            const int col = n0 + wn * 64 + nf * 8 + (lane & 3) * 2;
            const float b0 = bias[col], b1 = bias[col + 1];
            const float x0 = acc[mf][nf][0] + b0, x1 = acc[mf][nf][1] + b1;
            const float y0 = acc[mf][nf][2] + b0, y1 = acc[mf][nf][3] + b1;
            if (mode == 0) {
                __half2 h0 = __floats2half2_rn(x0, x1);
                __half2 h1 = __floats2half2_rn(y0, y1);
                *(__half2*)&Ch[(size_t)row * D_MODEL + col]       = h0;
                *(__half2*)&Ch[(size_t)(row + 8) * D_MODEL + col] = h1;
            } else if (mode == 1) {
                // direct write into new_k/new_v (proj half): t' = 1024 + t
                const int h  = col >> 7, d = col & 127;
#pragma unroll
                for (int rep = 0; rep < 2; rep++) {
                    const int rw = row + rep * 8;
                    const int bb = rw >> 10, t = rw & 1023;
                    const int j  = h * 128 + 64 + (t >> 4);
                    const int c  = (t & 15) * 128 + d;
                    float2 v = rep ? make_float2(y0, y1) : make_float2(x0, x1);
                    *(float2*)&C[((size_t)bb * 2048 + j) * 2048 + c] = v;
                }
            } else {
                *(float2*)&C[(size_t)row * D_MODEL + col]       = make_float2(x0, x1);
                *(float2*)&C[(size_t)(row + 8) * D_MODEL + col] = make_float2(y0, y1);
            }
        }
    }
}

// ---------------------------------------------------------------------------
// fp16 flash attention over the cache only (mask tril(TQ,total) => cache half).
// 128 threads (4 warps), 64 q-rows/CTA, 64 kv/tile, K/V double-buffered via
// cp.async. m16n8k16 HMMA; V fragments via ldmatrix.trans.
// qi reversed vs blockIdx.x: heavy (long) CTAs launch first -> better tail.
// ---------------------------------------------------------------------------
#define QOFF 0
#define KOFF 16384
#define VOFF (KOFF + 2 * 16384)
#define POFF (VOFF + 2 * 16384)
#define ATT_SMEM (POFF + 8192)   // 90112

__global__ __launch_bounds__(128, 2) void attn_kernel(
    const __half* __restrict__ gQ,
    const __half* __restrict__ hK,
    const __half* __restrict__ hV,
    __half* __restrict__ gO)
{
    extern __shared__ char smc[];
    const uint32_t sb = smem_u32(smc);
    const int tid = threadIdx.x, lane = tid & 31, w = tid >> 5;
    const int qi = (int)gridDim.x - 1 - blockIdx.x;   // heavy tiles first
    const int h = blockIdx.y, b = blockIdx.z;
    const int q0 = qi * 64;

    const __half* Qg = gQ + ((size_t)b * TQ + q0) * D_MODEL + h * HEAD_DIM;
    const __half* Kg = hK + (size_t)b * CACHE_LEN * D_MODEL + h * HEAD_DIM;
    const __half* Vg = hV + (size_t)b * CACHE_LEN * D_MODEL + h * HEAD_DIM;

    // Q tile 64x128 halves -> swizzled smem (rows 256B)
#pragma unroll
    for (int rep = 0; rep < 8; rep++) {
        const int g = rep * 128 + tid;
        const int r = g >> 4, i = g & 15;
        uint4 v = *(const uint4*)(Qg + (size_t)r * D_MODEL + i * 8);
        *(uint4*)(smc + QOFF + ((r * 256 + i * 16) ^ ((r & 7) << 4))) = v;
    }

    auto issueK = [&](int kt) {
#pragma unroll
        for (int rep = 0; rep < 8; rep++) {
            const int g = rep * 128 + tid;
            const int r = g >> 4, i = g & 15;
            cp_async16(sb + KOFF + (kt & 1) * 16384 + ((r * 256 + i * 16) ^ ((r & 7) << 4)),
                       Kg + (size_t)(kt * 64 + r) * D_MODEL + i * 8);
        }
        CP_COMMIT();
    };
    auto issueV = [&](int kt) {
#pragma unroll
        for (int rep = 0; rep < 8; rep++) {
            const int g = rep * 128 + tid;
            const int r = g >> 4, i = g & 15;
            cp_async16(sb + VOFF + (kt & 1) * 16384 + ((r * 256 + i * 16) ^ ((r & 7) << 4)),
                       Vg + (size_t)(kt * 64 + r) * D_MODEL + i * 8);
        }
        CP_COMMIT();
    };

    issueK(0); issueV(0);
    if (qi >= 1) { issueK(1); issueV(1); } else { CP_COMMIT(); CP_COMMIT(); }

    float acc_o[16][4];
#pragma unroll
    for (int i = 0; i < 16; i++)
#pragma unroll
        for (int j = 0; j < 4; j++) acc_o[i][j] = 0.f;
    float mrow[2] = {-1e30f, -1e30f};
    float lrow[2] = {0.f, 0.f};
    const float sc = 0.08838834764831845f;   // 1/sqrt(128)

    const int m_ = lane >> 3, rr = lane & 7;
    const int kh    = (m_ >> 1) * 16;
    const int a_row = w * 16 + (m_ & 1) * 8 + rr;

    for (int kt = 0; kt <= qi; kt++) {
        CP_WAIT(3);            // K(kt) landed (per-thread)
        __syncthreads();       // all threads' chunks visible (also covers Q on kt=0)

        const uint32_t kbase = sb + KOFF + (kt & 1) * 16384;
        float accs[8][4];
#pragma unroll
        for (int i = 0; i < 8; i++)
#pragma unroll
            for (int j = 0; j < 4; j++) accs[i][j] = 0.f;

#pragma unroll
        for (int ks = 0; ks < 8; ks++) {            // 8 x k16 over headdim 128
            const int colb = ks * 32 + kh;
            uint32_t a[4];
            ldsm_x4(a, sb + QOFF + ((a_row * 256 + colb) ^ ((a_row & 7) << 4)));
            uint32_t bfr[8][2];
#pragma unroll
            for (int nf2 = 0; nf2 < 4; nf2++) {
                const int row = nf2 * 16 + (m_ & 1) * 8 + rr;   // kv rows 0..63
                uint32_t t[4];
                ldsm_x4(t, kbase + ((row * 256 + colb) ^ ((row & 7) << 4)));
                bfr[nf2 * 2][0]     = t[0]; bfr[nf2 * 2][1]     = t[2];
                bfr[nf2 * 2 + 1][0] = t[1]; bfr[nf2 * 2 + 1][1] = t[3];
            }
#pragma unroll
            for (int nf = 0; nf < 8; nf++) mma_f16(accs[nf], a, bfr[nf]);
        }

        // scale + causal mask (diagonal tile only)
#pragma unroll
        for (int nf = 0; nf < 8; nf++)
#pragma unroll
            for (int v = 0; v < 4; v++) accs[nf][v] *= sc;
        if (kt == qi) {
#pragma unroll
            for (int nf = 0; nf < 8; nf++)
#pragma unroll
                for (int r = 0; r < 2; r++)
#pragma unroll
                    for (int j = 0; j < 2; j++) {
                        const int cl = nf * 8 + (lane & 3) * 2 + j;
                        const int rl = w * 16 + (lane >> 2) + r * 8;
                        if (cl > rl) accs[nf][r * 2 + j] = -1e30f;
                    }
        }

        // online softmax + write P (fp16, swizzled)
#pragma unroll
        for (int r = 0; r < 2; r++) {
            float vmax = -1e30f;
#pragma unroll
            for (int nf = 0; nf < 8; nf++) {
                vmax = fmaxf(vmax, accs[nf][r * 2]);
                vmax = fmaxf(vmax, accs[nf][r * 2 + 1]);
            }
            vmax = fmaxf(vmax, __shfl_xor_sync(0xffffffffu, vmax, 1));
            vmax = fmaxf(vmax, __shfl_xor_sync(0xffffffffu, vmax, 2));
            const float mnew = fmaxf(mrow[r], vmax);
            float psum = 0.f;
            const int qr = w * 16 + (lane >> 2) + r * 8;
#pragma unroll
            for (int nf = 0; nf < 8; nf++) {
                const float p0 = __expf(accs[nf][r * 2]     - mnew);
                const float p1 = __expf(accs[nf][r * 2 + 1] - mnew);
                psum += p0 + p1;
                __half2 hp = __floats2half2_rn(p0, p1);
                const uint32_t boff = (uint32_t)(qr * 128 + nf * 16 + (lane & 3) * 4)
                                      ^ ((qr & 7) << 4);
                *(uint32_t*)(smc + POFF + boff) = *(uint32_t*)&hp;
            }
            psum += __shfl_xor_sync(0xffffffffu, psum, 1);
            psum += __shfl_xor_sync(0xffffffffu, psum, 2);
            const float alpha = __expf(mrow[r] - mnew);
            lrow[r] = lrow[r] * alpha + psum;
            mrow[r] = mnew;
#pragma unroll
            for (int nf = 0; nf < 16; nf++) {
                acc_o[nf][r * 2]     *= alpha;
                acc_o[nf][r * 2 + 1] *= alpha;
            }
        }

        CP_WAIT(2);            // V(kt) landed
        __syncthreads();       // ... and visible; all warps done reading K(kt)
        if (kt + 2 <= qi) issueK(kt + 2); else CP_COMMIT();

        // O += P * V  (P from swizzled fp16 smem, V frags via ldmatrix.trans)
        const uint32_t vbase = sb + VOFF + (kt & 1) * 16384;
        const int p_row = w * 16 + (m_ & 1) * 8 + rr;
        const int vr_lane = ((lane >> 3) & 1) * 8 + (lane & 7);
        const int vc_lane = (lane >> 4) * 16;
#pragma unroll
        for (int ks = 0; ks < 4; ks++) {            // 4 x k16 over 64 kv
            const int colb = ks * 32 + kh;
            uint32_t aP[4];
            ldsm_x4(aP, sb + POFF + ((p_row * 128 + colb) ^ ((p_row & 7) << 4)));
#pragma unroll
            for (int dg = 0; dg < 8; dg++) {        // 16 halves of headdim each
                const int vrow = ks * 16 + vr_lane;
                const int vcol = dg * 32 + vc_lane;
                uint32_t t[4];
                ldsm_x4t(t, vbase + ((vrow * 256 + vcol) ^ ((vrow & 7) << 4)));
                uint32_t b0[2] = { t[0], t[1] };
                uint32_t b1[2] = { t[2], t[3] };
                mma_f16(acc_o[dg * 2],     aP, b0);
                mma_f16(acc_o[dg * 2 + 1], aP, b1);
            }
        }
        __syncthreads();       // all warps done reading V(kt)
        if (kt + 2 <= qi) issueV(kt + 2); else CP_COMMIT();
    }

    // normalize + write fp16
#pragma unroll
    for (int nf = 0; nf < 16; nf++)
#pragma unroll
        for (int r = 0; r < 2; r++) {
            const int row = q0 + w * 16 + (lane >> 2) + r * 8;
            const int col = h * HEAD_DIM + nf * 8 + (lane & 3) * 2;
            const float inv = 1.f / lrow[r];
            __half2 hv = __floats2half2_rn(acc_o[nf][r * 2] * inv,
                                           acc_o[nf][r * 2 + 1] * inv);
            *(__half2*)&gO[((size_t)b * TQ + row) * D_MODEL + col] = hv;
        }
}

// ---------------------------------------------------------------------------
// cache pass, fused: permuted fp32 cache half of new_k/new_v into d_out AND
// fp16 rounding of the caches for attention (single read of each cache).
// grid.z: 0 -> K, 1 -> V. 2097152 float4 per tensor.
// ---------------------------------------------------------------------------
__global__ __launch_bounds__(256) void copy_cache_kv(
    const float* __restrict__ cacheK,
    const float* __restrict__ cacheV,
    float* __restrict__ dstK,
    float* __restrict__ dstV,
    __half* __restrict__ hcK,
    __half* __restrict__ hcV)
{
    const int i = blockIdx.x * 256 + threadIdx.x;
    const int b   = i >> 19;            // 524288 float4 per batch
    const int rem = i & 524287;
    const int jj  = rem >> 9;           // 0..1023 (h*64 + cache row)
    const int c   = (rem & 511) * 4;
    const int h   = jj >> 6;
    const int j   = h * 128 + (jj & 63);
    const int t   = (jj & 63) * 16 + (c >> 7);
    const int d   = c & 127;

    const float* cache = blockIdx.z ? cacheV : cacheK;
    float*       dst   = blockIdx.z ? dstV   : dstK;
    __half*      hc    = blockIdx.z ? hcV    : hcK;

    const size_t src_off = ((size_t)b * CACHE_LEN + t) * D_MODEL + h * HEAD_DIM + d;
    float4 v = *(const float4*)&cache[src_off];
    *(float4*)&dst[((size_t)b * 2048 + j) * D_MODEL + c] = v;

    __half2 h0 = __floats2half2_rn(v.x, v.y);
    __half2 h1 = __floats2half2_rn(v.z, v.w);
    uint2 u;
    u.x = *(uint32_t*)&h0;
    u.y = *(uint32_t*)&h1;
    *(uint2*)&hc[src_off] = u;
}

// ---------------------------------------------------------------------------
// launch — serial single stream (overlap experiment R7 regressed; reverted)
// ---------------------------------------------------------------------------
extern "C" void kernel_launch(void* const* d_in, const int* in_sizes, int n_in,
                              void* d_out, int out_size)
{
    const float* query   = (const float*)d_in[0];
    const float* key     = (const float*)d_in[1];
    const float* value   = (const float*)d_in[2];
    const float* cacheK  = (const float*)d_in[3];
    const float* cacheV  = (const float*)d_in[4];
    const float* Wq      = (const float*)d_in[5];
    const float* bq      = (const float*)d_in[6];
    const float* Wk      = (const float*)d_in[7];
    const float* bk      = (const float*)d_in[8];
    const float* Wv      = (const float*)d_in[9];
    const float* bv      = (const float*)d_in[10];
    const float* Wo      = (const float*)d_in[11];
    const float* bo      = (const float*)d_in[12];
    float* out = (float*)d_out;

    __half *phQ, *pO, *phq, *phk, *phv, *phWq, *phWk, *phWv, *phWo, *phck, *phcv;
    cudaGetSymbolAddress((void**)&phQ, g_hQ);
    cudaGetSymbolAddress((void**)&pO, g_O);
    cudaGetSymbolAddress((void**)&phq, g_hq);
    cudaGetSymbolAddress((void**)&phk, g_hk);
    cudaGetSymbolAddress((void**)&phv, g_hv);
    cudaGetSymbolAddress((void**)&phWq, g_hWq);
    cudaGetSymbolAddress((void**)&phWk, g_hWk);
    cudaGetSymbolAddress((void**)&phWv, g_hWv);
    cudaGetSymbolAddress((void**)&phWo, g_hWo);
    cudaGetSymbolAddress((void**)&phck, g_hck);
    cudaGetSymbolAddress((void**)&phcv, g_hcv);

    cudaFuncSetAttribute(gemm_tc, cudaFuncAttributeMaxDynamicSharedMemorySize,
                         GEMM_SMEM);
    cudaFuncSetAttribute(attn_kernel, cudaFuncAttributeMaxDynamicSharedMemorySize,
                         ATT_SMEM);

    const int NA = M_ROWS * D_MODEL / 4;     // 2097152 float4
    const int NW = D_MODEL * D_MODEL / 4;    // 1048576 float4

    // 1) pre-round inputs to fp16 (caches handled by the fused cache pass)
    RoundArgs ra;
    ra.src[0] = query; ra.dst[0] = phq;  ra.n4[0] = NA;
    ra.src[1] = key;   ra.dst[1] = phk;  ra.n4[1] = NA;
    ra.src[2] = value; ra.dst[2] = phv;  ra.n4[2] = NA;
    ra.src[3] = Wq;    ra.dst[3] = phWq; ra.n4[3] = NW;
    ra.src[4] = Wk;    ra.dst[4] = phWk; ra.n4[4] = NW;
    ra.src[5] = Wv;    ra.dst[5] = phWv; ra.n4[5] = NW;
    ra.src[6] = Wo;    ra.dst[6] = phWo; ra.n4[6] = NW;
    round_f16<<<dim3(NA / 256, 1, 7), 256>>>(ra);

    // 2) cache pass: permuted fp32 halves into d_out + fp16 caches for attn
    copy_cache_kv<<<dim3(2097152 / 256, 1, 2), 256>>>(
        cacheK, cacheV, out + 8388608, out + 25165824, phck, phcv);

    // 3) Q/K/V projections. Q -> fp16 scratch; K/V -> straight into d_out.
    ProjArgs pa;
    pa.A[0] = phq;  pa.W[0] = phWq; pa.Bias[0] = bq;
    pa.Ch[0] = phQ; pa.C[0] = nullptr;            pa.mode[0] = 0;
    pa.A[1] = phk;  pa.W[1] = phWk; pa.Bias[1] = bk;
    pa.Ch[1] = nullptr; pa.C[1] = out + 8388608;  pa.mode[1] = 1;
    pa.A[2] = phv;  pa.W[2] = phWv; pa.Bias[2] = bv;
    pa.Ch[2] = nullptr; pa.C[2] = out + 25165824; pa.mode[2] = 1;
    gemm_tc<<<dim3(D_MODEL / 128, M_ROWS / 128, 3), 128, GEMM_SMEM>>>(pa);

    // 4) attention (cache-only, causal), fp16 HMMA
    attn_kernel<<<dim3(TQ / 64, NUM_HEADS, BATCH), 128, ATT_SMEM>>>(
        phQ, phck, phcv, pO);

    // 5) output projection -> out[0 .. 8388608)
    ProjArgs po;
    po.A[0] = pO; po.W[0] = phWo; po.Bias[0] = bo;
    po.C[0] = out; po.Ch[0] = nullptr; po.mode[0] = 2;
    po.A[1] = po.A[0]; po.W[1] = po.W[0]; po.Bias[1] = po.Bias[0];
    po.C[1] = po.C[0]; po.Ch[1] = nullptr; po.mode[1] = 2;
    po.A[2] = po.A[0]; po.W[2] = po.W[0]; po.Bias[2] = po.Bias[0];
    po.C[2] = po.C[0]; po.Ch[2] = nullptr; po.mode[2] = 2;
    gemm_tc<<<dim3(D_MODEL / 128, M_ROWS / 128, 1), 128, GEMM_SMEM>>>(po);
}

// round 9
// speedup vs baseline: 1.1723x; 1.0080x over previous
#include <cuda_runtime.h>
#include <cuda_bf16.h>
#include <cuda_fp16.h>
#include <cstdint>
#include <cstdio>

// ---------------------------------------------------------------------------
// Problem constants
// ---------------------------------------------------------------------------
#define D_MODEL   2048
#define NUM_HEADS 16
#define HEAD_DIM  128
#define BATCH     4
#define TQ        1024
#define CACHE_LEN 1024
#define M_ROWS    (BATCH * TQ)          // 4096

// scratch (device globals: allocation-free scratch per harness rules)
__device__ __half g_hQ[M_ROWS * D_MODEL];             // projected Q, fp16
__device__ __half g_O[M_ROWS * D_MODEL];              // attention out, fp16
// fp16 pre-rounded inputs
__device__ __half g_hq[M_ROWS * D_MODEL];
__device__ __half g_hk[M_ROWS * D_MODEL];
__device__ __half g_hv[M_ROWS * D_MODEL];
__device__ __half g_hWq[D_MODEL * D_MODEL];
__device__ __half g_hWk[D_MODEL * D_MODEL];
__device__ __half g_hWv[D_MODEL * D_MODEL];
__device__ __half g_hWo[D_MODEL * D_MODEL];
__device__ __half g_hck[BATCH * CACHE_LEN * D_MODEL]; // fp16 cache K (attention)
__device__ __half g_hcv[BATCH * CACHE_LEN * D_MODEL]; // fp16 cache V (attention)

// ---------------------------------------------------------------------------
// helpers
// ---------------------------------------------------------------------------
__device__ __forceinline__ uint32_t smem_u32(const void* p) {
    uint32_t a;
    asm("{ .reg .u64 t; cvta.to.shared.u64 t, %1; cvt.u32.u64 %0, t; }"
        : "=r"(a) : "l"(p));
    return a;
}

// fp16 m16n8k16: D += A*B  (row.col, f32 accum)
__device__ __forceinline__ void mma_f16(float* d, const uint32_t* a, const uint32_t* b) {
    asm volatile(
        "mma.sync.aligned.m16n8k16.row.col.f32.f16.f16.f32 "
        "{%0,%1,%2,%3}, {%4,%5,%6,%7}, {%8,%9}, {%0,%1,%2,%3};\n"
        : "+f"(d[0]), "+f"(d[1]), "+f"(d[2]), "+f"(d[3])
        : "r"(a[0]), "r"(a[1]), "r"(a[2]), "r"(a[3]),
          "r"(b[0]), "r"(b[1]));
}

__device__ __forceinline__ void ldsm_x4(uint32_t* r, uint32_t addr) {
    asm volatile("ldmatrix.sync.aligned.m8n8.x4.shared.b16 {%0,%1,%2,%3}, [%4];"
                 : "=r"(r[0]), "=r"(r[1]), "=r"(r[2]), "=r"(r[3]) : "r"(addr));
}

__device__ __forceinline__ void ldsm_x4t(uint32_t* r, uint32_t addr) {
    asm volatile("ldmatrix.sync.aligned.m8n8.x4.trans.shared.b16 {%0,%1,%2,%3}, [%4];"
                 : "=r"(r[0]), "=r"(r[1]), "=r"(r[2]), "=r"(r[3]) : "r"(addr));
}

__device__ __forceinline__ void cp_async16(uint32_t dst, const void* src) {
    asm volatile("cp.async.cg.shared.global [%0], [%1], 16;"
                 :: "r"(dst), "l"(src));
}
#define CP_COMMIT()  asm volatile("cp.async.commit_group;" ::: "memory")
#define CP_WAIT(N)   asm volatile("cp.async.wait_group %0;" :: "n"(N) : "memory")

// ---------------------------------------------------------------------------
// pre-rounding pass: dst = fp16(src) for 7 tensors in one launch (grid.z)
// ---------------------------------------------------------------------------
struct RoundArgs {
    const float* src[7];
    __half*      dst[7];
    int          n4[7];     // number of float4 elements
};

__global__ __launch_bounds__(256) void round_f16(RoundArgs ra) {
    const int z = blockIdx.z;
    const int i = blockIdx.x * 256 + threadIdx.x;
    if (i >= ra.n4[z]) return;
    float4 v = ((const float4*)ra.src[z])[i];
    __half2 h0 = __floats2half2_rn(v.x, v.y);
    __half2 h1 = __floats2half2_rn(v.z, v.w);
    uint2 u;
    u.x = *(uint32_t*)&h0;
    u.y = *(uint32_t*)&h1;
    ((uint2*)ra.dst[z])[i] = u;
}

// ---------------------------------------------------------------------------
// Pipelined TN GEMM (fp16 HMMA):  C[M,N] = A[M,K] * W[N,K]^T + bias[N]
// CTA 128x128 with FOUR warps (128 threads), warp tile 64x64 (2x2 grid).
// K-tile 64, 3-stage cp.async ring, m16n8k16 HMMA. (unchanged from R8)
// Output modes: 0 = fp16 to Ch (Q-proj), 1 = permuted fp32 into new_kv
// (K/V proj land directly in d_out), 2 = plain fp32 (O-proj).
// ---------------------------------------------------------------------------
#define NST        3
#define TILE_B     16384                 // 128 rows * 128 bytes
#define GEMM_SMEM  (2 * NST * TILE_B + 1024)
#define NKT        (D_MODEL / 64)        // 32 k-tiles

struct ProjArgs {
    const __half* A[3];
    const __half* W[3];
    const float*  Bias[3];
    float*        C[3];
    __half*       Ch[3];
    int           mode[3];
};

__global__ __launch_bounds__(128, 2) void gemm_tc(ProjArgs args) {
    extern __shared__ char dyn_smem[];
    char* db = (char*)(((uintptr_t)dyn_smem + 1023) & ~(uintptr_t)1023);
    const uint32_t db_u = smem_u32(db);

    const int z = blockIdx.z;
    const __half* __restrict__ A    = args.A[z];
    const __half* __restrict__ W    = args.W[z];
    const float*  __restrict__ bias = args.Bias[z];
    float* __restrict__        C    = args.C[z];
    __half* __restrict__       Ch   = args.Ch[z];
    const int mode = args.mode[z];

    const int tid  = threadIdx.x;
    const int lane = tid & 31;
    const int w    = tid >> 5;     // 0..3
    const int wm   = w >> 1;       // 0..1
    const int wn   = w & 1;        // 0..1
    const int n0   = blockIdx.x * 128;
    const int m0   = blockIdx.y * 128;

    const __half* Ag = A + (size_t)m0 * D_MODEL;
    const __half* Wg = W + (size_t)n0 * D_MODEL;

    // per-thread load geometry: 8 chunks A + 8 chunks B per stage (128 thr)
    uint32_t swoff[8];
    size_t   gofs[8];
#pragma unroll
    for (int rep = 0; rep < 8; rep++) {
        const int g = rep * 128 + tid;          // 0..1023
        const int r = g >> 3;                   // row 0..127
        const int i = g & 7;                    // 16B chunk
        gofs[rep]  = (size_t)r * D_MODEL + i * 8;
        swoff[rep] = (uint32_t)((r * 128 + i * 16) ^ ((r & 7) << 4));
    }

    float acc[4][8][4];
#pragma unroll
    for (int i = 0; i < 4; i++)
#pragma unroll
        for (int j = 0; j < 8; j++)
#pragma unroll
            for (int k = 0; k < 4; k++) acc[i][j][k] = 0.f;

    auto issue = [&](int ks) {
        const int slot = ks % NST;
        const int kc   = ks * 64;
        const uint32_t da  = db_u + slot * TILE_B;
        const uint32_t dbb = db_u + NST * TILE_B + slot * TILE_B;
#pragma unroll
        for (int rep = 0; rep < 8; rep++)
            cp_async16(da + swoff[rep], Ag + gofs[rep] + kc);
#pragma unroll
        for (int rep = 0; rep < 8; rep++)
            cp_async16(dbb + swoff[rep], Wg + gofs[rep] + kc);
        CP_COMMIT();
    };

    issue(0);
    issue(1);

    const int m_ = lane >> 3;
    const int rr = lane & 7;
    const int a_row_base = wm * 64 + (m_ & 1) * 8 + rr;   // + mf*16
    const int b_row_base = wn * 64 + (m_ & 1) * 8 + rr;   // + nf2*16
    const int k_half     = (m_ >> 1) * 16;

#pragma unroll 1
    for (int kt = 0; kt < NKT; kt++) {
        if (kt < NKT - 2) { CP_WAIT(1); } else { CP_WAIT(0); }
        __syncthreads();
        if (kt + 2 < NKT) issue(kt + 2);

        const int slot = kt % NST;
        const uint32_t da  = db_u + slot * TILE_B;
        const uint32_t dbb = db_u + NST * TILE_B + slot * TILE_B;

#pragma unroll
        for (int ks = 0; ks < 4; ks++) {
            const int kb = ks * 32 + k_half;
            uint32_t a[4][4], b[8][2];
#pragma unroll
            for (int mf = 0; mf < 4; mf++) {
                const int row = a_row_base + mf * 16;
                const uint32_t off = (uint32_t)((row * 128 + kb) ^ ((row & 7) << 4));
                ldsm_x4(a[mf], da + off);
            }
#pragma unroll
            for (int nf2 = 0; nf2 < 4; nf2++) {
                const int row = b_row_base + nf2 * 16;
                const uint32_t off = (uint32_t)((row * 128 + kb) ^ ((row & 7) << 4));
                uint32_t t[4];
                ldsm_x4(t, dbb + off);
                b[nf2 * 2][0]     = t[0]; b[nf2 * 2][1]     = t[2];
                b[nf2 * 2 + 1][0] = t[1]; b[nf2 * 2 + 1][1] = t[3];
            }
#pragma unroll
            for (int mf = 0; mf < 4; mf++)
#pragma unroll
                for (int nf = 0; nf < 8; nf++)
                    mma_f16(acc[mf][nf], a[mf], b[nf]);
        }
    }

    // epilogue (per mode)
#pragma unroll
    for (int mf = 0; mf < 4; mf++) {
#pragma unroll
        for (int nf = 0; nf < 8; nf++) {
            const int row = m0 + wm * 64 + mf * 16 + (lane >> 2);
            const int col = n0 + wn * 64 + nf * 8 + (lane & 3) * 2;
            const float b0 = bias[col], b1 = bias[col + 1];
            const float x0 = acc[mf][nf][0] + b0, x1 = acc[mf][nf][1] + b1;
            const float y0 = acc[mf][nf][2] + b0, y1 = acc[mf][nf][3] + b1;
            if (mode == 0) {
                __half2 h0 = __floats2half2_rn(x0, x1);
                __half2 h1 = __floats2half2_rn(y0, y1);
                *(__half2*)&Ch[(size_t)row * D_MODEL + col]       = h0;
                *(__half2*)&Ch[(size_t)(row + 8) * D_MODEL + col] = h1;
            } else if (mode == 1) {
                // direct write into new_k/new_v (proj half): t' = 1024 + t
                const int h  = col >> 7, d = col & 127;
#pragma unroll
                for (int rep = 0; rep < 2; rep++) {
                    const int rw = row + rep * 8;
                    const int bb = rw >> 10, t = rw & 1023;
                    const int j  = h * 128 + 64 + (t >> 4);
                    const int c  = (t & 15) * 128 + d;
                    float2 v = rep ? make_float2(y0, y1) : make_float2(x0, x1);
                    *(float2*)&C[((size_t)bb * 2048 + j) * 2048 + c] = v;
                }
            } else {
                *(float2*)&C[(size_t)row * D_MODEL + col]       = make_float2(x0, x1);
                *(float2*)&C[(size_t)(row + 8) * D_MODEL + col] = make_float2(y0, y1);
            }
        }
    }
}

// ---------------------------------------------------------------------------
// fp16 flash attention over the cache only (mask tril(TQ,total) => cache half).
// 128 threads (4 warps), 64 q-rows/CTA, 64 kv/tile, K/V double-buffered via
// cp.async. m16n8k16 HMMA; V fragments via ldmatrix.trans.
// P NEVER touches SMEM: the S-accumulator layout equals the PV A-fragment
// layout, so softmax packs half2 pairs straight into A-fragments.
// SMEM: Q 16K | K0 K1 32K | V0 V1 32K = 80K, 2 CTA/SM.
// qi reversed vs blockIdx.x: heavy (long) CTAs launch first -> better tail.
// ---------------------------------------------------------------------------
#define QOFF 0
#define KOFF 16384
#define VOFF (KOFF + 2 * 16384)
#define ATT_SMEM (VOFF + 2 * 16384)   // 81920

__global__ __launch_bounds__(128, 2) void attn_kernel(
    const __half* __restrict__ gQ,
    const __half* __restrict__ hK,
    const __half* __restrict__ hV,
    __half* __restrict__ gO)
{
    extern __shared__ char smc[];
    const uint32_t sb = smem_u32(smc);
    const int tid = threadIdx.x, lane = tid & 31, w = tid >> 5;
    const int qi = (int)gridDim.x - 1 - blockIdx.x;   // heavy tiles first
    const int h = blockIdx.y, b = blockIdx.z;
    const int q0 = qi * 64;

    const __half* Qg = gQ + ((size_t)b * TQ + q0) * D_MODEL + h * HEAD_DIM;
    const __half* Kg = hK + (size_t)b * CACHE_LEN * D_MODEL + h * HEAD_DIM;
    const __half* Vg = hV + (size_t)b * CACHE_LEN * D_MODEL + h * HEAD_DIM;

    // Q tile 64x128 halves -> swizzled smem (rows 256B)
#pragma unroll
    for (int rep = 0; rep < 8; rep++) {
        const int g = rep * 128 + tid;
        const int r = g >> 4, i = g & 15;
        uint4 v = *(const uint4*)(Qg + (size_t)r * D_MODEL + i * 8);
        *(uint4*)(smc + QOFF + ((r * 256 + i * 16) ^ ((r & 7) << 4))) = v;
    }

    auto issueK = [&](int kt) {
#pragma unroll
        for (int rep = 0; rep < 8; rep++) {
            const int g = rep * 128 + tid;
            const int r = g >> 4, i = g & 15;
            cp_async16(sb + KOFF + (kt & 1) * 16384 + ((r * 256 + i * 16) ^ ((r & 7) << 4)),
                       Kg + (size_t)(kt * 64 + r) * D_MODEL + i * 8);
        }
        CP_COMMIT();
    };
    auto issueV = [&](int kt) {
#pragma unroll
        for (int rep = 0; rep < 8; rep++) {
            const int g = rep * 128 + tid;
            const int r = g >> 4, i = g & 15;
            cp_async16(sb + VOFF + (kt & 1) * 16384 + ((r * 256 + i * 16) ^ ((r & 7) << 4)),
                       Vg + (size_t)(kt * 64 + r) * D_MODEL + i * 8);
        }
        CP_COMMIT();
    };

    issueK(0); issueV(0);
    if (qi >= 1) { issueK(1); issueV(1); } else { CP_COMMIT(); CP_COMMIT(); }

    float acc_o[16][4];
#pragma unroll
    for (int i = 0; i < 16; i++)
#pragma unroll
        for (int j = 0; j < 4; j++) acc_o[i][j] = 0.f;
    float mrow[2] = {-1e30f, -1e30f};
    float lrow[2] = {0.f, 0.f};
    const float sc = 0.08838834764831845f;   // 1/sqrt(128)

    const int m_ = lane >> 3, rr = lane & 7;
    const int kh    = (m_ >> 1) * 16;
    const int a_row = w * 16 + (m_ & 1) * 8 + rr;

    for (int kt = 0; kt <= qi; kt++) {
        CP_WAIT(3);            // K(kt) landed (per-thread)
        __syncthreads();       // all threads' chunks visible (also covers Q on kt=0)

        const uint32_t kbase = sb + KOFF + (kt & 1) * 16384;
        float accs[8][4];
#pragma unroll
        for (int i = 0; i < 8; i++)
#pragma unroll
            for (int j = 0; j < 4; j++) accs[i][j] = 0.f;

#pragma unroll
        for (int ks = 0; ks < 8; ks++) {            // 8 x k16 over headdim 128
            const int colb = ks * 32 + kh;
            uint32_t a[4];
            ldsm_x4(a, sb + QOFF + ((a_row * 256 + colb) ^ ((a_row & 7) << 4)));
            uint32_t bfr[8][2];
#pragma unroll
            for (int nf2 = 0; nf2 < 4; nf2++) {
                const int row = nf2 * 16 + (m_ & 1) * 8 + rr;   // kv rows 0..63
                uint32_t t[4];
                ldsm_x4(t, kbase + ((row * 256 + colb) ^ ((row & 7) << 4)));
                bfr[nf2 * 2][0]     = t[0]; bfr[nf2 * 2][1]     = t[2];
                bfr[nf2 * 2 + 1][0] = t[1]; bfr[nf2 * 2 + 1][1] = t[3];
            }
#pragma unroll
            for (int nf = 0; nf < 8; nf++) mma_f16(accs[nf], a, bfr[nf]);
        }

        // scale + causal mask (diagonal tile only)
#pragma unroll
        for (int nf = 0; nf < 8; nf++)
#pragma unroll
            for (int v = 0; v < 4; v++) accs[nf][v] *= sc;
        if (kt == qi) {
#pragma unroll
            for (int nf = 0; nf < 8; nf++)
#pragma unroll
                for (int r = 0; r < 2; r++)
#pragma unroll
                    for (int j = 0; j < 2; j++) {
                        const int cl = nf * 8 + (lane & 3) * 2 + j;
                        const int rl = w * 16 + (lane >> 2) + r * 8;
                        if (cl > rl) accs[nf][r * 2 + j] = -1e30f;
                    }
        }

        // online softmax -> P packed directly into A-fragment registers
        uint32_t ph[8][2];
#pragma unroll
        for (int r = 0; r < 2; r++) {
            float vmax = -1e30f;
#pragma unroll
            for (int nf = 0; nf < 8; nf++) {
                vmax = fmaxf(vmax, accs[nf][r * 2]);
                vmax = fmaxf(vmax, accs[nf][r * 2 + 1]);
            }
            vmax = fmaxf(vmax, __shfl_xor_sync(0xffffffffu, vmax, 1));
            vmax = fmaxf(vmax, __shfl_xor_sync(0xffffffffu, vmax, 2));
            const float mnew = fmaxf(mrow[r], vmax);
            float psum = 0.f;
#pragma unroll
            for (int nf = 0; nf < 8; nf++) {
                const float p0 = __expf(accs[nf][r * 2]     - mnew);
                const float p1 = __expf(accs[nf][r * 2 + 1] - mnew);
                psum += p0 + p1;
                __half2 hp = __floats2half2_rn(p0, p1);
                ph[nf][r] = *(uint32_t*)&hp;
            }
            psum += __shfl_xor_sync(0xffffffffu, psum, 1);
            psum += __shfl_xor_sync(0xffffffffu, psum, 2);
            const float alpha = __expf(mrow[r] - mnew);
            lrow[r] = lrow[r] * alpha + psum;
            mrow[r] = mnew;
#pragma unroll
            for (int nf = 0; nf < 16; nf++) {
                acc_o[nf][r * 2]     *= alpha;
                acc_o[nf][r * 2 + 1] *= alpha;
            }
        }

        CP_WAIT(2);            // V(kt) landed
        __syncthreads();       // ... and visible; all warps done reading K(kt)
        if (kt + 2 <= qi) issueK(kt + 2); else CP_COMMIT();

        // O += P * V  (P A-frags straight from registers; V via ldmatrix.trans)
        const uint32_t vbase = sb + VOFF + (kt & 1) * 16384;
        const int vr_lane = ((lane >> 3) & 1) * 8 + (lane & 7);
        const int vc_lane = (lane >> 4) * 16;
#pragma unroll
        for (int ks = 0; ks < 4; ks++) {            // 4 x k16 over 64 kv
            uint32_t aP[4];
            aP[0] = ph[2 * ks][0];
            aP[1] = ph[2 * ks][1];
            aP[2] = ph[2 * ks + 1][0];
            aP[3] = ph[2 * ks + 1][1];
#pragma unroll
            for (int dg = 0; dg < 8; dg++) {        // 16 halves of headdim each
                const int vrow = ks * 16 + vr_lane;
                const int vcol = dg * 32 + vc_lane;
                uint32_t t[4];
                ldsm_x4t(t, vbase + ((vrow * 256 + vcol) ^ ((vrow & 7) << 4)));
                uint32_t b0[2] = { t[0], t[1] };
                uint32_t b1[2] = { t[2], t[3] };
                mma_f16(acc_o[dg * 2],     aP, b0);
                mma_f16(acc_o[dg * 2 + 1], aP, b1);
            }
        }
        __syncthreads();       // all warps done reading V(kt)
        if (kt + 2 <= qi) issueV(kt + 2); else CP_COMMIT();
    }

    // normalize + write fp16
#pragma unroll
    for (int nf = 0; nf < 16; nf++)
#pragma unroll
        for (int r = 0; r < 2; r++) {
            const int row = q0 + w * 16 + (lane >> 2) + r * 8;
            const int col = h * HEAD_DIM + nf * 8 + (lane & 3) * 2;
            const float inv = 1.f / lrow[r];
            __half2 hv = __floats2half2_rn(acc_o[nf][r * 2] * inv,
                                           acc_o[nf][r * 2 + 1] * inv);
            *(__half2*)&gO[((size_t)b * TQ + row) * D_MODEL + col] = hv;
        }
}

// ---------------------------------------------------------------------------
// cache pass, fused: permuted fp32 cache half of new_k/new_v into d_out AND
// fp16 rounding of the caches for attention (single read of each cache).
// grid.z: 0 -> K, 1 -> V. 2097152 float4 per tensor.
// ---------------------------------------------------------------------------
__global__ __launch_bounds__(256) void copy_cache_kv(
    const float* __restrict__ cacheK,
    const float* __restrict__ cacheV,
    float* __restrict__ dstK,
    float* __restrict__ dstV,
    __half* __restrict__ hcK,
    __half* __restrict__ hcV)
{
    const int i = blockIdx.x * 256 + threadIdx.x;
    const int b   = i >> 19;            // 524288 float4 per batch
    const int rem = i & 524287;
    const int jj  = rem >> 9;           // 0..1023 (h*64 + cache row)
    const int c   = (rem & 511) * 4;
    const int h   = jj >> 6;
    const int j   = h * 128 + (jj & 63);
    const int t   = (jj & 63) * 16 + (c >> 7);
    const int d   = c & 127;

    const float* cache = blockIdx.z ? cacheV : cacheK;
    float*       dst   = blockIdx.z ? dstV   : dstK;
    __half*      hc    = blockIdx.z ? hcV    : hcK;

    const size_t src_off = ((size_t)b * CACHE_LEN + t) * D_MODEL + h * HEAD_DIM + d;
    float4 v = *(const float4*)&cache[src_off];
    *(float4*)&dst[((size_t)b * 2048 + j) * D_MODEL + c] = v;

    __half2 h0 = __floats2half2_rn(v.x, v.y);
    __half2 h1 = __floats2half2_rn(v.z, v.w);
    uint2 u;
    u.x = *(uint32_t*)&h0;
    u.y = *(uint32_t*)&h1;
    *(uint2*)&hc[src_off] = u;
}

// ---------------------------------------------------------------------------
// launch — serial single stream
// ---------------------------------------------------------------------------
extern "C" void kernel_launch(void* const* d_in, const int* in_sizes, int n_in,
                              void* d_out, int out_size)
{
    const float* query   = (const float*)d_in[0];
    const float* key     = (const float*)d_in[1];
    const float* value   = (const float*)d_in[2];
    const float* cacheK  = (const float*)d_in[3];
    const float* cacheV  = (const float*)d_in[4];
    const float* Wq      = (const float*)d_in[5];
    const float* bq      = (const float*)d_in[6];
    const float* Wk      = (const float*)d_in[7];
    const float* bk      = (const float*)d_in[8];
    const float* Wv      = (const float*)d_in[9];
    const float* bv      = (const float*)d_in[10];
    const float* Wo      = (const float*)d_in[11];
    const float* bo      = (const float*)d_in[12];
    float* out = (float*)d_out;

    __half *phQ, *pO, *phq, *phk, *phv, *phWq, *phWk, *phWv, *phWo, *phck, *phcv;
    cudaGetSymbolAddress((void**)&phQ, g_hQ);
    cudaGetSymbolAddress((void**)&pO, g_O);
    cudaGetSymbolAddress((void**)&phq, g_hq);
    cudaGetSymbolAddress((void**)&phk, g_hk);
    cudaGetSymbolAddress((void**)&phv, g_hv);
    cudaGetSymbolAddress((void**)&phWq, g_hWq);
    cudaGetSymbolAddress((void**)&phWk, g_hWk);
    cudaGetSymbolAddress((void**)&phWv, g_hWv);
    cudaGetSymbolAddress((void**)&phWo, g_hWo);
    cudaGetSymbolAddress((void**)&phck, g_hck);
    cudaGetSymbolAddress((void**)&phcv, g_hcv);

    cudaFuncSetAttribute(gemm_tc, cudaFuncAttributeMaxDynamicSharedMemorySize,
                         GEMM_SMEM);
    cudaFuncSetAttribute(attn_kernel, cudaFuncAttributeMaxDynamicSharedMemorySize,
                         ATT_SMEM);

    const int NA = M_ROWS * D_MODEL / 4;     // 2097152 float4
    const int NW = D_MODEL * D_MODEL / 4;    // 1048576 float4

    // 1) pre-round inputs to fp16 (caches handled by the fused cache pass)
    RoundArgs ra;
    ra.src[0] = query; ra.dst[0] = phq;  ra.n4[0] = NA;
    ra.src[1] = key;   ra.dst[1] = phk;  ra.n4[1] = NA;
    ra.src[2] = value; ra.dst[2] = phv;  ra.n4[2] = NA;
    ra.src[3] = Wq;    ra.dst[3] = phWq; ra.n4[3] = NW;
    ra.src[4] = Wk;    ra.dst[4] = phWk; ra.n4[4] = NW;
    ra.src[5] = Wv;    ra.dst[5] = phWv; ra.n4[5] = NW;
    ra.src[6] = Wo;    ra.dst[6] = phWo; ra.n4[6] = NW;
    round_f16<<<dim3(NA / 256, 1, 7), 256>>>(ra);

    // 2) cache pass: permuted fp32 halves into d_out + fp16 caches for attn
    copy_cache_kv<<<dim3(2097152 / 256, 1, 2), 256>>>(
        cacheK, cacheV, out + 8388608, out + 25165824, phck, phcv);

    // 3) Q/K/V projections. Q -> fp16 scratch; K/V -> straight into d_out.
    ProjArgs pa;
    pa.A[0] = phq;  pa.W[0] = phWq; pa.Bias[0] = bq;
    pa.Ch[0] = phQ; pa.C[0] = nullptr;            pa.mode[0] = 0;
    pa.A[1] = phk;  pa.W[1] = phWk; pa.Bias[1] = bk;
    pa.Ch[1] = nullptr; pa.C[1] = out + 8388608;  pa.mode[1] = 1;
    pa.A[2] = phv;  pa.W[2] = phWv; pa.Bias[2] = bv;
    pa.Ch[2] = nullptr; pa.C[2] = out + 25165824; pa.mode[2] = 1;
    gemm_tc<<<dim3(D_MODEL / 128, M_ROWS / 128, 3), 128, GEMM_SMEM>>>(pa);

    // 4) attention (cache-only, causal), fp16 HMMA, P-in-registers
    attn_kernel<<<dim3(TQ / 64, NUM_HEADS, BATCH), 128, ATT_SMEM>>>(
        phQ, phck, phcv, pO);

    // 5) output projection -> out[0 .. 8388608)
    ProjArgs po;
    po.A[0] = pO; po.W[0] = phWo; po.Bias[0] = bo;
    po.C[0] = out; po.Ch[0] = nullptr; po.mode[0] = 2;
    po.A[1] = po.A[0]; po.W[1] = po.W[0]; po.Bias[1] = po.Bias[0];
    po.C[1] = po.C[0]; po.Ch[1] = nullptr; po.mode[1] = 2;
    po.A[2] = po.A[0]; po.W[2] = po.W[0]; po.Bias[2] = po.Bias[0];
    po.C[2] = po.C[0]; po.Ch[2] = nullptr; po.mode[2] = 2;
    gemm_tc<<<dim3(D_MODEL / 128, M_ROWS / 128, 1), 128, GEMM_SMEM>>>(po);
}

// round 10
// speedup vs baseline: 1.1892x; 1.0144x over previous
#include <cuda_runtime.h>
#include <cuda_bf16.h>
#include <cuda_fp16.h>
#include <cstdint>
#include <cstdio>

// ---------------------------------------------------------------------------
// Problem constants
// ---------------------------------------------------------------------------
#define D_MODEL   2048
#define NUM_HEADS 16
#define HEAD_DIM  128
#define BATCH     4
#define TQ        1024
#define CACHE_LEN 1024
#define M_ROWS    (BATCH * TQ)          // 4096

// scratch (device globals: allocation-free scratch per harness rules)
__device__ __half g_hQ[M_ROWS * D_MODEL];             // projected Q, fp16
__device__ __half g_O[M_ROWS * D_MODEL];              // attention out, fp16
// fp16 pre-rounded inputs
__device__ __half g_hq[M_ROWS * D_MODEL];
__device__ __half g_hk[M_ROWS * D_MODEL];
__device__ __half g_hv[M_ROWS * D_MODEL];
__device__ __half g_hWq[D_MODEL * D_MODEL];
__device__ __half g_hWk[D_MODEL * D_MODEL];
__device__ __half g_hWv[D_MODEL * D_MODEL];
__device__ __half g_hWo[D_MODEL * D_MODEL];
__device__ __half g_hck[BATCH * CACHE_LEN * D_MODEL]; // fp16 cache K (attention)
__device__ __half g_hcv[BATCH * CACHE_LEN * D_MODEL]; // fp16 cache V (attention)

// ---------------------------------------------------------------------------
// helpers
// ---------------------------------------------------------------------------
__device__ __forceinline__ uint32_t smem_u32(const void* p) {
    uint32_t a;
    asm("{ .reg .u64 t; cvta.to.shared.u64 t, %1; cvt.u32.u64 %0, t; }"
        : "=r"(a) : "l"(p));
    return a;
}

// fp16 m16n8k16: D += A*B  (row.col, f32 accum)
__device__ __forceinline__ void mma_f16(float* d, const uint32_t* a, const uint32_t* b) {
    asm volatile(
        "mma.sync.aligned.m16n8k16.row.col.f32.f16.f16.f32 "
        "{%0,%1,%2,%3}, {%4,%5,%6,%7}, {%8,%9}, {%0,%1,%2,%3};\n"
        : "+f"(d[0]), "+f"(d[1]), "+f"(d[2]), "+f"(d[3])
        : "r"(a[0]), "r"(a[1]), "r"(a[2]), "r"(a[3]),
          "r"(b[0]), "r"(b[1]));
}

__device__ __forceinline__ void ldsm_x4(uint32_t* r, uint32_t addr) {
    asm volatile("ldmatrix.sync.aligned.m8n8.x4.shared.b16 {%0,%1,%2,%3}, [%4];"
                 : "=r"(r[0]), "=r"(r[1]), "=r"(r[2]), "=r"(r[3]) : "r"(addr));
}

__device__ __forceinline__ void ldsm_x4t(uint32_t* r, uint32_t addr) {
    asm volatile("ldmatrix.sync.aligned.m8n8.x4.trans.shared.b16 {%0,%1,%2,%3}, [%4];"
                 : "=r"(r[0]), "=r"(r[1]), "=r"(r[2]), "=r"(r[3]) : "r"(addr));
}

__device__ __forceinline__ void cp_async16(uint32_t dst, const void* src) {
    asm volatile("cp.async.cg.shared.global [%0], [%1], 16;"
                 :: "r"(dst), "l"(src));
}
#define CP_COMMIT()  asm volatile("cp.async.commit_group;" ::: "memory")
#define CP_WAIT(N)   asm volatile("cp.async.wait_group %0;" :: "n"(N) : "memory")

// ---------------------------------------------------------------------------
// pre-rounding pass: dst = fp16(src) for 7 tensors in one launch (grid.z)
// ---------------------------------------------------------------------------
struct RoundArgs {
    const float* src[7];
    __half*      dst[7];
    int          n4[7];     // number of float4 elements
};

__global__ __launch_bounds__(256) void round_f16(RoundArgs ra) {
    const int z = blockIdx.z;
    const int i = blockIdx.x * 256 + threadIdx.x;
    if (i >= ra.n4[z]) return;
    float4 v = ((const float4*)ra.src[z])[i];
    __half2 h0 = __floats2half2_rn(v.x, v.y);
    __half2 h1 = __floats2half2_rn(v.z, v.w);
    uint2 u;
    u.x = *(uint32_t*)&h0;
    u.y = *(uint32_t*)&h1;
    ((uint2*)ra.dst[z])[i] = u;
}

// ---------------------------------------------------------------------------
// Pipelined TN GEMM (fp16 HMMA):  C[M,N] = A[M,K] * W[N,K]^T + bias[N]
// CTA 128x128 with FOUR warps (128 threads), warp tile 64x64 (2x2 grid).
// K-tile 64, 3-stage cp.async ring, m16n8k16 HMMA. (unchanged from R8/R9 —
// measured at ~98% of the f32-accumulate classic-HMMA structural ceiling.)
// Output modes: 0 = fp16 to Ch (Q-proj), 1 = permuted fp32 into new_kv
// (K/V proj land directly in d_out), 2 = plain fp32 (O-proj).
// ---------------------------------------------------------------------------
#define NST        3
#define TILE_B     16384                 // 128 rows * 128 bytes
#define GEMM_SMEM  (2 * NST * TILE_B + 1024)
#define NKT        (D_MODEL / 64)        // 32 k-tiles

struct ProjArgs {
    const __half* A[3];
    const __half* W[3];
    const float*  Bias[3];
    float*        C[3];
    __half*       Ch[3];
    int           mode[3];
};

__global__ __launch_bounds__(128, 2) void gemm_tc(ProjArgs args) {
    extern __shared__ char dyn_smem[];
    char* db = (char*)(((uintptr_t)dyn_smem + 1023) & ~(uintptr_t)1023);
    const uint32_t db_u = smem_u32(db);

    const int z = blockIdx.z;
    const __half* __restrict__ A    = args.A[z];
    const __half* __restrict__ W    = args.W[z];
    const float*  __restrict__ bias = args.Bias[z];
    float* __restrict__        C    = args.C[z];
    __half* __restrict__       Ch   = args.Ch[z];
    const int mode = args.mode[z];

    const int tid  = threadIdx.x;
    const int lane = tid & 31;
    const int w    = tid >> 5;     // 0..3
    const int wm   = w >> 1;       // 0..1
    const int wn   = w & 1;        // 0..1
    const int n0   = blockIdx.x * 128;
    const int m0   = blockIdx.y * 128;

    const __half* Ag = A + (size_t)m0 * D_MODEL;
    const __half* Wg = W + (size_t)n0 * D_MODEL;

    // per-thread load geometry: 8 chunks A + 8 chunks B per stage (128 thr)
    uint32_t swoff[8];
    size_t   gofs[8];
#pragma unroll
    for (int rep = 0; rep < 8; rep++) {
        const int g = rep * 128 + tid;          // 0..1023
        const int r = g >> 3;                   // row 0..127
        const int i = g & 7;                    // 16B chunk
        gofs[rep]  = (size_t)r * D_MODEL + i * 8;
        swoff[rep] = (uint32_t)((r * 128 + i * 16) ^ ((r & 7) << 4));
    }

    float acc[4][8][4];
#pragma unroll
    for (int i = 0; i < 4; i++)
#pragma unroll
        for (int j = 0; j < 8; j++)
#pragma unroll
            for (int k = 0; k < 4; k++) acc[i][j][k] = 0.f;

    auto issue = [&](int ks) {
        const int slot = ks % NST;
        const int kc   = ks * 64;
        const uint32_t da  = db_u + slot * TILE_B;
        const uint32_t dbb = db_u + NST * TILE_B + slot * TILE_B;
#pragma unroll
        for (int rep = 0; rep < 8; rep++)
            cp_async16(da + swoff[rep], Ag + gofs[rep] + kc);
#pragma unroll
        for (int rep = 0; rep < 8; rep++)
            cp_async16(dbb + swoff[rep], Wg + gofs[rep] + kc);
        CP_COMMIT();
    };

    issue(0);
    issue(1);

    const int m_ = lane >> 3;
    const int rr = lane & 7;
    const int a_row_base = wm * 64 + (m_ & 1) * 8 + rr;   // + mf*16
    const int b_row_base = wn * 64 + (m_ & 1) * 8 + rr;   // + nf2*16
    const int k_half     = (m_ >> 1) * 16;

#pragma unroll 1
    for (int kt = 0; kt < NKT; kt++) {
        if (kt < NKT - 2) { CP_WAIT(1); } else { CP_WAIT(0); }
        __syncthreads();
        if (kt + 2 < NKT) issue(kt + 2);

        const int slot = kt % NST;
        const uint32_t da  = db_u + slot * TILE_B;
        const uint32_t dbb = db_u + NST * TILE_B + slot * TILE_B;

#pragma unroll
        for (int ks = 0; ks < 4; ks++) {
            const int kb = ks * 32 + k_half;
            uint32_t a[4][4], b[8][2];
#pragma unroll
            for (int mf = 0; mf < 4; mf++) {
                const int row = a_row_base + mf * 16;
                const uint32_t off = (uint32_t)((row * 128 + kb) ^ ((row & 7) << 4));
                ldsm_x4(a[mf], da + off);
            }
#pragma unroll
            for (int nf2 = 0; nf2 < 4; nf2++) {
                const int row = b_row_base + nf2 * 16;
                const uint32_t off = (uint32_t)((row * 128 + kb) ^ ((row & 7) << 4));
                uint32_t t[4];
                ldsm_x4(t, dbb + off);
                b[nf2 * 2][0]     = t[0]; b[nf2 * 2][1]     = t[2];
                b[nf2 * 2 + 1][0] = t[1]; b[nf2 * 2 + 1][1] = t[3];
            }
#pragma unroll
            for (int mf = 0; mf < 4; mf++)
#pragma unroll
                for (int nf = 0; nf < 8; nf++)
                    mma_f16(acc[mf][nf], a[mf], b[nf]);
        }
    }

    // epilogue (per mode)
#pragma unroll
    for (int mf = 0; mf < 4; mf++) {
#pragma unroll
        for (int nf = 0; nf < 8; nf++) {
            const int row = m0 + wm * 64 + mf * 16 + (lane >> 2);
            const int col = n0 + wn * 64 + nf * 8 + (lane & 3) * 2;
            const float b0 = bias[col], b1 = bias[col + 1];
            const float x0 = acc[mf][nf][0] + b0, x1 = acc[mf][nf][1] + b1;
            const float y0 = acc[mf][nf][2] + b0, y1 = acc[mf][nf][3] + b1;
            if (mode == 0) {
                __half2 h0 = __floats2half2_rn(x0, x1);
                __half2 h1 = __floats2half2_rn(y0, y1);
                *(__half2*)&Ch[(size_t)row * D_MODEL + col]       = h0;
                *(__half2*)&Ch[(size_t)(row + 8) * D_MODEL + col] = h1;
            } else if (mode == 1) {
                // direct write into new_k/new_v (proj half): t' = 1024 + t
                const int h  = col >> 7, d = col & 127;
#pragma unroll
                for (int rep = 0; rep < 2; rep++) {
                    const int rw = row + rep * 8;
                    const int bb = rw >> 10, t = rw & 1023;
                    const int j  = h * 128 + 64 + (t >> 4);
                    const int c  = (t & 15) * 128 + d;
                    float2 v = rep ? make_float2(y0, y1) : make_float2(x0, x1);
                    *(float2*)&C[((size_t)bb * 2048 + j) * 2048 + c] = v;
                }
            } else {
                *(float2*)&C[(size_t)row * D_MODEL + col]       = make_float2(x0, x1);
                *(float2*)&C[(size_t)(row + 8) * D_MODEL + col] = make_float2(y0, y1);
            }
        }
    }
}

// ---------------------------------------------------------------------------
// fp16 flash attention over the cache only (mask tril(TQ,total) => cache half).
// 128 threads (4 warps), 64 q-rows/CTA, 64 kv/tile.
// R10 restructure: K+V fused into ONE commit group per kv-tile -> single
// CP_WAIT + 2 barriers per iteration (was 2 waits + 3 barriers); softmax
// flows straight into PV. Scale folded into exp2 argument (scores unscaled).
// P stays in registers (S-accum layout == PV A-fragment layout).
// SMEM: Q 16K | K0 K1 32K | V0 V1 32K = 80K, 2 CTA/SM.
// qi reversed vs blockIdx.x: heavy (long) CTAs launch first -> better tail.
// ---------------------------------------------------------------------------
#define QOFF 0
#define KOFF 16384
#define VOFF (KOFF + 2 * 16384)
#define ATT_SMEM (VOFF + 2 * 16384)   // 81920

__global__ __launch_bounds__(128, 2) void attn_kernel(
    const __half* __restrict__ gQ,
    const __half* __restrict__ hK,
    const __half* __restrict__ hV,
    __half* __restrict__ gO)
{
    extern __shared__ char smc[];
    const uint32_t sb = smem_u32(smc);
    const int tid = threadIdx.x, lane = tid & 31, w = tid >> 5;
    const int qi = (int)gridDim.x - 1 - blockIdx.x;   // heavy tiles first
    const int h = blockIdx.y, b = blockIdx.z;
    const int q0 = qi * 64;

    const __half* Qg = gQ + ((size_t)b * TQ + q0) * D_MODEL + h * HEAD_DIM;
    const __half* Kg = hK + (size_t)b * CACHE_LEN * D_MODEL + h * HEAD_DIM;
    const __half* Vg = hV + (size_t)b * CACHE_LEN * D_MODEL + h * HEAD_DIM;

    // Q tile 64x128 halves -> swizzled smem (rows 256B)
#pragma unroll
    for (int rep = 0; rep < 8; rep++) {
        const int g = rep * 128 + tid;
        const int r = g >> 4, i = g & 15;
        uint4 v = *(const uint4*)(Qg + (size_t)r * D_MODEL + i * 8);
        *(uint4*)(smc + QOFF + ((r * 256 + i * 16) ^ ((r & 7) << 4))) = v;
    }

    // one commit group per kv-tile: K chunks + V chunks together
    auto issueKV = [&](int kt) {
#pragma unroll
        for (int rep = 0; rep < 8; rep++) {
            const int g = rep * 128 + tid;
            const int r = g >> 4, i = g & 15;
            const uint32_t so = (uint32_t)((r * 256 + i * 16) ^ ((r & 7) << 4));
            cp_async16(sb + KOFF + (kt & 1) * 16384 + so,
                       Kg + (size_t)(kt * 64 + r) * D_MODEL + i * 8);
            cp_async16(sb + VOFF + (kt & 1) * 16384 + so,
                       Vg + (size_t)(kt * 64 + r) * D_MODEL + i * 8);
        }
        CP_COMMIT();
    };

    issueKV(0);
    if (qi >= 1) issueKV(1); else CP_COMMIT();

    float acc_o[16][4];
#pragma unroll
    for (int i = 0; i < 16; i++)
#pragma unroll
        for (int j = 0; j < 4; j++) acc_o[i][j] = 0.f;
    float mrow[2] = {-1e30f, -1e30f};     // running max of UNSCALED scores
    float lrow[2] = {0.f, 0.f};
    // exp(sc*(s-m)) == exp2f((s-m)*C2), C2 = (1/sqrt(128))*log2(e)
    const float C2 = (float)(0.08838834764831845 * 1.4426950408889634);

    const int m_ = lane >> 3, rr = lane & 7;
    const int kh    = (m_ >> 1) * 16;
    const int a_row = w * 16 + (m_ & 1) * 8 + rr;

    for (int kt = 0; kt <= qi; kt++) {
        CP_WAIT(1);            // KV(kt) landed (groups complete in order)
        __syncthreads();       // visible to all warps (covers Q on kt=0)

        const uint32_t kbase = sb + KOFF + (kt & 1) * 16384;
        float accs[8][4];
#pragma unroll
        for (int i = 0; i < 8; i++)
#pragma unroll
            for (int j = 0; j < 4; j++) accs[i][j] = 0.f;

#pragma unroll
        for (int ks = 0; ks < 8; ks++) {            // 8 x k16 over headdim 128
            const int colb = ks * 32 + kh;
            uint32_t a[4];
            ldsm_x4(a, sb + QOFF + ((a_row * 256 + colb) ^ ((a_row & 7) << 4)));
            uint32_t bfr[8][2];
#pragma unroll
            for (int nf2 = 0; nf2 < 4; nf2++) {
                const int row = nf2 * 16 + (m_ & 1) * 8 + rr;   // kv rows 0..63
                uint32_t t[4];
                ldsm_x4(t, kbase + ((row * 256 + colb) ^ ((row & 7) << 4)));
                bfr[nf2 * 2][0]     = t[0]; bfr[nf2 * 2][1]     = t[2];
                bfr[nf2 * 2 + 1][0] = t[1]; bfr[nf2 * 2 + 1][1] = t[3];
            }
#pragma unroll
            for (int nf = 0; nf < 8; nf++) mma_f16(accs[nf], a, bfr[nf]);
        }

        // causal mask (diagonal tile only) on UNSCALED scores
        if (kt == qi) {
#pragma unroll
            for (int nf = 0; nf < 8; nf++)
#pragma unroll
                for (int r = 0; r < 2; r++)
#pragma unroll
                    for (int j = 0; j < 2; j++) {
                        const int cl = nf * 8 + (lane & 3) * 2 + j;
                        const int rl = w * 16 + (lane >> 2) + r * 8;
                        if (cl > rl) accs[nf][r * 2 + j] = -1e30f;
                    }
        }

        // online softmax (scale folded into exp2) -> P packed into A-frags
        uint32_t ph[8][2];
#pragma unroll
        for (int r = 0; r < 2; r++) {
            float vmax = -1e30f;
#pragma unroll
            for (int nf = 0; nf < 8; nf++) {
                vmax = fmaxf(vmax, accs[nf][r * 2]);
                vmax = fmaxf(vmax, accs[nf][r * 2 + 1]);
            }
            vmax = fmaxf(vmax, __shfl_xor_sync(0xffffffffu, vmax, 1));
            vmax = fmaxf(vmax, __shfl_xor_sync(0xffffffffu, vmax, 2));
            const float mnew = fmaxf(mrow[r], vmax);
            float psum = 0.f;
#pragma unroll
            for (int nf = 0; nf < 8; nf++) {
                const float p0 = exp2f((accs[nf][r * 2]     - mnew) * C2);
                const float p1 = exp2f((accs[nf][r * 2 + 1] - mnew) * C2);
                psum += p0 + p1;
                __half2 hp = __floats2half2_rn(p0, p1);
                ph[nf][r] = *(uint32_t*)&hp;
            }
            psum += __shfl_xor_sync(0xffffffffu, psum, 1);
            psum += __shfl_xor_sync(0xffffffffu, psum, 2);
            const float alpha = exp2f((mrow[r] - mnew) * C2);
            lrow[r] = lrow[r] * alpha + psum;
            mrow[r] = mnew;
#pragma unroll
            for (int nf = 0; nf < 16; nf++) {
                acc_o[nf][r * 2]     *= alpha;
                acc_o[nf][r * 2 + 1] *= alpha;
            }
        }

        // O += P * V  (V arrived with K; P A-frags from registers)
        const uint32_t vbase = sb + VOFF + (kt & 1) * 16384;
        const int vr_lane = ((lane >> 3) & 1) * 8 + (lane & 7);
        const int vc_lane = (lane >> 4) * 16;
#pragma unroll
        for (int ks = 0; ks < 4; ks++) {            // 4 x k16 over 64 kv
            uint32_t aP[4];
            aP[0] = ph[2 * ks][0];
            aP[1] = ph[2 * ks][1];
            aP[2] = ph[2 * ks + 1][0];
            aP[3] = ph[2 * ks + 1][1];
#pragma unroll
            for (int dg = 0; dg < 8; dg++) {        // 16 halves of headdim each
                const int vrow = ks * 16 + vr_lane;
                const int vcol = dg * 32 + vc_lane;
                uint32_t t[4];
                ldsm_x4t(t, vbase + ((vrow * 256 + vcol) ^ ((vrow & 7) << 4)));
                uint32_t b0[2] = { t[0], t[1] };
                uint32_t b1[2] = { t[2], t[3] };
                mma_f16(acc_o[dg * 2],     aP, b0);
                mma_f16(acc_o[dg * 2 + 1], aP, b1);
            }
        }

        __syncthreads();       // all warps done reading K(kt)/V(kt)
        if (kt + 2 <= qi) issueKV(kt + 2); else CP_COMMIT();
    }

    // normalize + write fp16
#pragma unroll
    for (int nf = 0; nf < 16; nf++)
#pragma unroll
        for (int r = 0; r < 2; r++) {
            const int row = q0 + w * 16 + (lane >> 2) + r * 8;
            const int col = h * HEAD_DIM + nf * 8 + (lane & 3) * 2;
            const float inv = 1.f / lrow[r];
            __half2 hv = __floats2half2_rn(acc_o[nf][r * 2] * inv,
                                           acc_o[nf][r * 2 + 1] * inv);
            *(__half2*)&gO[((size_t)b * TQ + row) * D_MODEL + col] = hv;
        }
}

// ---------------------------------------------------------------------------
// cache pass, fused: permuted fp32 cache half of new_k/new_v into d_out AND
// fp16 rounding of the caches for attention (single read of each cache).
// grid.z: 0 -> K, 1 -> V. 2097152 float4 per tensor.
// ---------------------------------------------------------------------------
__global__ __launch_bounds__(256) void copy_cache_kv(
    const float* __restrict__ cacheK,
    const float* __restrict__ cacheV,
    float* __restrict__ dstK,
    float* __restrict__ dstV,
    __half* __restrict__ hcK,
    __half* __restrict__ hcV)
{
    const int i = blockIdx.x * 256 + threadIdx.x;
    const int b   = i >> 19;            // 524288 float4 per batch
    const int rem = i & 524287;
    const int jj  = rem >> 9;           // 0..1023 (h*64 + cache row)
    const int c   = (rem & 511) * 4;
    const int h   = jj >> 6;
    const int j   = h * 128 + (jj & 63);
    const int t   = (jj & 63) * 16 + (c >> 7);
    const int d   = c & 127;

    const float* cache = blockIdx.z ? cacheV : cacheK;
    float*       dst   = blockIdx.z ? dstV   : dstK;
    __half*      hc    = blockIdx.z ? hcV    : hcK;

    const size_t src_off = ((size_t)b * CACHE_LEN + t) * D_MODEL + h * HEAD_DIM + d;
    float4 v = *(const float4*)&cache[src_off];
    *(float4*)&dst[((size_t)b * 2048 + j) * D_MODEL + c] = v;

    __half2 h0 = __floats2half2_rn(v.x, v.y);
    __half2 h1 = __floats2half2_rn(v.z, v.w);
    uint2 u;
    u.x = *(uint32_t*)&h0;
    u.y = *(uint32_t*)&h1;
    *(uint2*)&hc[src_off] = u;
}

// ---------------------------------------------------------------------------
// launch — serial single stream
// ---------------------------------------------------------------------------
extern "C" void kernel_launch(void* const* d_in, const int* in_sizes, int n_in,
                              void* d_out, int out_size)
{
    const float* query   = (const float*)d_in[0];
    const float* key     = (const float*)d_in[1];
    const float* value   = (const float*)d_in[2];
    const float* cacheK  = (const float*)d_in[3];
    const float* cacheV  = (const float*)d_in[4];
    const float* Wq      = (const float*)d_in[5];
    const float* bq      = (const float*)d_in[6];
    const float* Wk      = (const float*)d_in[7];
    const float* bk      = (const float*)d_in[8];
    const float* Wv      = (const float*)d_in[9];
    const float* bv      = (const float*)d_in[10];
    const float* Wo      = (const float*)d_in[11];
    const float* bo      = (const float*)d_in[12];
    float* out = (float*)d_out;

    __half *phQ, *pO, *phq, *phk, *phv, *phWq, *phWk, *phWv, *phWo, *phck, *phcv;
    cudaGetSymbolAddress((void**)&phQ, g_hQ);
    cudaGetSymbolAddress((void**)&pO, g_O);
    cudaGetSymbolAddress((void**)&phq, g_hq);
    cudaGetSymbolAddress((void**)&phk, g_hk);
    cudaGetSymbolAddress((void**)&phv, g_hv);
    cudaGetSymbolAddress((void**)&phWq, g_hWq);
    cudaGetSymbolAddress((void**)&phWk, g_hWk);
    cudaGetSymbolAddress((void**)&phWv, g_hWv);
    cudaGetSymbolAddress((void**)&phWo, g_hWo);
    cudaGetSymbolAddress((void**)&phck, g_hck);
    cudaGetSymbolAddress((void**)&phcv, g_hcv);

    cudaFuncSetAttribute(gemm_tc, cudaFuncAttributeMaxDynamicSharedMemorySize,
                         GEMM_SMEM);
    cudaFuncSetAttribute(attn_kernel, cudaFuncAttributeMaxDynamicSharedMemorySize,
                         ATT_SMEM);

    const int NA = M_ROWS * D_MODEL / 4;     // 2097152 float4
    const int NW = D_MODEL * D_MODEL / 4;    // 1048576 float4

    // 1) pre-round inputs to fp16 (caches handled by the fused cache pass)
    RoundArgs ra;
    ra.src[0] = query; ra.dst[0] = phq;  ra.n4[0] = NA;
    ra.src[1] = key;   ra.dst[1] = phk;  ra.n4[1] = NA;
    ra.src[2] = value; ra.dst[2] = phv;  ra.n4[2] = NA;
    ra.src[3] = Wq;    ra.dst[3] = phWq; ra.n4[3] = NW;
    ra.src[4] = Wk;    ra.dst[4] = phWk; ra.n4[4] = NW;
    ra.src[5] = Wv;    ra.dst[5] = phWv; ra.n4[5] = NW;
    ra.src[6] = Wo;    ra.dst[6] = phWo; ra.n4[6] = NW;
    round_f16<<<dim3(NA / 256, 1, 7), 256>>>(ra);

    // 2) cache pass: permuted fp32 halves into d_out + fp16 caches for attn
    copy_cache_kv<<<dim3(2097152 / 256, 1, 2), 256>>>(
        cacheK, cacheV, out + 8388608, out + 25165824, phck, phcv);

    // 3) Q/K/V projections. Q -> fp16 scratch; K/V -> straight into d_out.
    ProjArgs pa;
    pa.A[0] = phq;  pa.W[0] = phWq; pa.Bias[0] = bq;
    pa.Ch[0] = phQ; pa.C[0] = nullptr;            pa.mode[0] = 0;
    pa.A[1] = phk;  pa.W[1] = phWk; pa.Bias[1] = bk;
    pa.Ch[1] = nullptr; pa.C[1] = out + 8388608;  pa.mode[1] = 1;
    pa.A[2] = phv;  pa.W[2] = phWv; pa.Bias[2] = bv;
    pa.Ch[2] = nullptr; pa.C[2] = out + 25165824; pa.mode[2] = 1;
    gemm_tc<<<dim3(D_MODEL / 128, M_ROWS / 128, 3), 128, GEMM_SMEM>>>(pa);

    // 4) attention (cache-only, causal), fp16 HMMA, fused-KV pipeline
    attn_kernel<<<dim3(TQ / 64, NUM_HEADS, BATCH), 128, ATT_SMEM>>>(
        phQ, phck, phcv, pO);

    // 5) output projection -> out[0 .. 8388608)
    ProjArgs po;
    po.A[0] = pO; po.W[0] = phWo; po.Bias[0] = bo;
    po.C[0] = out; po.Ch[0] = nullptr; po.mode[0] = 2;
    po.A[1] = po.A[0]; po.W[1] = po.W[0]; po.Bias[1] = po.Bias[0];
    po.C[1] = po.C[0]; po.Ch[1] = nullptr; po.mode[1] = 2;
    po.A[2] = po.A[0]; po.W[2] = po.W[0]; po.Bias[2] = po.Bias[0];
    po.C[2] = po.C[0]; po.Ch[2] = nullptr; po.mode[2] = 2;
    gemm_tc<<<dim3(D_MODEL / 128, M_ROWS / 128, 1), 128, GEMM_SMEM>>>(po);
}

// round 11
// speedup vs baseline: 1.1938x; 1.0039x over previous
#include <cuda_runtime.h>
#include <cuda_bf16.h>
#include <cuda_fp16.h>
#include <cstdint>
#include <cstdio>

// ---------------------------------------------------------------------------
// Problem constants
// ---------------------------------------------------------------------------
#define D_MODEL   2048
#define NUM_HEADS 16
#define HEAD_DIM  128
#define BATCH     4
#define TQ        1024
#define CACHE_LEN 1024
#define M_ROWS    (BATCH * TQ)          // 4096

// scratch (device globals: allocation-free scratch per harness rules)
__device__ __half g_hQ[M_ROWS * D_MODEL];             // projected Q, fp16
__device__ __half g_O[M_ROWS * D_MODEL];              // attention out, fp16
// fp16 pre-rounded inputs
__device__ __half g_hq[M_ROWS * D_MODEL];
__device__ __half g_hk[M_ROWS * D_MODEL];
__device__ __half g_hv[M_ROWS * D_MODEL];
__device__ __half g_hWq[D_MODEL * D_MODEL];
__device__ __half g_hWk[D_MODEL * D_MODEL];
__device__ __half g_hWv[D_MODEL * D_MODEL];
__device__ __half g_hWo[D_MODEL * D_MODEL];
__device__ __half g_hck[BATCH * CACHE_LEN * D_MODEL]; // fp16 cache K (attention)
__device__ __half g_hcv[BATCH * CACHE_LEN * D_MODEL]; // fp16 cache V (attention)

// ---------------------------------------------------------------------------
// helpers
// ---------------------------------------------------------------------------
__device__ __forceinline__ uint32_t smem_u32(const void* p) {
    uint32_t a;
    asm("{ .reg .u64 t; cvta.to.shared.u64 t, %1; cvt.u32.u64 %0, t; }"
        : "=r"(a) : "l"(p));
    return a;
}

// fp16 m16n8k16: D += A*B  (row.col, f32 accum)
__device__ __forceinline__ void mma_f16(float* d, const uint32_t* a, const uint32_t* b) {
    asm volatile(
        "mma.sync.aligned.m16n8k16.row.col.f32.f16.f16.f32 "
        "{%0,%1,%2,%3}, {%4,%5,%6,%7}, {%8,%9}, {%0,%1,%2,%3};\n"
        : "+f"(d[0]), "+f"(d[1]), "+f"(d[2]), "+f"(d[3])
        : "r"(a[0]), "r"(a[1]), "r"(a[2]), "r"(a[3]),
          "r"(b[0]), "r"(b[1]));
}

__device__ __forceinline__ void ldsm_x4(uint32_t* r, uint32_t addr) {
    asm volatile("ldmatrix.sync.aligned.m8n8.x4.shared.b16 {%0,%1,%2,%3}, [%4];"
                 : "=r"(r[0]), "=r"(r[1]), "=r"(r[2]), "=r"(r[3]) : "r"(addr));
}

__device__ __forceinline__ void ldsm_x4t(uint32_t* r, uint32_t addr) {
    asm volatile("ldmatrix.sync.aligned.m8n8.x4.trans.shared.b16 {%0,%1,%2,%3}, [%4];"
                 : "=r"(r[0]), "=r"(r[1]), "=r"(r[2]), "=r"(r[3]) : "r"(addr));
}

// packed half2 2^x (one MUFU op for two values)
__device__ __forceinline__ uint32_t h2exp2_(uint32_t x) {
    uint32_t r;
    asm("ex2.approx.f16x2 %0, %1;" : "=r"(r) : "r"(x));
    return r;
}

__device__ __forceinline__ void cp_async16(uint32_t dst, const void* src) {
    asm volatile("cp.async.cg.shared.global [%0], [%1], 16;"
                 :: "r"(dst), "l"(src));
}
#define CP_COMMIT()  asm volatile("cp.async.commit_group;" ::: "memory")
#define CP_WAIT(N)   asm volatile("cp.async.wait_group %0;" :: "n"(N) : "memory")

// ---------------------------------------------------------------------------
// pre-rounding pass: dst = fp16(src) for 7 tensors in one launch (grid.z)
// ---------------------------------------------------------------------------
struct RoundArgs {
    const float* src[7];
    __half*      dst[7];
    int          n4[7];     // number of float4 elements
};

__global__ __launch_bounds__(256) void round_f16(RoundArgs ra) {
    const int z = blockIdx.z;
    const int i = blockIdx.x * 256 + threadIdx.x;
    if (i >= ra.n4[z]) return;
    float4 v = ((const float4*)ra.src[z])[i];
    __half2 h0 = __floats2half2_rn(v.x, v.y);
    __half2 h1 = __floats2half2_rn(v.z, v.w);
    uint2 u;
    u.x = *(uint32_t*)&h0;
    u.y = *(uint32_t*)&h1;
    ((uint2*)ra.dst[z])[i] = u;
}

// ---------------------------------------------------------------------------
// Pipelined TN GEMM (fp16 HMMA):  C[M,N] = A[M,K] * W[N,K]^T + bias[N]
// CTA 128x128 with FOUR warps (128 threads), warp tile 64x64 (2x2 grid).
// K-tile 64, 3-stage cp.async ring, m16n8k16 HMMA. (unchanged — measured at
// ~98% of the f32-accumulate classic-HMMA structural ceiling.)
// Output modes: 0 = fp16 to Ch (Q-proj), 1 = permuted fp32 into new_kv
// (K/V proj land directly in d_out), 2 = plain fp32 (O-proj).
// ---------------------------------------------------------------------------
#define NST        3
#define TILE_B     16384                 // 128 rows * 128 bytes
#define GEMM_SMEM  (2 * NST * TILE_B + 1024)
#define NKT        (D_MODEL / 64)        // 32 k-tiles

struct ProjArgs {
    const __half* A[3];
    const __half* W[3];
    const float*  Bias[3];
    float*        C[3];
    __half*       Ch[3];
    int           mode[3];
};

__global__ __launch_bounds__(128, 2) void gemm_tc(ProjArgs args) {
    extern __shared__ char dyn_smem[];
    char* db = (char*)(((uintptr_t)dyn_smem + 1023) & ~(uintptr_t)1023);
    const uint32_t db_u = smem_u32(db);

    const int z = blockIdx.z;
    const __half* __restrict__ A    = args.A[z];
    const __half* __restrict__ W    = args.W[z];
    const float*  __restrict__ bias = args.Bias[z];
    float* __restrict__        C    = args.C[z];
    __half* __restrict__       Ch   = args.Ch[z];
    const int mode = args.mode[z];

    const int tid  = threadIdx.x;
    const int lane = tid & 31;
    const int w    = tid >> 5;     // 0..3
    const int wm   = w >> 1;       // 0..1
    const int wn   = w & 1;        // 0..1
    const int n0   = blockIdx.x * 128;
    const int m0   = blockIdx.y * 128;

    const __half* Ag = A + (size_t)m0 * D_MODEL;
    const __half* Wg = W + (size_t)n0 * D_MODEL;

    // per-thread load geometry: 8 chunks A + 8 chunks B per stage (128 thr)
    uint32_t swoff[8];
    size_t   gofs[8];
#pragma unroll
    for (int rep = 0; rep < 8; rep++) {
        const int g = rep * 128 + tid;          // 0..1023
        const int r = g >> 3;                   // row 0..127
        const int i = g & 7;                    // 16B chunk
        gofs[rep]  = (size_t)r * D_MODEL + i * 8;
        swoff[rep] = (uint32_t)((r * 128 + i * 16) ^ ((r & 7) << 4));
    }

    float acc[4][8][4];
#pragma unroll
    for (int i = 0; i < 4; i++)
#pragma unroll
        for (int j = 0; j < 8; j++)
#pragma unroll
            for (int k = 0; k < 4; k++) acc[i][j][k] = 0.f;

    auto issue = [&](int ks) {
        const int slot = ks % NST;
        const int kc   = ks * 64;
        const uint32_t da  = db_u + slot * TILE_B;
        const uint32_t dbb = db_u + NST * TILE_B + slot * TILE_B;
#pragma unroll
        for (int rep = 0; rep < 8; rep++)
            cp_async16(da + swoff[rep], Ag + gofs[rep] + kc);
#pragma unroll
        for (int rep = 0; rep < 8; rep++)
            cp_async16(dbb + swoff[rep], Wg + gofs[rep] + kc);
        CP_COMMIT();
    };

    issue(0);
    issue(1);

    const int m_ = lane >> 3;
    const int rr = lane & 7;
    const int a_row_base = wm * 64 + (m_ & 1) * 8 + rr;   // + mf*16
    const int b_row_base = wn * 64 + (m_ & 1) * 8 + rr;   // + nf2*16
    const int k_half     = (m_ >> 1) * 16;

#pragma unroll 1
    for (int kt = 0; kt < NKT; kt++) {
        if (kt < NKT - 2) { CP_WAIT(1); } else { CP_WAIT(0); }
        __syncthreads();
        if (kt + 2 < NKT) issue(kt + 2);

        const int slot = kt % NST;
        const uint32_t da  = db_u + slot * TILE_B;
        const uint32_t dbb = db_u + NST * TILE_B + slot * TILE_B;

#pragma unroll
        for (int ks = 0; ks < 4; ks++) {
            const int kb = ks * 32 + k_half;
            uint32_t a[4][4], b[8][2];
#pragma unroll
            for (int mf = 0; mf < 4; mf++) {
                const int row = a_row_base + mf * 16;
                const uint32_t off = (uint32_t)((row * 128 + kb) ^ ((row & 7) << 4));
                ldsm_x4(a[mf], da + off);
            }
#pragma unroll
            for (int nf2 = 0; nf2 < 4; nf2++) {
                const int row = b_row_base + nf2 * 16;
                const uint32_t off = (uint32_t)((row * 128 + kb) ^ ((row & 7) << 4));
                uint32_t t[4];
                ldsm_x4(t, dbb + off);
                b[nf2 * 2][0]     = t[0]; b[nf2 * 2][1]     = t[2];
                b[nf2 * 2 + 1][0] = t[1]; b[nf2 * 2 + 1][1] = t[3];
            }
#pragma unroll
            for (int mf = 0; mf < 4; mf++)
#pragma unroll
                for (int nf = 0; nf < 8; nf++)
                    mma_f16(acc[mf][nf], a[mf], b[nf]);
        }
    }

    // epilogue (per mode)
#pragma unroll
    for (int mf = 0; mf < 4; mf++) {
#pragma unroll
        for (int nf = 0; nf < 8; nf++) {
            const int row = m0 + wm * 64 + mf * 16 + (lane >> 2);
            const int col = n0 + wn * 64 + nf * 8 + (lane & 3) * 2;
            const float b0 = bias[col], b1 = bias[col + 1];
            const float x0 = acc[mf][nf][0] + b0, x1 = acc[mf][nf][1] + b1;
            const float y0 = acc[mf][nf][2] + b0, y1 = acc[mf][nf][3] + b1;
            if (mode == 0) {
                __half2 h0 = __floats2half2_rn(x0, x1);
                __half2 h1 = __floats2half2_rn(y0, y1);
                *(__half2*)&Ch[(size_t)row * D_MODEL + col]       = h0;
                *(__half2*)&Ch[(size_t)(row + 8) * D_MODEL + col] = h1;
            } else if (mode == 1) {
                // direct write into new_k/new_v (proj half): t' = 1024 + t
                const int h  = col >> 7, d = col & 127;
#pragma unroll
                for (int rep = 0; rep < 2; rep++) {
                    const int rw = row + rep * 8;
                    const int bb = rw >> 10, t = rw & 1023;
                    const int j  = h * 128 + 64 + (t >> 4);
                    const int c  = (t & 15) * 128 + d;
                    float2 v = rep ? make_float2(y0, y1) : make_float2(x0, x1);
                    *(float2*)&C[((size_t)bb * 2048 + j) * 2048 + c] = v;
                }
            } else {
                *(float2*)&C[(size_t)row * D_MODEL + col]       = make_float2(x0, x1);
                *(float2*)&C[(size_t)(row + 8) * D_MODEL + col] = make_float2(y0, y1);
            }
        }
    }
}

// ---------------------------------------------------------------------------
// fp16 flash attention over the cache only (mask tril(TQ,total) => cache half).
// 128 threads (4 warps), 64 q-rows/CTA, 64 kv/tile, fused K+V commit groups,
// single CP_WAIT + 2 barriers per iteration; P in registers.
// R11: softmax issue-diet —
//   * P pair via ex2.approx.f16x2 (one MUFU per 2 values, no separate pack)
//   * row-sum l computed BY the tensor core: extra m16n8k16 per ks against a
//     ones-column B-frag, accumulated in acc_l and alpha-rescaled like acc_o;
//     the per-tile psum FADD/SHFL reduction is gone entirely.
// SMEM: Q 16K | K0 K1 32K | V0 V1 32K = 80K, 2 CTA/SM.
// qi reversed vs blockIdx.x: heavy (long) CTAs launch first -> better tail.
// ---------------------------------------------------------------------------
#define QOFF 0
#define KOFF 16384
#define VOFF (KOFF + 2 * 16384)
#define ATT_SMEM (VOFF + 2 * 16384)   // 81920

__global__ __launch_bounds__(128, 2) void attn_kernel(
    const __half* __restrict__ gQ,
    const __half* __restrict__ hK,
    const __half* __restrict__ hV,
    __half* __restrict__ gO)
{
    extern __shared__ char smc[];
    const uint32_t sb = smem_u32(smc);
    const int tid = threadIdx.x, lane = tid & 31, w = tid >> 5;
    const int qi = (int)gridDim.x - 1 - blockIdx.x;   // heavy tiles first
    const int h = blockIdx.y, b = blockIdx.z;
    const int q0 = qi * 64;

    const __half* Qg = gQ + ((size_t)b * TQ + q0) * D_MODEL + h * HEAD_DIM;
    const __half* Kg = hK + (size_t)b * CACHE_LEN * D_MODEL + h * HEAD_DIM;
    const __half* Vg = hV + (size_t)b * CACHE_LEN * D_MODEL + h * HEAD_DIM;

    // Q tile 64x128 halves -> swizzled smem (rows 256B)
#pragma unroll
    for (int rep = 0; rep < 8; rep++) {
        const int g = rep * 128 + tid;
        const int r = g >> 4, i = g & 15;
        uint4 v = *(const uint4*)(Qg + (size_t)r * D_MODEL + i * 8);
        *(uint4*)(smc + QOFF + ((r * 256 + i * 16) ^ ((r & 7) << 4))) = v;
    }

    // one commit group per kv-tile: K chunks + V chunks together
    auto issueKV = [&](int kt) {
#pragma unroll
        for (int rep = 0; rep < 8; rep++) {
            const int g = rep * 128 + tid;
            const int r = g >> 4, i = g & 15;
            const uint32_t so = (uint32_t)((r * 256 + i * 16) ^ ((r & 7) << 4));
            cp_async16(sb + KOFF + (kt & 1) * 16384 + so,
                       Kg + (size_t)(kt * 64 + r) * D_MODEL + i * 8);
            cp_async16(sb + VOFF + (kt & 1) * 16384 + so,
                       Vg + (size_t)(kt * 64 + r) * D_MODEL + i * 8);
        }
        CP_COMMIT();
    };

    issueKV(0);
    if (qi >= 1) issueKV(1); else CP_COMMIT();

    float acc_o[16][4];
#pragma unroll
    for (int i = 0; i < 16; i++)
#pragma unroll
        for (int j = 0; j < 4; j++) acc_o[i][j] = 0.f;
    float acc_l[4] = {0.f, 0.f, 0.f, 0.f};   // ones-column row-sum accumulator
    float mrow[2] = {-1e30f, -1e30f};        // running max of UNSCALED scores
    // exp(sc*(s-m)) == exp2f((s-m)*C2), C2 = (1/sqrt(128))*log2(e)
    const float C2 = (float)(0.08838834764831845 * 1.4426950408889634);

    // B-frag of all-ones in column 0 (col = lane>>2): lanes 0..3 hold 1.0h pairs
    const uint32_t b_ones = ((lane >> 2) == 0) ? 0x3C003C00u : 0u;
    uint32_t bO[2] = { b_ones, b_ones };

    const int m_ = lane >> 3, rr = lane & 7;
    const int kh    = (m_ >> 1) * 16;
    const int a_row = w * 16 + (m_ & 1) * 8 + rr;

    for (int kt = 0; kt <= qi; kt++) {
        CP_WAIT(1);            // KV(kt) landed (groups complete in order)
        __syncthreads();       // visible to all warps (covers Q on kt=0)

        const uint32_t kbase = sb + KOFF + (kt & 1) * 16384;
        float accs[8][4];
#pragma unroll
        for (int i = 0; i < 8; i++)
#pragma unroll
            for (int j = 0; j < 4; j++) accs[i][j] = 0.f;

#pragma unroll
        for (int ks = 0; ks < 8; ks++) {            // 8 x k16 over headdim 128
            const int colb = ks * 32 + kh;
            uint32_t a[4];
            ldsm_x4(a, sb + QOFF + ((a_row * 256 + colb) ^ ((a_row & 7) << 4)));
            uint32_t bfr[8][2];
#pragma unroll
            for (int nf2 = 0; nf2 < 4; nf2++) {
                const int row = nf2 * 16 + (m_ & 1) * 8 + rr;   // kv rows 0..63
                uint32_t t[4];
                ldsm_x4(t, kbase + ((row * 256 + colb) ^ ((row & 7) << 4)));
                bfr[nf2 * 2][0]     = t[0]; bfr[nf2 * 2][1]     = t[2];
                bfr[nf2 * 2 + 1][0] = t[1]; bfr[nf2 * 2 + 1][1] = t[3];
            }
#pragma unroll
            for (int nf = 0; nf < 8; nf++) mma_f16(accs[nf], a, bfr[nf]);
        }

        // causal mask (diagonal tile only) on UNSCALED scores
        if (kt == qi) {
#pragma unroll
            for (int nf = 0; nf < 8; nf++)
#pragma unroll
                for (int r = 0; r < 2; r++)
#pragma unroll
                    for (int j = 0; j < 2; j++) {
                        const int cl = nf * 8 + (lane & 3) * 2 + j;
                        const int rl = w * 16 + (lane >> 2) + r * 8;
                        if (cl > rl) accs[nf][r * 2 + j] = -1e30f;
                    }
        }

        // online softmax (scale folded into exp2; P pairs via ex2.f16x2)
        uint32_t ph[8][2];
#pragma unroll
        for (int r = 0; r < 2; r++) {
            float vmax = -1e30f;
#pragma unroll
            for (int nf = 0; nf < 8; nf++) {
                vmax = fmaxf(vmax, accs[nf][r * 2]);
                vmax = fmaxf(vmax, accs[nf][r * 2 + 1]);
            }
            vmax = fmaxf(vmax, __shfl_xor_sync(0xffffffffu, vmax, 1));
            vmax = fmaxf(vmax, __shfl_xor_sync(0xffffffffu, vmax, 2));
            const float mnew = fmaxf(mrow[r], vmax);
#pragma unroll
            for (int nf = 0; nf < 8; nf++) {
                __half2 e = __floats2half2_rn((accs[nf][r * 2]     - mnew) * C2,
                                              (accs[nf][r * 2 + 1] - mnew) * C2);
                ph[nf][r] = h2exp2_(*(uint32_t*)&e);
            }
            const float alpha = exp2f((mrow[r] - mnew) * C2);
            mrow[r] = mnew;
            acc_l[r * 2]     *= alpha;
            acc_l[r * 2 + 1] *= alpha;
#pragma unroll
            for (int nf = 0; nf < 16; nf++) {
                acc_o[nf][r * 2]     *= alpha;
                acc_o[nf][r * 2 + 1] *= alpha;
            }
        }

        // O += P * V ; l += P * 1  (V arrived with K; P A-frags from registers)
        const uint32_t vbase = sb + VOFF + (kt & 1) * 16384;
        const int vr_lane = ((lane >> 3) & 1) * 8 + (lane & 7);
        const int vc_lane = (lane >> 4) * 16;
#pragma unroll
        for (int ks = 0; ks < 4; ks++) {            // 4 x k16 over 64 kv
            uint32_t aP[4];
            aP[0] = ph[2 * ks][0];
            aP[1] = ph[2 * ks][1];
            aP[2] = ph[2 * ks + 1][0];
            aP[3] = ph[2 * ks + 1][1];
            mma_f16(acc_l, aP, bO);                 // row-sum into col 0
#pragma unroll
            for (int dg = 0; dg < 8; dg++) {        // 16 halves of headdim each
                const int vrow = ks * 16 + vr_lane;
                const int vcol = dg * 32 + vc_lane;
                uint32_t t[4];
                ldsm_x4t(t, vbase + ((vrow * 256 + vcol) ^ ((vrow & 7) << 4)));
                uint32_t b0[2] = { t[0], t[1] };
                uint32_t b1[2] = { t[2], t[3] };
                mma_f16(acc_o[dg * 2],     aP, b0);
                mma_f16(acc_o[dg * 2 + 1], aP, b1);
            }
        }

        __syncthreads();       // all warps done reading K(kt)/V(kt)
        if (kt + 2 <= qi) issueKV(kt + 2); else CP_COMMIT();
    }

    // l lives in col 0 (lanes with lane%4==0); broadcast across each quad
    const int qlead = lane & ~3;
    const float l0 = __shfl_sync(0xffffffffu, acc_l[0], qlead);
    const float l1 = __shfl_sync(0xffffffffu, acc_l[2], qlead);
    const float inv0 = 1.f / l0;
    const float inv1 = 1.f / l1;

    // normalize + write fp16
#pragma unroll
    for (int nf = 0; nf < 16; nf++)
#pragma unroll
        for (int r = 0; r < 2; r++) {
            const int row = q0 + w * 16 + (lane >> 2) + r * 8;
            const int col = h * HEAD_DIM + nf * 8 + (lane & 3) * 2;
            const float inv = r ? inv1 : inv0;
            __half2 hv = __floats2half2_rn(acc_o[nf][r * 2] * inv,
                                           acc_o[nf][r * 2 + 1] * inv);
            *(__half2*)&gO[((size_t)b * TQ + row) * D_MODEL + col] = hv;
        }
}

// ---------------------------------------------------------------------------
// cache pass, fused: permuted fp32 cache half of new_k/new_v into d_out AND
// fp16 rounding of the caches for attention (single read of each cache).
// grid.z: 0 -> K, 1 -> V. 2097152 float4 per tensor.
// ---------------------------------------------------------------------------
__global__ __launch_bounds__(256) void copy_cache_kv(
    const float* __restrict__ cacheK,
    const float* __restrict__ cacheV,
    float* __restrict__ dstK,
    float* __restrict__ dstV,
    __half* __restrict__ hcK,
    __half* __restrict__ hcV)
{
    const int i = blockIdx.x * 256 + threadIdx.x;
    const int b   = i >> 19;            // 524288 float4 per batch
    const int rem = i & 524287;
    const int jj  = rem >> 9;           // 0..1023 (h*64 + cache row)
    const int c   = (rem & 511) * 4;
    const int h   = jj >> 6;
    const int j   = h * 128 + (jj & 63);
    const int t   = (jj & 63) * 16 + (c >> 7);
    const int d   = c & 127;

    const float* cache = blockIdx.z ? cacheV : cacheK;
    float*       dst   = blockIdx.z ? dstV   : dstK;
    __half*      hc    = blockIdx.z ? hcV    : hcK;

    const size_t src_off = ((size_t)b * CACHE_LEN + t) * D_MODEL + h * HEAD_DIM + d;
    float4 v = *(const float4*)&cache[src_off];
    *(float4*)&dst[((size_t)b * 2048 + j) * D_MODEL + c] = v;

    __half2 h0 = __floats2half2_rn(v.x, v.y);
    __half2 h1 = __floats2half2_rn(v.z, v.w);
    uint2 u;
    u.x = *(uint32_t*)&h0;
    u.y = *(uint32_t*)&h1;
    *(uint2*)&hc[src_off] = u;
}

// ---------------------------------------------------------------------------
// launch — serial single stream
// ---------------------------------------------------------------------------
extern "C" void kernel_launch(void* const* d_in, const int* in_sizes, int n_in,
                              void* d_out, int out_size)
{
    const float* query   = (const float*)d_in[0];
    const float* key     = (const float*)d_in[1];
    const float* value   = (const float*)d_in[2];
    const float* cacheK  = (const float*)d_in[3];
    const float* cacheV  = (const float*)d_in[4];
    const float* Wq      = (const float*)d_in[5];
    const float* bq      = (const float*)d_in[6];
    const float* Wk      = (const float*)d_in[7];
    const float* bk      = (const float*)d_in[8];
    const float* Wv      = (const float*)d_in[9];
    const float* bv      = (const float*)d_in[10];
    const float* Wo      = (const float*)d_in[11];
    const float* bo      = (const float*)d_in[12];
    float* out = (float*)d_out;

    __half *phQ, *pO, *phq, *phk, *phv, *phWq, *phWk, *phWv, *phWo, *phck, *phcv;
    cudaGetSymbolAddress((void**)&phQ, g_hQ);
    cudaGetSymbolAddress((void**)&pO, g_O);
    cudaGetSymbolAddress((void**)&phq, g_hq);
    cudaGetSymbolAddress((void**)&phk, g_hk);
    cudaGetSymbolAddress((void**)&phv, g_hv);
    cudaGetSymbolAddress((void**)&phWq, g_hWq);
    cudaGetSymbolAddress((void**)&phWk, g_hWk);
    cudaGetSymbolAddress((void**)&phWv, g_hWv);
    cudaGetSymbolAddress((void**)&phWo, g_hWo);
    cudaGetSymbolAddress((void**)&phck, g_hck);
    cudaGetSymbolAddress((void**)&phcv, g_hcv);

    cudaFuncSetAttribute(gemm_tc, cudaFuncAttributeMaxDynamicSharedMemorySize,
                         GEMM_SMEM);
    cudaFuncSetAttribute(attn_kernel, cudaFuncAttributeMaxDynamicSharedMemorySize,
                         ATT_SMEM);

    const int NA = M_ROWS * D_MODEL / 4;     // 2097152 float4
    const int NW = D_MODEL * D_MODEL / 4;    // 1048576 float4

    // 1) pre-round inputs to fp16 (caches handled by the fused cache pass)
    RoundArgs ra;
    ra.src[0] = query; ra.dst[0] = phq;  ra.n4[0] = NA;
    ra.src[1] = key;   ra.dst[1] = phk;  ra.n4[1] = NA;
    ra.src[2] = value; ra.dst[2] = phv;  ra.n4[2] = NA;
    ra.src[3] = Wq;    ra.dst[3] = phWq; ra.n4[3] = NW;
    ra.src[4] = Wk;    ra.dst[4] = phWk; ra.n4[4] = NW;
    ra.src[5] = Wv;    ra.dst[5] = phWv; ra.n4[5] = NW;
    ra.src[6] = Wo;    ra.dst[6] = phWo; ra.n4[6] = NW;
    round_f16<<<dim3(NA / 256, 1, 7), 256>>>(ra);

    // 2) cache pass: permuted fp32 halves into d_out + fp16 caches for attn
    copy_cache_kv<<<dim3(2097152 / 256, 1, 2), 256>>>(
        cacheK, cacheV, out + 8388608, out + 25165824, phck, phcv);

    // 3) Q/K/V projections. Q -> fp16 scratch; K/V -> straight into d_out.
    ProjArgs pa;
    pa.A[0] = phq;  pa.W[0] = phWq; pa.Bias[0] = bq;
    pa.Ch[0] = phQ; pa.C[0] = nullptr;            pa.mode[0] = 0;
    pa.A[1] = phk;  pa.W[1] = phWk; pa.Bias[1] = bk;
    pa.Ch[1] = nullptr; pa.C[1] = out + 8388608;  pa.mode[1] = 1;
    pa.A[2] = phv;  pa.W[2] = phWv; pa.Bias[2] = bv;
    pa.Ch[2] = nullptr; pa.C[2] = out + 25165824; pa.mode[2] = 1;
    gemm_tc<<<dim3(D_MODEL / 128, M_ROWS / 128, 3), 128, GEMM_SMEM>>>(pa);

    // 4) attention (cache-only, causal), fp16 HMMA, fused-KV pipeline
    attn_kernel<<<dim3(TQ / 64, NUM_HEADS, BATCH), 128, ATT_SMEM>>>(
        phQ, phck, phcv, pO);

    // 5) output projection -> out[0 .. 8388608)
    ProjArgs po;
    po.A[0] = pO; po.W[0] = phWo; po.Bias[0] = bo;
    po.C[0] = out; po.Ch[0] = nullptr; po.mode[0] = 2;
    po.A[1] = po.A[0]; po.W[1] = po.W[0]; po.Bias[1] = po.Bias[0];
    po.C[1] = po.C[0]; po.Ch[1] = nullptr; po.mode[1] = 2;
    po.A[2] = po.A[0]; po.W[2] = po.W[0]; po.Bias[2] = po.Bias[0];
    po.C[2] = po.C[0]; po.Ch[2] = nullptr; po.mode[2] = 2;
    gemm_tc<<<dim3(D_MODEL / 128, M_ROWS / 128, 1), 128, GEMM_SMEM>>>(po);
}

// round 12
// speedup vs baseline: 1.2126x; 1.0157x over previous
#include <cuda_runtime.h>
#include <cuda_bf16.h>
#include <cuda_fp16.h>
#include <cstdint>
#include <cstdio>

// ---------------------------------------------------------------------------
// Problem constants
// ---------------------------------------------------------------------------
#define D_MODEL   2048
#define NUM_HEADS 16
#define HEAD_DIM  128
#define BATCH     4
#define TQ        1024
#define CACHE_LEN 1024
#define M_ROWS    (BATCH * TQ)          // 4096

// scratch (device globals: allocation-free scratch per harness rules)
__device__ __half g_hQ[M_ROWS * D_MODEL];             // projected Q, fp16
__device__ __half g_O[M_ROWS * D_MODEL];              // attention out, fp16
// fp16 pre-rounded inputs
__device__ __half g_hq[M_ROWS * D_MODEL];
__device__ __half g_hk[M_ROWS * D_MODEL];
__device__ __half g_hv[M_ROWS * D_MODEL];
__device__ __half g_hWq[D_MODEL * D_MODEL];
__device__ __half g_hWk[D_MODEL * D_MODEL];
__device__ __half g_hWv[D_MODEL * D_MODEL];
__device__ __half g_hWo[D_MODEL * D_MODEL];
__device__ __half g_hck[BATCH * CACHE_LEN * D_MODEL]; // fp16 cache K (attention)
__device__ __half g_hcv[BATCH * CACHE_LEN * D_MODEL]; // fp16 cache V (attention)

// ---------------------------------------------------------------------------
// helpers
// ---------------------------------------------------------------------------
__device__ __forceinline__ uint32_t smem_u32(const void* p) {
    uint32_t a;
    asm("{ .reg .u64 t; cvta.to.shared.u64 t, %1; cvt.u32.u64 %0, t; }"
        : "=r"(a) : "l"(p));
    return a;
}

// fp16 m16n8k16: D += A*B  (row.col, f32 accum)
__device__ __forceinline__ void mma_f16(float* d, const uint32_t* a, const uint32_t* b) {
    asm volatile(
        "mma.sync.aligned.m16n8k16.row.col.f32.f16.f16.f32 "
        "{%0,%1,%2,%3}, {%4,%5,%6,%7}, {%8,%9}, {%0,%1,%2,%3};\n"
        : "+f"(d[0]), "+f"(d[1]), "+f"(d[2]), "+f"(d[3])
        : "r"(a[0]), "r"(a[1]), "r"(a[2]), "r"(a[3]),
          "r"(b[0]), "r"(b[1]));
}

__device__ __forceinline__ void ldsm_x4(uint32_t* r, uint32_t addr) {
    asm volatile("ldmatrix.sync.aligned.m8n8.x4.shared.b16 {%0,%1,%2,%3}, [%4];"
                 : "=r"(r[0]), "=r"(r[1]), "=r"(r[2]), "=r"(r[3]) : "r"(addr));
}

__device__ __forceinline__ void ldsm_x4t(uint32_t* r, uint32_t addr) {
    asm volatile("ldmatrix.sync.aligned.m8n8.x4.trans.shared.b16 {%0,%1,%2,%3}, [%4];"
                 : "=r"(r[0]), "=r"(r[1]), "=r"(r[2]), "=r"(r[3]) : "r"(addr));
}

// packed half2 2^x (one MUFU op for two values)
__device__ __forceinline__ uint32_t h2exp2_(uint32_t x) {
    uint32_t r;
    asm("ex2.approx.f16x2 %0, %1;" : "=r"(r) : "r"(x));
    return r;
}

__device__ __forceinline__ void cp_async16(uint32_t dst, const void* src) {
    asm volatile("cp.async.cg.shared.global [%0], [%1], 16;"
                 :: "r"(dst), "l"(src));
}
#define CP_COMMIT()  asm volatile("cp.async.commit_group;" ::: "memory")
#define CP_WAIT(N)   asm volatile("cp.async.wait_group %0;" :: "n"(N) : "memory")

// ---------------------------------------------------------------------------
// pre-rounding pass: dst = fp16(src), up to 7 tensors per launch (grid.z)
// ---------------------------------------------------------------------------
struct RoundArgs {
    const float* src[7];
    __half*      dst[7];
    int          n4[7];     // number of float4 elements
};

__global__ __launch_bounds__(256) void round_f16(RoundArgs ra) {
    const int z = blockIdx.z;
    const int i = blockIdx.x * 256 + threadIdx.x;
    if (i >= ra.n4[z]) return;
    float4 v = ((const float4*)ra.src[z])[i];
    __half2 h0 = __floats2half2_rn(v.x, v.y);
    __half2 h1 = __floats2half2_rn(v.z, v.w);
    uint2 u;
    u.x = *(uint32_t*)&h0;
    u.y = *(uint32_t*)&h1;
    ((uint2*)ra.dst[z])[i] = u;
}

// ---------------------------------------------------------------------------
// Pipelined TN GEMM (fp16 HMMA):  C[M,N] = A[M,K] * W[N,K]^T + bias[N]
// CTA 128x128 with FOUR warps (128 threads), warp tile 64x64 (2x2 grid).
// K-tile 64, 3-stage cp.async ring, m16n8k16 HMMA. (unchanged — measured at
// ~98% of the f32-accumulate classic-HMMA structural ceiling.)
// Output modes: 0 = fp16 to Ch (Q-proj), 1 = permuted fp32 into new_kv
// (K/V proj land directly in d_out), 2 = plain fp32 (O-proj).
// ---------------------------------------------------------------------------
#define NST        3
#define TILE_B     16384                 // 128 rows * 128 bytes
#define GEMM_SMEM  (2 * NST * TILE_B + 1024)
#define NKT        (D_MODEL / 64)        // 32 k-tiles

struct ProjArgs {
    const __half* A[3];
    const __half* W[3];
    const float*  Bias[3];
    float*        C[3];
    __half*       Ch[3];
    int           mode[3];
};

__global__ __launch_bounds__(128, 2) void gemm_tc(ProjArgs args) {
    extern __shared__ char dyn_smem[];
    char* db = (char*)(((uintptr_t)dyn_smem + 1023) & ~(uintptr_t)1023);
    const uint32_t db_u = smem_u32(db);

    const int z = blockIdx.z;
    const __half* __restrict__ A    = args.A[z];
    const __half* __restrict__ W    = args.W[z];
    const float*  __restrict__ bias = args.Bias[z];
    float* __restrict__        C    = args.C[z];
    __half* __restrict__       Ch   = args.Ch[z];
    const int mode = args.mode[z];

    const int tid  = threadIdx.x;
    const int lane = tid & 31;
    const int w    = tid >> 5;     // 0..3
    const int wm   = w >> 1;       // 0..1
    const int wn   = w & 1;        // 0..1
    const int n0   = blockIdx.x * 128;
    const int m0   = blockIdx.y * 128;

    const __half* Ag = A + (size_t)m0 * D_MODEL;
    const __half* Wg = W + (size_t)n0 * D_MODEL;

    // per-thread load geometry: 8 chunks A + 8 chunks B per stage (128 thr)
    uint32_t swoff[8];
    size_t   gofs[8];
#pragma unroll
    for (int rep = 0; rep < 8; rep++) {
        const int g = rep * 128 + tid;          // 0..1023
        const int r = g >> 3;                   // row 0..127
        const int i = g & 7;                    // 16B chunk
        gofs[rep]  = (size_t)r * D_MODEL + i * 8;
        swoff[rep] = (uint32_t)((r * 128 + i * 16) ^ ((r & 7) << 4));
    }

    float acc[4][8][4];
#pragma unroll
    for (int i = 0; i < 4; i++)
#pragma unroll
        for (int j = 0; j < 8; j++)
#pragma unroll
            for (int k = 0; k < 4; k++) acc[i][j][k] = 0.f;

    auto issue = [&](int ks) {
        const int slot = ks % NST;
        const int kc   = ks * 64;
        const uint32_t da  = db_u + slot * TILE_B;
        const uint32_t dbb = db_u + NST * TILE_B + slot * TILE_B;
#pragma unroll
        for (int rep = 0; rep < 8; rep++)
            cp_async16(da + swoff[rep], Ag + gofs[rep] + kc);
#pragma unroll
        for (int rep = 0; rep < 8; rep++)
            cp_async16(dbb + swoff[rep], Wg + gofs[rep] + kc);
        CP_COMMIT();
    };

    issue(0);
    issue(1);

    const int m_ = lane >> 3;
    const int rr = lane & 7;
    const int a_row_base = wm * 64 + (m_ & 1) * 8 + rr;   // + mf*16
    const int b_row_base = wn * 64 + (m_ & 1) * 8 + rr;   // + nf2*16
    const int k_half     = (m_ >> 1) * 16;

#pragma unroll 1
    for (int kt = 0; kt < NKT; kt++) {
        if (kt < NKT - 2) { CP_WAIT(1); } else { CP_WAIT(0); }
        __syncthreads();
        if (kt + 2 < NKT) issue(kt + 2);

        const int slot = kt % NST;
        const uint32_t da  = db_u + slot * TILE_B;
        const uint32_t dbb = db_u + NST * TILE_B + slot * TILE_B;

#pragma unroll
        for (int ks = 0; ks < 4; ks++) {
            const int kb = ks * 32 + k_half;
            uint32_t a[4][4], b[8][2];
#pragma unroll
            for (int mf = 0; mf < 4; mf++) {
                const int row = a_row_base + mf * 16;
                const uint32_t off = (uint32_t)((row * 128 + kb) ^ ((row & 7) << 4));
                ldsm_x4(a[mf], da + off);
            }
#pragma unroll
            for (int nf2 = 0; nf2 < 4; nf2++) {
                const int row = b_row_base + nf2 * 16;
                const uint32_t off = (uint32_t)((row * 128 + kb) ^ ((row & 7) << 4));
                uint32_t t[4];
                ldsm_x4(t, dbb + off);
                b[nf2 * 2][0]     = t[0]; b[nf2 * 2][1]     = t[2];
                b[nf2 * 2 + 1][0] = t[1]; b[nf2 * 2 + 1][1] = t[3];
            }
#pragma unroll
            for (int mf = 0; mf < 4; mf++)
#pragma unroll
                for (int nf = 0; nf < 8; nf++)
                    mma_f16(acc[mf][nf], a[mf], b[nf]);
        }
    }

    // epilogue (per mode)
#pragma unroll
    for (int mf = 0; mf < 4; mf++) {
#pragma unroll
        for (int nf = 0; nf < 8; nf++) {
            const int row = m0 + wm * 64 + mf * 16 + (lane >> 2);
            const int col = n0 + wn * 64 + nf * 8 + (lane & 3) * 2;
            const float b0 = bias[col], b1 = bias[col + 1];
            const float x0 = acc[mf][nf][0] + b0, x1 = acc[mf][nf][1] + b1;
            const float y0 = acc[mf][nf][2] + b0, y1 = acc[mf][nf][3] + b1;
            if (mode == 0) {
                __half2 h0 = __floats2half2_rn(x0, x1);
                __half2 h1 = __floats2half2_rn(y0, y1);
                *(__half2*)&Ch[(size_t)row * D_MODEL + col]       = h0;
                *(__half2*)&Ch[(size_t)(row + 8) * D_MODEL + col] = h1;
            } else if (mode == 1) {
                // direct write into new_k/new_v (proj half): t' = 1024 + t
                const int h  = col >> 7, d = col & 127;
#pragma unroll
                for (int rep = 0; rep < 2; rep++) {
                    const int rw = row + rep * 8;
                    const int bb = rw >> 10, t = rw & 1023;
                    const int j  = h * 128 + 64 + (t >> 4);
                    const int c  = (t & 15) * 128 + d;
                    float2 v = rep ? make_float2(y0, y1) : make_float2(x0, x1);
                    *(float2*)&C[((size_t)bb * 2048 + j) * 2048 + c] = v;
                }
            } else {
                *(float2*)&C[(size_t)row * D_MODEL + col]       = make_float2(x0, x1);
                *(float2*)&C[(size_t)(row + 8) * D_MODEL + col] = make_float2(y0, y1);
            }
        }
    }
}

// ---------------------------------------------------------------------------
// fp16 flash attention over the cache only (mask tril(TQ,total) => cache half).
// 128 threads (4 warps), 64 q-rows/CTA, 64 kv/tile, fused K+V commit groups,
// single CP_WAIT + 2 barriers per iteration; P in registers; l via ones-column
// tensor-core MMA; P pairs via ex2.approx.f16x2. (unchanged from R11)
// SMEM: Q 16K | K0 K1 32K | V0 V1 32K = 80K, 2 CTA/SM.
// qi reversed vs blockIdx.x: heavy (long) CTAs launch first -> better tail.
// ---------------------------------------------------------------------------
#define QOFF 0
#define KOFF 16384
#define VOFF (KOFF + 2 * 16384)
#define ATT_SMEM (VOFF + 2 * 16384)   // 81920

__global__ __launch_bounds__(128, 2) void attn_kernel(
    const __half* __restrict__ gQ,
    const __half* __restrict__ hK,
    const __half* __restrict__ hV,
    __half* __restrict__ gO)
{
    extern __shared__ char smc[];
    const uint32_t sb = smem_u32(smc);
    const int tid = threadIdx.x, lane = tid & 31, w = tid >> 5;
    const int qi = (int)gridDim.x - 1 - blockIdx.x;   // heavy tiles first
    const int h = blockIdx.y, b = blockIdx.z;
    const int q0 = qi * 64;

    const __half* Qg = gQ + ((size_t)b * TQ + q0) * D_MODEL + h * HEAD_DIM;
    const __half* Kg = hK + (size_t)b * CACHE_LEN * D_MODEL + h * HEAD_DIM;
    const __half* Vg = hV + (size_t)b * CACHE_LEN * D_MODEL + h * HEAD_DIM;

    // Q tile 64x128 halves -> swizzled smem (rows 256B)
#pragma unroll
    for (int rep = 0; rep < 8; rep++) {
        const int g = rep * 128 + tid;
        const int r = g >> 4, i = g & 15;
        uint4 v = *(const uint4*)(Qg + (size_t)r * D_MODEL + i * 8);
        *(uint4*)(smc + QOFF + ((r * 256 + i * 16) ^ ((r & 7) << 4))) = v;
    }

    // one commit group per kv-tile: K chunks + V chunks together
    auto issueKV = [&](int kt) {
#pragma unroll
        for (int rep = 0; rep < 8; rep++) {
            const int g = rep * 128 + tid;
            const int r = g >> 4, i = g & 15;
            const uint32_t so = (uint32_t)((r * 256 + i * 16) ^ ((r & 7) << 4));
            cp_async16(sb + KOFF + (kt & 1) * 16384 + so,
                       Kg + (size_t)(kt * 64 + r) * D_MODEL + i * 8);
            cp_async16(sb + VOFF + (kt & 1) * 16384 + so,
                       Vg + (size_t)(kt * 64 + r) * D_MODEL + i * 8);
        }
        CP_COMMIT();
    };

    issueKV(0);
    if (qi >= 1) issueKV(1); else CP_COMMIT();

    float acc_o[16][4];
#pragma unroll
    for (int i = 0; i < 16; i++)
#pragma unroll
        for (int j = 0; j < 4; j++) acc_o[i][j] = 0.f;
    float acc_l[4] = {0.f, 0.f, 0.f, 0.f};   // ones-column row-sum accumulator
    float mrow[2] = {-1e30f, -1e30f};        // running max of UNSCALED scores
    // exp(sc*(s-m)) == exp2f((s-m)*C2), C2 = (1/sqrt(128))*log2(e)
    const float C2 = (float)(0.08838834764831845 * 1.4426950408889634);

    // B-frag of all-ones in column 0 (col = lane>>2): lanes 0..3 hold 1.0h pairs
    const uint32_t b_ones = ((lane >> 2) == 0) ? 0x3C003C00u : 0u;
    uint32_t bO[2] = { b_ones, b_ones };

    const int m_ = lane >> 3, rr = lane & 7;
    const int kh    = (m_ >> 1) * 16;
    const int a_row = w * 16 + (m_ & 1) * 8 + rr;

    for (int kt = 0; kt <= qi; kt++) {
        CP_WAIT(1);            // KV(kt) landed (groups complete in order)
        __syncthreads();       // visible to all warps (covers Q on kt=0)

        const uint32_t kbase = sb + KOFF + (kt & 1) * 16384;
        float accs[8][4];
#pragma unroll
        for (int i = 0; i < 8; i++)
#pragma unroll
            for (int j = 0; j < 4; j++) accs[i][j] = 0.f;

#pragma unroll
        for (int ks = 0; ks < 8; ks++) {            // 8 x k16 over headdim 128
            const int colb = ks * 32 + kh;
            uint32_t a[4];
            ldsm_x4(a, sb + QOFF + ((a_row * 256 + colb) ^ ((a_row & 7) << 4)));
            uint32_t bfr[8][2];
#pragma unroll
            for (int nf2 = 0; nf2 < 4; nf2++) {
                const int row = nf2 * 16 + (m_ & 1) * 8 + rr;   // kv rows 0..63
                uint32_t t[4];
                ldsm_x4(t, kbase + ((row * 256 + colb) ^ ((row & 7) << 4)));
                bfr[nf2 * 2][0]     = t[0]; bfr[nf2 * 2][1]     = t[2];
                bfr[nf2 * 2 + 1][0] = t[1]; bfr[nf2 * 2 + 1][1] = t[3];
            }
#pragma unroll
            for (int nf = 0; nf < 8; nf++) mma_f16(accs[nf], a, bfr[nf]);
        }

        // causal mask (diagonal tile only) on UNSCALED scores
        if (kt == qi) {
#pragma unroll
            for (int nf = 0; nf < 8; nf++)
#pragma unroll
                for (int r = 0; r < 2; r++)
#pragma unroll
                    for (int j = 0; j < 2; j++) {
                        const int cl = nf * 8 + (lane & 3) * 2 + j;
                        const int rl = w * 16 + (lane >> 2) + r * 8;
                        if (cl > rl) accs[nf][r * 2 + j] = -1e30f;
                    }
        }

        // online softmax (scale folded into exp2; P pairs via ex2.f16x2)
        uint32_t ph[8][2];
#pragma unroll
        for (int r = 0; r < 2; r++) {
            float vmax = -1e30f;
#pragma unroll
            for (int nf = 0; nf < 8; nf++) {
                vmax = fmaxf(vmax, accs[nf][r * 2]);
                vmax = fmaxf(vmax, accs[nf][r * 2 + 1]);
            }
            vmax = fmaxf(vmax, __shfl_xor_sync(0xffffffffu, vmax, 1));
            vmax = fmaxf(vmax, __shfl_xor_sync(0xffffffffu, vmax, 2));
            const float mnew = fmaxf(mrow[r], vmax);
#pragma unroll
            for (int nf = 0; nf < 8; nf++) {
                __half2 e = __floats2half2_rn((accs[nf][r * 2]     - mnew) * C2,
                                              (accs[nf][r * 2 + 1] - mnew) * C2);
                ph[nf][r] = h2exp2_(*(uint32_t*)&e);
            }
            const float alpha = exp2f((mrow[r] - mnew) * C2);
            mrow[r] = mnew;
            acc_l[r * 2]     *= alpha;
            acc_l[r * 2 + 1] *= alpha;
#pragma unroll
            for (int nf = 0; nf < 16; nf++) {
                acc_o[nf][r * 2]     *= alpha;
                acc_o[nf][r * 2 + 1] *= alpha;
            }
        }

        // O += P * V ; l += P * 1  (V arrived with K; P A-frags from registers)
        const uint32_t vbase = sb + VOFF + (kt & 1) * 16384;
        const int vr_lane = ((lane >> 3) & 1) * 8 + (lane & 7);
        const int vc_lane = (lane >> 4) * 16;
#pragma unroll
        for (int ks = 0; ks < 4; ks++) {            // 4 x k16 over 64 kv
            uint32_t aP[4];
            aP[0] = ph[2 * ks][0];
            aP[1] = ph[2 * ks][1];
            aP[2] = ph[2 * ks + 1][0];
            aP[3] = ph[2 * ks + 1][1];
            mma_f16(acc_l, aP, bO);                 // row-sum into col 0
#pragma unroll
            for (int dg = 0; dg < 8; dg++) {        // 16 halves of headdim each
                const int vrow = ks * 16 + vr_lane;
                const int vcol = dg * 32 + vc_lane;
                uint32_t t[4];
                ldsm_x4t(t, vbase + ((vrow * 256 + vcol) ^ ((vrow & 7) << 4)));
                uint32_t b0[2] = { t[0], t[1] };
                uint32_t b1[2] = { t[2], t[3] };
                mma_f16(acc_o[dg * 2],     aP, b0);
                mma_f16(acc_o[dg * 2 + 1], aP, b1);
            }
        }

        __syncthreads();       // all warps done reading K(kt)/V(kt)
        if (kt + 2 <= qi) issueKV(kt + 2); else CP_COMMIT();
    }

    // l lives in col 0 (lanes with lane%4==0); broadcast across each quad
    const int qlead = lane & ~3;
    const float l0 = __shfl_sync(0xffffffffu, acc_l[0], qlead);
    const float l1 = __shfl_sync(0xffffffffu, acc_l[2], qlead);
    const float inv0 = 1.f / l0;
    const float inv1 = 1.f / l1;

    // normalize + write fp16
#pragma unroll
    for (int nf = 0; nf < 16; nf++)
#pragma unroll
        for (int r = 0; r < 2; r++) {
            const int row = q0 + w * 16 + (lane >> 2) + r * 8;
            const int col = h * HEAD_DIM + nf * 8 + (lane & 3) * 2;
            const float inv = r ? inv1 : inv0;
            __half2 hv = __floats2half2_rn(acc_o[nf][r * 2] * inv,
                                           acc_o[nf][r * 2 + 1] * inv);
            *(__half2*)&gO[((size_t)b * TQ + row) * D_MODEL + col] = hv;
        }
}

// ---------------------------------------------------------------------------
// cache pass, fused: permuted fp32 cache half of new_k/new_v into d_out AND
// fp16 rounding of the caches for attention (single read of each cache).
// grid.z: 0 -> K, 1 -> V. 2097152 float4 per tensor.
// ---------------------------------------------------------------------------
__global__ __launch_bounds__(256) void copy_cache_kv(
    const float* __restrict__ cacheK,
    const float* __restrict__ cacheV,
    float* __restrict__ dstK,
    float* __restrict__ dstV,
    __half* __restrict__ hcK,
    __half* __restrict__ hcV)
{
    const int i = blockIdx.x * 256 + threadIdx.x;
    const int b   = i >> 19;            // 524288 float4 per batch
    const int rem = i & 524287;
    const int jj  = rem >> 9;           // 0..1023 (h*64 + cache row)
    const int c   = (rem & 511) * 4;
    const int h   = jj >> 6;
    const int j   = h * 128 + (jj & 63);
    const int t   = (jj & 63) * 16 + (c >> 7);
    const int d   = c & 127;

    const float* cache = blockIdx.z ? cacheV : cacheK;
    float*       dst   = blockIdx.z ? dstV   : dstK;
    __half*      hc    = blockIdx.z ? hcV    : hcK;

    const size_t src_off = ((size_t)b * CACHE_LEN + t) * D_MODEL + h * HEAD_DIM + d;
    float4 v = *(const float4*)&cache[src_off];
    *(float4*)&dst[((size_t)b * 2048 + j) * D_MODEL + c] = v;

    __half2 h0 = __floats2half2_rn(v.x, v.y);
    __half2 h1 = __floats2half2_rn(v.z, v.w);
    uint2 u;
    u.x = *(uint32_t*)&h0;
    u.y = *(uint32_t*)&h1;
    *(uint2*)&hc[src_off] = u;
}

// ---------------------------------------------------------------------------
// launch — s2 hides the pure-memory passes (cache copy + Wo rounding) under
// the QKV GEMM. Fork after the 6-tensor round; join before attention.
// Rationale: copy kernel has 16 regs / 0 smem -> co-resides in the GEMM's
// free warp slots; GEMM is 3% DRAM so the copy gets nearly full bandwidth.
// (This is the opposite profile of the R7 overlap failure: no smem conflict,
// no DRAM-bound x DRAM-bound collision.)
// ---------------------------------------------------------------------------
extern "C" void kernel_launch(void* const* d_in, const int* in_sizes, int n_in,
                              void* d_out, int out_size)
{
    const float* query   = (const float*)d_in[0];
    const float* key     = (const float*)d_in[1];
    const float* value   = (const float*)d_in[2];
    const float* cacheK  = (const float*)d_in[3];
    const float* cacheV  = (const float*)d_in[4];
    const float* Wq      = (const float*)d_in[5];
    const float* bq      = (const float*)d_in[6];
    const float* Wk      = (const float*)d_in[7];
    const float* bk      = (const float*)d_in[8];
    const float* Wv      = (const float*)d_in[9];
    const float* bv      = (const float*)d_in[10];
    const float* Wo      = (const float*)d_in[11];
    const float* bo      = (const float*)d_in[12];
    float* out = (float*)d_out;

    __half *phQ, *pO, *phq, *phk, *phv, *phWq, *phWk, *phWv, *phWo, *phck, *phcv;
    cudaGetSymbolAddress((void**)&phQ, g_hQ);
    cudaGetSymbolAddress((void**)&pO, g_O);
    cudaGetSymbolAddress((void**)&phq, g_hq);
    cudaGetSymbolAddress((void**)&phk, g_hk);
    cudaGetSymbolAddress((void**)&phv, g_hv);
    cudaGetSymbolAddress((void**)&phWq, g_hWq);
    cudaGetSymbolAddress((void**)&phWk, g_hWk);
    cudaGetSymbolAddress((void**)&phWv, g_hWv);
    cudaGetSymbolAddress((void**)&phWo, g_hWo);
    cudaGetSymbolAddress((void**)&phck, g_hck);
    cudaGetSymbolAddress((void**)&phcv, g_hcv);

    // one-time stream/event creation (resources only; identical work per call)
    static cudaStream_t s2 = nullptr;
    static cudaEvent_t  evF = nullptr, evJ = nullptr;
    if (s2 == nullptr) {
        cudaStreamCreateWithFlags(&s2, cudaStreamNonBlocking);
        cudaEventCreateWithFlags(&evF, cudaEventDisableTiming);
        cudaEventCreateWithFlags(&evJ, cudaEventDisableTiming);
    }

    cudaFuncSetAttribute(gemm_tc, cudaFuncAttributeMaxDynamicSharedMemorySize,
                         GEMM_SMEM);
    cudaFuncSetAttribute(attn_kernel, cudaFuncAttributeMaxDynamicSharedMemorySize,
                         ATT_SMEM);

    const int NA = M_ROWS * D_MODEL / 4;     // 2097152 float4
    const int NW = D_MODEL * D_MODEL / 4;    // 1048576 float4

    // 1) round the 6 tensors the QKV GEMM needs (s0)
    RoundArgs ra;
    ra.src[0] = query; ra.dst[0] = phq;  ra.n4[0] = NA;
    ra.src[1] = key;   ra.dst[1] = phk;  ra.n4[1] = NA;
    ra.src[2] = value; ra.dst[2] = phv;  ra.n4[2] = NA;
    ra.src[3] = Wq;    ra.dst[3] = phWq; ra.n4[3] = NW;
    ra.src[4] = Wk;    ra.dst[4] = phWk; ra.n4[4] = NW;
    ra.src[5] = Wv;    ra.dst[5] = phWv; ra.n4[5] = NW;
    ra.src[6] = Wv;    ra.dst[6] = phWv; ra.n4[6] = 0;   // unused slot
    round_f16<<<dim3(NA / 256, 1, 6), 256>>>(ra);

    // fork: s2 runs the pure-memory passes under the QKV GEMM
    cudaEventRecord(evF, 0);
    cudaStreamWaitEvent(s2, evF, 0);

    // s2: cache pass (permuted fp32 halves into d_out + fp16 caches for attn)
    copy_cache_kv<<<dim3(2097152 / 256, 1, 2), 256, 0, s2>>>(
        cacheK, cacheV, out + 8388608, out + 25165824, phck, phcv);
    // s2: round Wo (needed only by the O-projection, long after the join)
    RoundArgs rw;
    rw.src[0] = Wo; rw.dst[0] = phWo; rw.n4[0] = NW;
    for (int s = 1; s < 7; s++) { rw.src[s] = Wo; rw.dst[s] = phWo; rw.n4[s] = 0; }
    round_f16<<<dim3(NW / 256, 1, 1), 256, 0, s2>>>(rw);
    cudaEventRecord(evJ, s2);

    // 2) s0: Q/K/V projections. Q -> fp16 scratch; K/V -> straight into d_out.
    ProjArgs pa;
    pa.A[0] = phq;  pa.W[0] = phWq; pa.Bias[0] = bq;
    pa.Ch[0] = phQ; pa.C[0] = nullptr;            pa.mode[0] = 0;
    pa.A[1] = phk;  pa.W[1] = phWk; pa.Bias[1] = bk;
    pa.Ch[1] = nullptr; pa.C[1] = out + 8388608;  pa.mode[1] = 1;
    pa.A[2] = phv;  pa.W[2] = phWv; pa.Bias[2] = bv;
    pa.Ch[2] = nullptr; pa.C[2] = out + 25165824; pa.mode[2] = 1;
    gemm_tc<<<dim3(D_MODEL / 128, M_ROWS / 128, 3), 128, GEMM_SMEM>>>(pa);

    // join: attention needs the fp16 caches (and Wo is ready for O-proj)
    cudaStreamWaitEvent(0, evJ, 0);

    // 3) attention (cache-only, causal), fp16 HMMA, fused-KV pipeline
    attn_kernel<<<dim3(TQ / 64, NUM_HEADS, BATCH), 128, ATT_SMEM>>>(
        phQ, phck, phcv, pO);

    // 4) output projection -> out[0 .. 8388608)
    ProjArgs po;
    po.A[0] = pO; po.W[0] = phWo; po.Bias[0] = bo;
    po.C[0] = out; po.Ch[0] = nullptr; po.mode[0] = 2;
    po.A[1] = po.A[0]; po.W[1] = po.W[0]; po.Bias[1] = po.Bias[0];
    po.C[1] = po.C[0]; po.Ch[1] = nullptr; po.mode[1] = 2;
    po.A[2] = po.A[0]; po.W[2] = po.W[0]; po.Bias[2] = po.Bias[0];
    po.C[2] = po.C[0]; po.Ch[2] = nullptr; po.mode[2] = 2;
    gemm_tc<<<dim3(D_MODEL / 128, M_ROWS / 128, 1), 128, GEMM_SMEM>>>(po);
}

// round 13
// speedup vs baseline: 1.2604x; 1.0394x over previous
#include <cuda_runtime.h>
#include <cuda_bf16.h>
#include <cuda_fp16.h>
#include <cstdint>
#include <cstdio>

// ---------------------------------------------------------------------------
// Problem constants
// ---------------------------------------------------------------------------
#define D_MODEL   2048
#define NUM_HEADS 16
#define HEAD_DIM  128
#define BATCH     4
#define TQ        1024
#define CACHE_LEN 1024
#define M_ROWS    (BATCH * TQ)          // 4096

// scratch (device globals: allocation-free scratch per harness rules)
__device__ __half g_hQ[M_ROWS * D_MODEL];             // projected Q, fp16
__device__ __half g_O[M_ROWS * D_MODEL];              // attention out, fp16
// fp16 pre-rounded inputs
__device__ __half g_hq[M_ROWS * D_MODEL];
__device__ __half g_hk[M_ROWS * D_MODEL];
__device__ __half g_hv[M_ROWS * D_MODEL];
__device__ __half g_hWq[D_MODEL * D_MODEL];
__device__ __half g_hWk[D_MODEL * D_MODEL];
__device__ __half g_hWv[D_MODEL * D_MODEL];
__device__ __half g_hWo[D_MODEL * D_MODEL];
__device__ __half g_hck[BATCH * CACHE_LEN * D_MODEL]; // fp16 cache K (attention)
__device__ __half g_hcv[BATCH * CACHE_LEN * D_MODEL]; // fp16 cache V (attention)

// ---------------------------------------------------------------------------
// helpers
// ---------------------------------------------------------------------------
__device__ __forceinline__ uint32_t smem_u32(const void* p) {
    uint32_t a;
    asm("{ .reg .u64 t; cvta.to.shared.u64 t, %1; cvt.u32.u64 %0, t; }"
        : "=r"(a) : "l"(p));
    return a;
}

// fp16 m16n8k16: D += A*B  (row.col, f32 accum)
__device__ __forceinline__ void mma_f16(float* d, const uint32_t* a, const uint32_t* b) {
    asm volatile(
        "mma.sync.aligned.m16n8k16.row.col.f32.f16.f16.f32 "
        "{%0,%1,%2,%3}, {%4,%5,%6,%7}, {%8,%9}, {%0,%1,%2,%3};\n"
        : "+f"(d[0]), "+f"(d[1]), "+f"(d[2]), "+f"(d[3])
        : "r"(a[0]), "r"(a[1]), "r"(a[2]), "r"(a[3]),
          "r"(b[0]), "r"(b[1]));
}

__device__ __forceinline__ void ldsm_x4(uint32_t* r, uint32_t addr) {
    asm volatile("ldmatrix.sync.aligned.m8n8.x4.shared.b16 {%0,%1,%2,%3}, [%4];"
                 : "=r"(r[0]), "=r"(r[1]), "=r"(r[2]), "=r"(r[3]) : "r"(addr));
}

__device__ __forceinline__ void ldsm_x4t(uint32_t* r, uint32_t addr) {
    asm volatile("ldmatrix.sync.aligned.m8n8.x4.trans.shared.b16 {%0,%1,%2,%3}, [%4];"
                 : "=r"(r[0]), "=r"(r[1]), "=r"(r[2]), "=r"(r[3]) : "r"(addr));
}

// packed half2 2^x (one MUFU op for two values)
__device__ __forceinline__ uint32_t h2exp2_(uint32_t x) {
    uint32_t r;
    asm("ex2.approx.f16x2 %0, %1;" : "=r"(r) : "r"(x));
    return r;
}

__device__ __forceinline__ void cp_async16(uint32_t dst, const void* src) {
    asm volatile("cp.async.cg.shared.global [%0], [%1], 16;"
                 :: "r"(dst), "l"(src));
}
#define CP_COMMIT()  asm volatile("cp.async.commit_group;" ::: "memory")
#define CP_WAIT(N)   asm volatile("cp.async.wait_group %0;" :: "n"(N) : "memory")

// ---------------------------------------------------------------------------
// pre-rounding pass: dst = fp16(src), up to 7 tensors per launch (grid.z)
// ---------------------------------------------------------------------------
struct RoundArgs {
    const float* src[7];
    __half*      dst[7];
    int          n4[7];     // number of float4 elements
};

__global__ __launch_bounds__(256) void round_f16(RoundArgs ra) {
    const int z = blockIdx.z;
    const int i = blockIdx.x * 256 + threadIdx.x;
    if (i >= ra.n4[z]) return;
    float4 v = ((const float4*)ra.src[z])[i];
    __half2 h0 = __floats2half2_rn(v.x, v.y);
    __half2 h1 = __floats2half2_rn(v.z, v.w);
    uint2 u;
    u.x = *(uint32_t*)&h0;
    u.y = *(uint32_t*)&h1;
    ((uint2*)ra.dst[z])[i] = u;
}

// ---------------------------------------------------------------------------
// Pipelined TN GEMM (fp16 HMMA):  C[M,N] = A[M,K] * W[N,K]^T + bias[N]
// CTA 128x128 with FOUR warps (128 threads), warp tile 64x64 (2x2 grid).
// K-tile 64, 3-stage cp.async ring, m16n8k16 HMMA. (byte-identical to R12;
// profiled at tensor=60.7% — latency-bound, NOT at a structural ceiling.)
// Output modes: 0 = fp16 to Ch (Q-proj), 1 = permuted fp32 into new_kv
// (K/V proj land directly in d_out), 2 = plain fp32 (O-proj).
// ---------------------------------------------------------------------------
#define NST        3
#define TILE_B     16384                 // 128 rows * 128 bytes
#define GEMM_SMEM  (2 * NST * TILE_B + 1024)
#define NKT        (D_MODEL / 64)        // 32 k-tiles

struct ProjArgs {
    const __half* A[3];
    const __half* W[3];
    const float*  Bias[3];
    float*        C[3];
    __half*       Ch[3];
    int           mode[3];
};

__global__ __launch_bounds__(128, 2) void gemm_tc(ProjArgs args) {
    extern __shared__ char dyn_smem[];
    char* db = (char*)(((uintptr_t)dyn_smem + 1023) & ~(uintptr_t)1023);
    const uint32_t db_u = smem_u32(db);

    const int z = blockIdx.z;
    const __half* __restrict__ A    = args.A[z];
    const __half* __restrict__ W    = args.W[z];
    const float*  __restrict__ bias = args.Bias[z];
    float* __restrict__        C    = args.C[z];
    __half* __restrict__       Ch   = args.Ch[z];
    const int mode = args.mode[z];

    const int tid  = threadIdx.x;
    const int lane = tid & 31;
    const int w    = tid >> 5;     // 0..3
    const int wm   = w >> 1;       // 0..1
    const int wn   = w & 1;        // 0..1
    const int n0   = blockIdx.x * 128;
    const int m0   = blockIdx.y * 128;

    const __half* Ag = A + (size_t)m0 * D_MODEL;
    const __half* Wg = W + (size_t)n0 * D_MODEL;

    // per-thread load geometry: 8 chunks A + 8 chunks B per stage (128 thr)
    uint32_t swoff[8];
    size_t   gofs[8];
#pragma unroll
    for (int rep = 0; rep < 8; rep++) {
        const int g = rep * 128 + tid;          // 0..1023
        const int r = g >> 3;                   // row 0..127
        const int i = g & 7;                    // 16B chunk
        gofs[rep]  = (size_t)r * D_MODEL + i * 8;
        swoff[rep] = (uint32_t)((r * 128 + i * 16) ^ ((r & 7) << 4));
    }

    float acc[4][8][4];
#pragma unroll
    for (int i = 0; i < 4; i++)
#pragma unroll
        for (int j = 0; j < 8; j++)
#pragma unroll
            for (int k = 0; k < 4; k++) acc[i][j][k] = 0.f;

    auto issue = [&](int ks) {
        const int slot = ks % NST;
        const int kc   = ks * 64;
        const uint32_t da  = db_u + slot * TILE_B;
        const uint32_t dbb = db_u + NST * TILE_B + slot * TILE_B;
#pragma unroll
        for (int rep = 0; rep < 8; rep++)
            cp_async16(da + swoff[rep], Ag + gofs[rep] + kc);
#pragma unroll
        for (int rep = 0; rep < 8; rep++)
            cp_async16(dbb + swoff[rep], Wg + gofs[rep] + kc);
        CP_COMMIT();
    };

    issue(0);
    issue(1);

    const int m_ = lane >> 3;
    const int rr = lane & 7;
    const int a_row_base = wm * 64 + (m_ & 1) * 8 + rr;   // + mf*16
    const int b_row_base = wn * 64 + (m_ & 1) * 8 + rr;   // + nf2*16
    const int k_half     = (m_ >> 1) * 16;

#pragma unroll 1
    for (int kt = 0; kt < NKT; kt++) {
        if (kt < NKT - 2) { CP_WAIT(1); } else { CP_WAIT(0); }
        __syncthreads();
        if (kt + 2 < NKT) issue(kt + 2);

        const int slot = kt % NST;
        const uint32_t da  = db_u + slot * TILE_B;
        const uint32_t dbb = db_u + NST * TILE_B + slot * TILE_B;

#pragma unroll
        for (int ks = 0; ks < 4; ks++) {
            const int kb = ks * 32 + k_half;
            uint32_t a[4][4], b[8][2];
#pragma unroll
            for (int mf = 0; mf < 4; mf++) {
                const int row = a_row_base + mf * 16;
                const uint32_t off = (uint32_t)((row * 128 + kb) ^ ((row & 7) << 4));
                ldsm_x4(a[mf], da + off);
            }
#pragma unroll
            for (int nf2 = 0; nf2 < 4; nf2++) {
                const int row = b_row_base + nf2 * 16;
                const uint32_t off = (uint32_t)((row * 128 + kb) ^ ((row & 7) << 4));
                uint32_t t[4];
                ldsm_x4(t, dbb + off);
                b[nf2 * 2][0]     = t[0]; b[nf2 * 2][1]     = t[2];
                b[nf2 * 2 + 1][0] = t[1]; b[nf2 * 2 + 1][1] = t[3];
            }
#pragma unroll
            for (int mf = 0; mf < 4; mf++)
#pragma unroll
                for (int nf = 0; nf < 8; nf++)
                    mma_f16(acc[mf][nf], a[mf], b[nf]);
        }
    }

    // epilogue (per mode)
#pragma unroll
    for (int mf = 0; mf < 4; mf++) {
#pragma unroll
        for (int nf = 0; nf < 8; nf++) {
            const int row = m0 + wm * 64 + mf * 16 + (lane >> 2);
            const int col = n0 + wn * 64 + nf * 8 + (lane & 3) * 2;
            const float b0 = bias[col], b1 = bias[col + 1];
            const float x0 = acc[mf][nf][0] + b0, x1 = acc[mf][nf][1] + b1;
            const float y0 = acc[mf][nf][2] + b0, y1 = acc[mf][nf][3] + b1;
            if (mode == 0) {
                __half2 h0 = __floats2half2_rn(x0, x1);
                __half2 h1 = __floats2half2_rn(y0, y1);
                *(__half2*)&Ch[(size_t)row * D_MODEL + col]       = h0;
                *(__half2*)&Ch[(size_t)(row + 8) * D_MODEL + col] = h1;
            } else if (mode == 1) {
                // direct write into new_k/new_v (proj half): t' = 1024 + t
                const int h  = col >> 7, d = col & 127;
#pragma unroll
                for (int rep = 0; rep < 2; rep++) {
                    const int rw = row + rep * 8;
                    const int bb = rw >> 10, t = rw & 1023;
                    const int j  = h * 128 + 64 + (t >> 4);
                    const int c  = (t & 15) * 128 + d;
                    float2 v = rep ? make_float2(y0, y1) : make_float2(x0, x1);
                    *(float2*)&C[((size_t)bb * 2048 + j) * 2048 + c] = v;
                }
            } else {
                *(float2*)&C[(size_t)row * D_MODEL + col]       = make_float2(x0, x1);
                *(float2*)&C[(size_t)(row + 8) * D_MODEL + col] = make_float2(y0, y1);
            }
        }
    }
}

// ---------------------------------------------------------------------------
// fp16 flash attention over the cache only (mask tril(TQ,total) => cache half).
// 128 threads (4 warps), 64 q-rows/CTA, 64 kv/tile, fused K+V commit groups,
// single CP_WAIT + 2 barriers per iteration; P in registers; l via ones-column
// tensor-core MMA; P pairs via ex2.approx.f16x2. (byte-identical to R12)
// SMEM: Q 16K | K0 K1 32K | V0 V1 32K = 80K, 2 CTA/SM.
// qi reversed vs blockIdx.x: heavy (long) CTAs launch first -> better tail.
// ---------------------------------------------------------------------------
#define QOFF 0
#define KOFF 16384
#define VOFF (KOFF + 2 * 16384)
#define ATT_SMEM (VOFF + 2 * 16384)   // 81920

__global__ __launch_bounds__(128, 2) void attn_kernel(
    const __half* __restrict__ gQ,
    const __half* __restrict__ hK,
    const __half* __restrict__ hV,
    __half* __restrict__ gO)
{
    extern __shared__ char smc[];
    const uint32_t sb = smem_u32(smc);
    const int tid = threadIdx.x, lane = tid & 31, w = tid >> 5;
    const int qi = (int)gridDim.x - 1 - blockIdx.x;   // heavy tiles first
    const int h = blockIdx.y, b = blockIdx.z;
    const int q0 = qi * 64;

    const __half* Qg = gQ + ((size_t)b * TQ + q0) * D_MODEL + h * HEAD_DIM;
    const __half* Kg = hK + (size_t)b * CACHE_LEN * D_MODEL + h * HEAD_DIM;
    const __half* Vg = hV + (size_t)b * CACHE_LEN * D_MODEL + h * HEAD_DIM;

    // Q tile 64x128 halves -> swizzled smem (rows 256B)
#pragma unroll
    for (int rep = 0; rep < 8; rep++) {
        const int g = rep * 128 + tid;
        const int r = g >> 4, i = g & 15;
        uint4 v = *(const uint4*)(Qg + (size_t)r * D_MODEL + i * 8);
        *(uint4*)(smc + QOFF + ((r * 256 + i * 16) ^ ((r & 7) << 4))) = v;
    }

    // one commit group per kv-tile: K chunks + V chunks together
    auto issueKV = [&](int kt) {
#pragma unroll
        for (int rep = 0; rep < 8; rep++) {
            const int g = rep * 128 + tid;
            const int r = g >> 4, i = g & 15;
            const uint32_t so = (uint32_t)((r * 256 + i * 16) ^ ((r & 7) << 4));
            cp_async16(sb + KOFF + (kt & 1) * 16384 + so,
                       Kg + (size_t)(kt * 64 + r) * D_MODEL + i * 8);
            cp_async16(sb + VOFF + (kt & 1) * 16384 + so,
                       Vg + (size_t)(kt * 64 + r) * D_MODEL + i * 8);
        }
        CP_COMMIT();
    };

    issueKV(0);
    if (qi >= 1) issueKV(1); else CP_COMMIT();

    float acc_o[16][4];
#pragma unroll
    for (int i = 0; i < 16; i++)
#pragma unroll
        for (int j = 0; j < 4; j++) acc_o[i][j] = 0.f;
    float acc_l[4] = {0.f, 0.f, 0.f, 0.f};   // ones-column row-sum accumulator
    float mrow[2] = {-1e30f, -1e30f};        // running max of UNSCALED scores
    // exp(sc*(s-m)) == exp2f((s-m)*C2), C2 = (1/sqrt(128))*log2(e)
    const float C2 = (float)(0.08838834764831845 * 1.4426950408889634);

    // B-frag of all-ones in column 0 (col = lane>>2): lanes 0..3 hold 1.0h pairs
    const uint32_t b_ones = ((lane >> 2) == 0) ? 0x3C003C00u : 0u;
    uint32_t bO[2] = { b_ones, b_ones };

    const int m_ = lane >> 3, rr = lane & 7;
    const int kh    = (m_ >> 1) * 16;
    const int a_row = w * 16 + (m_ & 1) * 8 + rr;

    for (int kt = 0; kt <= qi; kt++) {
        CP_WAIT(1);            // KV(kt) landed (groups complete in order)
        __syncthreads();       // visible to all warps (covers Q on kt=0)

        const uint32_t kbase = sb + KOFF + (kt & 1) * 16384;
        float accs[8][4];
#pragma unroll
        for (int i = 0; i < 8; i++)
#pragma unroll
            for (int j = 0; j < 4; j++) accs[i][j] = 0.f;

#pragma unroll
        for (int ks = 0; ks < 8; ks++) {            // 8 x k16 over headdim 128
            const int colb = ks * 32 + kh;
            uint32_t a[4];
            ldsm_x4(a, sb + QOFF + ((a_row * 256 + colb) ^ ((a_row & 7) << 4)));
            uint32_t bfr[8][2];
#pragma unroll
            for (int nf2 = 0; nf2 < 4; nf2++) {
                const int row = nf2 * 16 + (m_ & 1) * 8 + rr;   // kv rows 0..63
                uint32_t t[4];
                ldsm_x4(t, kbase + ((row * 256 + colb) ^ ((row & 7) << 4)));
                bfr[nf2 * 2][0]     = t[0]; bfr[nf2 * 2][1]     = t[2];
                bfr[nf2 * 2 + 1][0] = t[1]; bfr[nf2 * 2 + 1][1] = t[3];
            }
#pragma unroll
            for (int nf = 0; nf < 8; nf++) mma_f16(accs[nf], a, bfr[nf]);
        }

        // causal mask (diagonal tile only) on UNSCALED scores
        if (kt == qi) {
#pragma unroll
            for (int nf = 0; nf < 8; nf++)
#pragma unroll
                for (int r = 0; r < 2; r++)
#pragma unroll
                    for (int j = 0; j < 2; j++) {
                        const int cl = nf * 8 + (lane & 3) * 2 + j;
                        const int rl = w * 16 + (lane >> 2) + r * 8;
                        if (cl > rl) accs[nf][r * 2 + j] = -1e30f;
                    }
        }

        // online softmax (scale folded into exp2; P pairs via ex2.f16x2)
        uint32_t ph[8][2];
#pragma unroll
        for (int r = 0; r < 2; r++) {
            float vmax = -1e30f;
#pragma unroll
            for (int nf = 0; nf < 8; nf++) {
                vmax = fmaxf(vmax, accs[nf][r * 2]);
                vmax = fmaxf(vmax, accs[nf][r * 2 + 1]);
            }
            vmax = fmaxf(vmax, __shfl_xor_sync(0xffffffffu, vmax, 1));
            vmax = fmaxf(vmax, __shfl_xor_sync(0xffffffffu, vmax, 2));
            const float mnew = fmaxf(mrow[r], vmax);
#pragma unroll
            for (int nf = 0; nf < 8; nf++) {
                __half2 e = __floats2half2_rn((accs[nf][r * 2]     - mnew) * C2,
                                              (accs[nf][r * 2 + 1] - mnew) * C2);
                ph[nf][r] = h2exp2_(*(uint32_t*)&e);
            }
            const float alpha = exp2f((mrow[r] - mnew) * C2);
            mrow[r] = mnew;
            acc_l[r * 2]     *= alpha;
            acc_l[r * 2 + 1] *= alpha;
#pragma unroll
            for (int nf = 0; nf < 16; nf++) {
                acc_o[nf][r * 2]     *= alpha;
                acc_o[nf][r * 2 + 1] *= alpha;
            }
        }

        // O += P * V ; l += P * 1  (V arrived with K; P A-frags from registers)
        const uint32_t vbase = sb + VOFF + (kt & 1) * 16384;
        const int vr_lane = ((lane >> 3) & 1) * 8 + (lane & 7);
        const int vc_lane = (lane >> 4) * 16;
#pragma unroll
        for (int ks = 0; ks < 4; ks++) {            // 4 x k16 over 64 kv
            uint32_t aP[4];
            aP[0] = ph[2 * ks][0];
            aP[1] = ph[2 * ks][1];
            aP[2] = ph[2 * ks + 1][0];
            aP[3] = ph[2 * ks + 1][1];
            mma_f16(acc_l, aP, bO);                 // row-sum into col 0
#pragma unroll
            for (int dg = 0; dg < 8; dg++) {        // 16 halves of headdim each
                const int vrow = ks * 16 + vr_lane;
                const int vcol = dg * 32 + vc_lane;
                uint32_t t[4];
                ldsm_x4t(t, vbase + ((vrow * 256 + vcol) ^ ((vrow & 7) << 4)));
                uint32_t b0[2] = { t[0], t[1] };
                uint32_t b1[2] = { t[2], t[3] };
                mma_f16(acc_o[dg * 2],     aP, b0);
                mma_f16(acc_o[dg * 2 + 1], aP, b1);
            }
        }

        __syncthreads();       // all warps done reading K(kt)/V(kt)
        if (kt + 2 <= qi) issueKV(kt + 2); else CP_COMMIT();
    }

    // l lives in col 0 (lanes with lane%4==0); broadcast across each quad
    const int qlead = lane & ~3;
    const float l0 = __shfl_sync(0xffffffffu, acc_l[0], qlead);
    const float l1 = __shfl_sync(0xffffffffu, acc_l[2], qlead);
    const float inv0 = 1.f / l0;
    const float inv1 = 1.f / l1;

    // normalize + write fp16
#pragma unroll
    for (int nf = 0; nf < 16; nf++)
#pragma unroll
        for (int r = 0; r < 2; r++) {
            const int row = q0 + w * 16 + (lane >> 2) + r * 8;
            const int col = h * HEAD_DIM + nf * 8 + (lane & 3) * 2;
            const float inv = r ? inv1 : inv0;
            __half2 hv = __floats2half2_rn(acc_o[nf][r * 2] * inv,
                                           acc_o[nf][r * 2 + 1] * inv);
            *(__half2*)&gO[((size_t)b * TQ + row) * D_MODEL + col] = hv;
        }
}

// ---------------------------------------------------------------------------
// cache pass, fused: permuted fp32 cache half of new_k/new_v into d_out AND
// fp16 rounding of the caches for attention (single read of each cache).
// grid.z: 0 -> K, 1 -> V. 2097152 float4 per tensor.
// ---------------------------------------------------------------------------
__global__ __launch_bounds__(256) void copy_cache_kv(
    const float* __restrict__ cacheK,
    const float* __restrict__ cacheV,
    float* __restrict__ dstK,
    float* __restrict__ dstV,
    __half* __restrict__ hcK,
    __half* __restrict__ hcV)
{
    const int i = blockIdx.x * 256 + threadIdx.x;
    const int b   = i >> 19;            // 524288 float4 per batch
    const int rem = i & 524287;
    const int jj  = rem >> 9;           // 0..1023 (h*64 + cache row)
    const int c   = (rem & 511) * 4;
    const int h   = jj >> 6;
    const int j   = h * 128 + (jj & 63);
    const int t   = (jj & 63) * 16 + (c >> 7);
    const int d   = c & 127;

    const float* cache = blockIdx.z ? cacheV : cacheK;
    float*       dst   = blockIdx.z ? dstV   : dstK;
    __half*      hc    = blockIdx.z ? hcV    : hcK;

    const size_t src_off = ((size_t)b * CACHE_LEN + t) * D_MODEL + h * HEAD_DIM + d;
    float4 v = *(const float4*)&cache[src_off];
    *(float4*)&dst[((size_t)b * 2048 + j) * D_MODEL + c] = v;

    __half2 h0 = __floats2half2_rn(v.x, v.y);
    __half2 h1 = __floats2half2_rn(v.z, v.w);
    uint2 u;
    u.x = *(uint32_t*)&h0;
    u.y = *(uint32_t*)&h1;
    *(uint2*)&hc[src_off] = u;
}

// ---------------------------------------------------------------------------
// launch — dependency-true two-branch DAG:
//   s2 (t=0):   cache pass (->evC) -> round(k,v,Wk,Wv) -> K/V-proj (->evK)
//   s0:         round(q,Wq,Wo) -> Q-proj -> [evC] attn -> O-proj -> [evK]
// attention (80KB, 41.8% tensor) hides inside K/V-proj (97KB, 60.7% tensor);
// they co-reside per SM (177KB < 228KB smem, 58K < 64K regs).
// ---------------------------------------------------------------------------
extern "C" void kernel_launch(void* const* d_in, const int* in_sizes, int n_in,
                              void* d_out, int out_size)
{
    const float* query   = (const float*)d_in[0];
    const float* key     = (const float*)d_in[1];
    const float* value   = (const float*)d_in[2];
    const float* cacheK  = (const float*)d_in[3];
    const float* cacheV  = (const float*)d_in[4];
    const float* Wq      = (const float*)d_in[5];
    const float* bq      = (const float*)d_in[6];
    const float* Wk      = (const float*)d_in[7];
    const float* bk      = (const float*)d_in[8];
    const float* Wv      = (const float*)d_in[9];
    const float* bv      = (const float*)d_in[10];
    const float* Wo      = (const float*)d_in[11];
    const float* bo      = (const float*)d_in[12];
    float* out = (float*)d_out;

    __half *phQ, *pO, *phq, *phk, *phv, *phWq, *phWk, *phWv, *phWo, *phck, *phcv;
    cudaGetSymbolAddress((void**)&phQ, g_hQ);
    cudaGetSymbolAddress((void**)&pO, g_O);
    cudaGetSymbolAddress((void**)&phq, g_hq);
    cudaGetSymbolAddress((void**)&phk, g_hk);
    cudaGetSymbolAddress((void**)&phv, g_hv);
    cudaGetSymbolAddress((void**)&phWq, g_hWq);
    cudaGetSymbolAddress((void**)&phWk, g_hWk);
    cudaGetSymbolAddress((void**)&phWv, g_hWv);
    cudaGetSymbolAddress((void**)&phWo, g_hWo);
    cudaGetSymbolAddress((void**)&phck, g_hck);
    cudaGetSymbolAddress((void**)&phcv, g_hcv);

    // one-time stream/event creation (resources only; identical work per call)
    static cudaStream_t s2 = nullptr;
    static cudaEvent_t  evF = nullptr, evC = nullptr, evK = nullptr;
    if (s2 == nullptr) {
        cudaStreamCreateWithFlags(&s2, cudaStreamNonBlocking);
        cudaEventCreateWithFlags(&evF, cudaEventDisableTiming);
        cudaEventCreateWithFlags(&evC, cudaEventDisableTiming);
        cudaEventCreateWithFlags(&evK, cudaEventDisableTiming);
    }

    cudaFuncSetAttribute(gemm_tc, cudaFuncAttributeMaxDynamicSharedMemorySize,
                         GEMM_SMEM);
    cudaFuncSetAttribute(attn_kernel, cudaFuncAttributeMaxDynamicSharedMemorySize,
                         ATT_SMEM);

    const int NA = M_ROWS * D_MODEL / 4;     // 2097152 float4
    const int NW = D_MODEL * D_MODEL / 4;    // 1048576 float4

    // fork s2 at t=0 (its first kernels have no s0 dependencies)
    cudaEventRecord(evF, 0);
    cudaStreamWaitEvent(s2, evF, 0);

    // ---- s2 branch ----
    // cache pass: permuted fp32 halves into d_out + fp16 caches for attn
    copy_cache_kv<<<dim3(2097152 / 256, 1, 2), 256, 0, s2>>>(
        cacheK, cacheV, out + 8388608, out + 25165824, phck, phcv);
    cudaEventRecord(evC, s2);

    // round k, v, Wk, Wv (feeds K/V-proj only)
    RoundArgs rb;
    rb.src[0] = key;   rb.dst[0] = phk;  rb.n4[0] = NA;
    rb.src[1] = value; rb.dst[1] = phv;  rb.n4[1] = NA;
    rb.src[2] = Wk;    rb.dst[2] = phWk; rb.n4[2] = NW;
    rb.src[3] = Wv;    rb.dst[3] = phWv; rb.n4[3] = NW;
    for (int s = 4; s < 7; s++) { rb.src[s] = Wv; rb.dst[s] = phWv; rb.n4[s] = 0; }
    round_f16<<<dim3(NA / 256, 1, 4), 256, 0, s2>>>(rb);

    // K/V projections straight into d_out (mode 1)
    ProjArgs pkv;
    pkv.A[0] = phk; pkv.W[0] = phWk; pkv.Bias[0] = bk;
    pkv.C[0] = out + 8388608;  pkv.Ch[0] = nullptr; pkv.mode[0] = 1;
    pkv.A[1] = phv; pkv.W[1] = phWv; pkv.Bias[1] = bv;
    pkv.C[1] = out + 25165824; pkv.Ch[1] = nullptr; pkv.mode[1] = 1;
    pkv.A[2] = pkv.A[0]; pkv.W[2] = pkv.W[0]; pkv.Bias[2] = pkv.Bias[0];
    pkv.C[2] = pkv.C[0]; pkv.Ch[2] = nullptr; pkv.mode[2] = 1;
    gemm_tc<<<dim3(D_MODEL / 128, M_ROWS / 128, 2), 128, GEMM_SMEM, s2>>>(pkv);
    cudaEventRecord(evK, s2);

    // ---- s0 branch ----
    // round q, Wq, Wo (feeds Q-proj and O-proj)
    RoundArgs raA;
    raA.src[0] = query; raA.dst[0] = phq;  raA.n4[0] = NA;
    raA.src[1] = Wq;    raA.dst[1] = phWq; raA.n4[1] = NW;
    raA.src[2] = Wo;    raA.dst[2] = phWo; raA.n4[2] = NW;
    for (int s = 3; s < 7; s++) { raA.src[s] = Wo; raA.dst[s] = phWo; raA.n4[s] = 0; }
    round_f16<<<dim3(NA / 256, 1, 3), 256>>>(raA);

    // Q projection -> fp16 scratch (mode 0)
    ProjArgs pq;
    pq.A[0] = phq; pq.W[0] = phWq; pq.Bias[0] = bq;
    pq.C[0] = nullptr; pq.Ch[0] = phQ; pq.mode[0] = 0;
    pq.A[1] = pq.A[0]; pq.W[1] = pq.W[0]; pq.Bias[1] = pq.Bias[0];
    pq.C[1] = nullptr; pq.Ch[1] = phQ; pq.mode[1] = 0;
    pq.A[2] = pq.A[0]; pq.W[2] = pq.W[0]; pq.Bias[2] = pq.Bias[0];
    pq.C[2] = nullptr; pq.Ch[2] = phQ; pq.mode[2] = 0;
    gemm_tc<<<dim3(D_MODEL / 128, M_ROWS / 128, 1), 128, GEMM_SMEM>>>(pq);

    // attention needs the fp16 caches from s2's cache pass
    cudaStreamWaitEvent(0, evC, 0);
    attn_kernel<<<dim3(TQ / 64, NUM_HEADS, BATCH), 128, ATT_SMEM>>>(
        phQ, phck, phcv, pO);

    // O-projection -> out[0 .. 8388608)  (co-runs with K/V-proj tail)
    ProjArgs po;
    po.A[0] = pO; po.W[0] = phWo; po.Bias[0] = bo;
    po.C[0] = out; po.Ch[0] = nullptr; po.mode[0] = 2;
    po.A[1] = po.A[0]; po.W[1] = po.W[0]; po.Bias[1] = po.Bias[0];
    po.C[1] = po.C[0]; po.Ch[1] = nullptr; po.mode[1] = 2;
    po.A[2] = po.A[0]; po.W[2] = po.W[0]; po.Bias[2] = po.Bias[0];
    po.C[2] = po.C[0]; po.Ch[2] = nullptr; po.mode[2] = 2;
    gemm_tc<<<dim3(D_MODEL / 128, M_ROWS / 128, 1), 128, GEMM_SMEM>>>(po);

    // join
    cudaStreamWaitEvent(0, evK, 0);
}